// round 8
// baseline (speedup 1.0000x reference)
#include <cuda_runtime.h>
#include <cstdint>

// ---------------------------------------------------------------------------
// Problem constants
// ---------------------------------------------------------------------------
constexpr int BB = 32, CC = 256, HH = 56, WW = 56;
constexpr int HP = 58, WP = 58;                 // padded spatial
constexpr int HWs = HH * WW;                    // 3136
constexpr int CHW = CC * HWs;                   // 802816
constexpr int PIX = BB * HWs;                   // 100352
constexpr int KW  = 72;                         // K in 32-bit words (2304 bits)
constexpr int KD  = 2304;                       // K in int8 elements
constexpr int KBITS = 2304;
constexpr float BN_EPS = 1e-5f;

// ---- hybrid split: popc covers pixels [0, 69376), IMMA covers the rest ----
constexpr int TM = 64;                          // popc CTA pixel tile
constexpr int TN = 128;                         // popc CTA cout tile
constexpr int POPC_MTILES = 1084;               // 1084*64 = 69376 pixels
constexpr int IMMA_PIX0  = POPC_MTILES * TM;    // 69376
constexpr int IMMA_MTILES = 242;                // 242*128 = 30976 pixels
constexpr int POPC_BLOCKS = POPC_MTILES * 2;    // 2168  (2 x 128-cout halves)
constexpr int IMMA_BLOCKS = IMMA_MTILES * 4;    // 968   (4 x 64-cout quarters)
constexpr int TOT_BLOCKS  = POPC_BLOCKS + IMMA_BLOCKS;  // 3136

// popc smem: W tile [72][128] + X tile [72][64] words
constexpr int SW_WORDS = KW * TN;               // 9216
constexpr int SX_WORDS = KW * TM;               // 4608
constexpr int SMEM_DYN = (SW_WORDS + SX_WORDS) * 4;   // 55296 B

// IMMA smem (within the same 55296): 2 stages of (A 128x80 + B 64x80) int8
constexpr int ISSTR = 80;
constexpr int IA_BYTES = 128 * ISSTR;           // 10240
constexpr int IB_BYTES = 64 * ISSTR;            // 5120
constexpr int ISTAGE = IA_BYTES + IB_BYTES;     // 15360 (x2 = 30720 <= 55296)

// ---------------------------------------------------------------------------
// Device scratch (allocation-free: __device__ globals)
// ---------------------------------------------------------------------------
__device__ uint32_t g_xp[(size_t)BB * HP * WP * 8];   // packed x, padded NHWC, 3.4MB
__device__ uint32_t g_wpT[KW * CC];                   // packed w, [k][cout]
__device__ uint4    g_wb_raw[(size_t)CC * KD / 16];   // int8 w, [co][tap*256+ci], 590KB
__device__ int      g_corr[9 * CC];                   // border corrections
__device__ short    g_y16[(size_t)PIX * CC];          // conv result, NCHW int16, 51MB
__device__ float    g_scale[CC];
__device__ unsigned long long g_isum[CC];
__device__ unsigned long long g_isumsq[CC];
__device__ float    g_ab[2 * CC];

#define G_WB ((int8_t*)g_wb_raw)

// ---------------------------------------------------------------------------
// PTX helpers (baseline, assemble at .target sm_103)
// ---------------------------------------------------------------------------
__device__ __forceinline__ uint32_t smem_to_u32(const void* p) {
    uint32_t a;
    asm("{ .reg .u64 t; cvta.to.shared.u64 t, %1; cvt.u32.u64 %0, t; }" : "=r"(a) : "l"(p));
    return a;
}
__device__ __forceinline__ void ldsm4(uint32_t& r0, uint32_t& r1, uint32_t& r2,
                                      uint32_t& r3, uint32_t addr) {
    asm volatile("ldmatrix.sync.aligned.m8n8.x4.shared.b16 {%0,%1,%2,%3}, [%4];"
                 : "=r"(r0), "=r"(r1), "=r"(r2), "=r"(r3) : "r"(addr));
}
__device__ __forceinline__ void mma_s8(int* d, uint32_t a0, uint32_t a1,
                                       uint32_t a2, uint32_t a3,
                                       uint32_t b0, uint32_t b1) {
    asm volatile(
        "mma.sync.aligned.m16n8k32.row.col.s32.s8.s8.s32 "
        "{%0,%1,%2,%3}, {%4,%5,%6,%7}, {%8,%9}, {%0,%1,%2,%3};"
        : "+r"(d[0]), "+r"(d[1]), "+r"(d[2]), "+r"(d[3])
        : "r"(a0), "r"(a1), "r"(a2), "r"(a3), "r"(b0), "r"(b1));
}

// ---------------------------------------------------------------------------
// Kernel: weight prep — scale, packed bits [k][o], int8 signs [o][tap*256+ci],
// border-correction table, zero integer BN accumulators.
// ---------------------------------------------------------------------------
__global__ void wprep_kernel(const float* __restrict__ w) {
    int o = blockIdx.x, tid = threadIdx.x;
    int lane = tid & 31, warp = tid >> 5;
    const float* wp = w + ((size_t)o * CC + tid) * 9;
    float v[9]; float s = 0.0f;
#pragma unroll
    for (int t = 0; t < 9; t++) { v[t] = wp[t]; s += fabsf(v[t]); }
#pragma unroll
    for (int off = 16; off; off >>= 1) s += __shfl_xor_sync(~0u, s, off);
    __shared__ float sh[8];
    __shared__ uint32_t words[9][8];
    __shared__ int S[9];
    if (lane == 0) sh[warp] = s;

#pragma unroll
    for (int t = 0; t < 9; t++) {
        uint32_t m = __ballot_sync(~0u, v[t] > 0.0f);
        if (lane == 0) words[t][warp] = m;
        int sg = (v[t] > 0.0f) ? 1 : ((v[t] < 0.0f) ? -1 : 0);
        G_WB[(size_t)o * KD + t * 256 + tid] = (int8_t)sg;
    }
    __syncthreads();
    if (tid == 0) {
        float tot = 0.0f;
        for (int i = 0; i < 8; i++) tot += sh[i];
        g_scale[o] = tot / (float)KBITS;
        g_isum[o] = 0ull; g_isumsq[o] = 0ull;
    }
    if (tid < 72) {
        int t = tid >> 3, j = tid & 7;
        g_wpT[(t * 8 + j) * CC + o] = words[t][j];
    }
    if (tid < 9) {
        int P = 0;
        for (int j = 0; j < 8; j++) P += __popc(words[tid][j]);
        S[tid] = 2 * P - 256;          // sum_ci sign(w[o][ci][tap])
    }
    __syncthreads();
    if (tid < 9) {                      // tid = border category ht*3+wt
        int ht = tid / 3, wt = tid % 3;
        int corr = 0;
        for (int kh = 0; kh < 3; kh++)
            for (int kw = 0; kw < 3; kw++) {
                bool miss = (ht == 0 && kh == 0) || (ht == 2 && kh == 2) ||
                            (wt == 0 && kw == 0) || (wt == 2 && kw == 2);
                if (miss) corr += S[kh * 3 + kw];
            }
        g_corr[tid * CC + o] = corr;
    }
}

// ---------------------------------------------------------------------------
// Kernel: zero packed-x buffer (pad ring stays 0 = "all -1", corrected later)
// ---------------------------------------------------------------------------
__global__ void zero_xp_kernel() {
    size_t i = (size_t)blockIdx.x * 256 + threadIdx.x;
    ((uint4*)g_xp)[i] = make_uint4(0, 0, 0, 0);
}

// ---------------------------------------------------------------------------
// Kernel: pack sign bits of x: NCHW fp32 -> padded [b][h][w][8 words]
// ---------------------------------------------------------------------------
__global__ void xpack_kernel(const float* __restrict__ x) {
    int h = blockIdx.x, b = blockIdx.y;
    int lane = threadIdx.x & 31, warp = threadIdx.x >> 5;
    const float4* xrow =
        (const float4*)(x + (((size_t)(b * CC + warp * 32 + lane)) * HH + h) * WW);
    uint32_t* base = &g_xp[(((size_t)(b * HP + h + 1)) * WP + 1) * 8 + warp];
    for (int w0 = 0; w0 < WW; w0 += 4) {
        float4 v = xrow[w0 >> 2];
        uint32_t m0 = __ballot_sync(~0u, v.x > 0.0f);
        uint32_t m1 = __ballot_sync(~0u, v.y > 0.0f);
        uint32_t m2 = __ballot_sync(~0u, v.z > 0.0f);
        uint32_t m3 = __ballot_sync(~0u, v.w > 0.0f);
        if (lane == 0) {
            base[(w0 + 0) * 8] = m0; base[(w0 + 1) * 8] = m1;
            base[(w0 + 2) * 8] = m2; base[(w0 + 3) * 8] = m3;
        }
    }
}

// ---------------------------------------------------------------------------
// Shared epilogue helpers
// ---------------------------------------------------------------------------
__device__ __forceinline__ int pixel_cat(int p) {
    int hw = p % HWs;
    int h = hw / WW, w = hw - h * WW;
    int ht = (h == 0) ? 0 : ((h == HH - 1) ? 2 : 1);
    int wt = (w == 0) ? 0 : ((w == WW - 1) ? 2 : 1);
    return ht * 3 + wt;
}

// ---------------------------------------------------------------------------
// popc block: 64 pixels x 128 couts (exact R6 body)
// ---------------------------------------------------------------------------
__device__ __forceinline__ void popc_block(uint32_t* smem, int q) {
    uint32_t* sW = smem;                // [72][128]
    uint32_t* sX = smem + SW_WORDS;     // [72][64]
    const int tid = threadIdx.x;
    const int lane = tid & 31;
    const int p0 = (q >> 1) * TM;
    const int n0 = (q & 1) * TN;

    {
        int col = tid & 127, khalf = tid >> 7;
        for (int k = khalf; k < KW; k += 2)
            sW[k * TN + col] = g_wpT[k * CC + n0 + col];
    }
    for (int idx = tid; idx < 576; idx += 256) {
        int pix = idx & 63, tap = idx >> 6;
        int p = p0 + pix;
        int b = p / HWs, hw = p - b * HWs;
        int h = hw / WW, w = hw - h * WW;
        int kh = tap / 3, kw = tap - 3 * kh;
        const uint4* src =
            (const uint4*)&g_xp[(((size_t)(b * HP + h + kh)) * WP + (w + kw)) * 8];
        uint4 q0 = src[0], q1 = src[1];
        int kb = tap * 8;
        sX[(kb + 0) * TM + pix] = q0.x; sX[(kb + 1) * TM + pix] = q0.y;
        sX[(kb + 2) * TM + pix] = q0.z; sX[(kb + 3) * TM + pix] = q0.w;
        sX[(kb + 4) * TM + pix] = q1.x; sX[(kb + 5) * TM + pix] = q1.y;
        sX[(kb + 6) * TM + pix] = q1.z; sX[(kb + 7) * TM + pix] = q1.w;
    }
    __syncthreads();

    const int pg = tid & 15;
    const int cg = tid >> 4;
    const uint4* sXv = (const uint4*)sX;
    const uint4* sWv = (const uint4*)sW;

    int acc[4][8];
#pragma unroll
    for (int i = 0; i < 4; i++)
#pragma unroll
        for (int j = 0; j < 8; j++) acc[i][j] = 0;

#pragma unroll 2
    for (int k = 0; k < KW; k += 2) {
        uint4 xq0 = sXv[k * 16 + pg];
        uint4 xq1 = sXv[(k + 1) * 16 + pg];
        uint32_t xs0[4] = {xq0.x, xq0.y, xq0.z, xq0.w};
        uint32_t xs1[4] = {xq1.x, xq1.y, xq1.z, xq1.w};
        {
            uint4 w0 = sWv[k * 32 + cg * 2];
            uint4 w1 = sWv[(k + 1) * 32 + cg * 2];
            uint32_t ws0[4] = {w0.x, w0.y, w0.z, w0.w};
            uint32_t ws1[4] = {w1.x, w1.y, w1.z, w1.w};
#pragma unroll
            for (int i = 0; i < 4; i++)
#pragma unroll
                for (int j = 0; j < 4; j++)
                    acc[i][j] += __popc(xs0[i] ^ ws0[j]) + __popc(xs1[i] ^ ws1[j]);
        }
        {
            uint4 w0 = sWv[k * 32 + cg * 2 + 1];
            uint4 w1 = sWv[(k + 1) * 32 + cg * 2 + 1];
            uint32_t ws0[4] = {w0.x, w0.y, w0.z, w0.w};
            uint32_t ws1[4] = {w1.x, w1.y, w1.z, w1.w};
#pragma unroll
            for (int i = 0; i < 4; i++)
#pragma unroll
                for (int j = 0; j < 4; j++)
                    acc[i][j + 4] += __popc(xs0[i] ^ ws0[j]) + __popc(xs1[i] ^ ws1[j]);
        }
    }

    int pcat[4];
#pragma unroll
    for (int i = 0; i < 4; i++) pcat[i] = pixel_cat(p0 + pg * 4 + i);
    int u[4][8];
#pragma unroll
    for (int j = 0; j < 8; j++) {
        int c = n0 + cg * 8 + j;
#pragma unroll
        for (int i = 0; i < 4; i++) {
            int corr = (pcat[i] == 4) ? 0 : g_corr[pcat[i] * CC + c];
            u[i][j] = KBITS - 2 * acc[i][j] + corr;
        }
    }

#pragma unroll
    for (int j = 0; j < 8; j++) {
        int s = 0, s2 = 0;
#pragma unroll
        for (int i = 0; i < 4; i++) { s += u[i][j]; s2 += u[i][j] * u[i][j]; }
#pragma unroll
        for (int m = 1; m < 16; m <<= 1) {
            s  += __shfl_xor_sync(~0u, s, m);
            s2 += __shfl_xor_sync(~0u, s2, m);
        }
        if ((lane & 15) == 0) {
            int c = n0 + cg * 8 + j;
            atomicAdd(&g_isum[c],   (unsigned long long)(long long)s);
            atomicAdd(&g_isumsq[c], (unsigned long long)(long long)s2);
        }
    }
    {
        int p2 = p0 + pg * 4;
        int b2 = p2 / HWs, hw2 = p2 - b2 * HWs;
        short* yd = g_y16 + (size_t)b2 * CHW + hw2;
#pragma unroll
        for (int j = 0; j < 8; j++) {
            int c = n0 + cg * 8 + j;
            uint2 val;
            val.x = (uint32_t)(u[0][j] & 0xffff) | ((uint32_t)u[1][j] << 16);
            val.y = (uint32_t)(u[2][j] & 0xffff) | ((uint32_t)u[3][j] << 16);
            *(uint2*)&yd[(size_t)c * HWs] = val;
        }
    }
}

// ---------------------------------------------------------------------------
// IMMA block: 128 pixels x 64 couts via legacy tensor path (mma m16n8k32 s8).
// A expanded on the fly from packed bits (idle ALU); B from int8 weights.
// ---------------------------------------------------------------------------
__device__ __forceinline__ void imma_block(uint32_t* smem32, int jb) {
    char* smem = (char*)smem32;
    const uint32_t sbase = smem_to_u32(smem);
    const int tid = threadIdx.x;
    const int wid = tid >> 5;
    const int lane = tid & 31;
    const int wm = wid & 3;          // 32-row block
    const int wn = wid >> 2;         // 32-col block (0..1)
    const int m0 = IMMA_PIX0 + (jb >> 2) * 128;
    const int n0 = (jb & 3) * 64;

    // A staging: thread covers pixel row r, 32-channel half
    const int r = tid >> 1, half = tid & 1;
    int p = m0 + r;
    int b = p / HWs; int hw = p - b * HWs;
    int h = hw / WW; int w = hw - h * WW;
    const uint32_t* axsrc = &g_xp[(((size_t)(b * HP + h)) * WP + w) * 8];
    // B staging: row = tid>>2 (0..63), 16B quarter = tid&3
    const int8_t* bsrc = G_WB + (size_t)(n0 + (tid >> 2)) * KD + (tid & 3) * 16;
    const int sdstA = r * ISSTR + half * 32;
    const int sdstB = IA_BYTES + (tid >> 2) * ISSTR + (tid & 3) * 16;

    uint32_t aw; uint4 bw;
    auto gload = [&](int kc) {
        int tap = kc >> 2;
        int kh = tap / 3, kw = tap - 3 * kh;
        aw = axsrc[(kh * WP + kw) * 8 + (kc & 3) * 2 + half];
        bw = *(const uint4*)(bsrc + tap * 256 + (kc & 3) * 64);
    };
    auto expand_store = [&](int buf) {
        uint32_t ex[8];
#pragma unroll
        for (int n = 0; n < 8; n++) {
            uint32_t nib = (aw >> (n * 4)) & 0xF;
            uint32_t spread = (nib * 0x00204081u) & 0x01010101u;
            ex[n] = __vsub4(spread << 1, 0x01010101u);   // bit->+1, clear->-1
        }
        char* da = smem + buf * ISTAGE + sdstA;
        *(uint4*)(da)      = make_uint4(ex[0], ex[1], ex[2], ex[3]);
        *(uint4*)(da + 16) = make_uint4(ex[4], ex[5], ex[6], ex[7]);
        *(uint4*)(smem + buf * ISTAGE + sdstB) = bw;
    };

    int acc[2][4][4];
#pragma unroll
    for (int mf = 0; mf < 2; mf++)
#pragma unroll
        for (int nf = 0; nf < 4; nf++)
#pragma unroll
            for (int i = 0; i < 4; i++) acc[mf][nf][i] = 0;

    const int lrow = lane & 15;
    const int lko  = (lane >> 4) * 16;
    const uint32_t aFrag = (uint32_t)((wm * 32 + lrow) * ISSTR + lko);
    const uint32_t bFrag = (uint32_t)(IA_BYTES + (wn * 32 + lrow) * ISSTR + lko);

    gload(0); expand_store(0);
    __syncthreads();
    for (int kc = 0; kc < 36; kc++) {
        const int buf = kc & 1;
        if (kc + 1 < 36) gload(kc + 1);
        const uint32_t sb = sbase + buf * ISTAGE;
#pragma unroll
        for (int s = 0; s < 2; s++) {
            uint32_t a[2][4];
#pragma unroll
            for (int mf = 0; mf < 2; mf++)
                ldsm4(a[mf][0], a[mf][1], a[mf][2], a[mf][3],
                      sb + aFrag + mf * 16 * ISSTR + s * 32);
#pragma unroll
            for (int nb = 0; nb < 2; nb++) {
                uint32_t b0, b1, b2, b3;
                ldsm4(b0, b1, b2, b3, sb + bFrag + nb * 16 * ISSTR + s * 32);
                mma_s8(acc[0][2 * nb],     a[0][0], a[0][1], a[0][2], a[0][3], b0, b2);
                mma_s8(acc[0][2 * nb + 1], a[0][0], a[0][1], a[0][2], a[0][3], b1, b3);
                mma_s8(acc[1][2 * nb],     a[1][0], a[1][1], a[1][2], a[1][3], b0, b2);
                mma_s8(acc[1][2 * nb + 1], a[1][0], a[1][1], a[1][2], a[1][3], b1, b3);
            }
        }
        __syncthreads();
        if (kc + 1 < 36) expand_store(buf ^ 1);
        __syncthreads();
    }

    // ---- epilogue: u = acc + border corr; fused stats; int16 store ----
    int u[2][4][4];
#pragma unroll
    for (int mf = 0; mf < 2; mf++) {
#pragma unroll
        for (int rh = 0; rh < 2; rh++) {
            int p2 = m0 + wm * 32 + mf * 16 + (lane >> 2) + rh * 8;
            int cat = pixel_cat(p2);
#pragma unroll
            for (int nf = 0; nf < 4; nf++) {
#pragma unroll
                for (int jj = 0; jj < 2; jj++) {
                    int c = n0 + wn * 32 + nf * 8 + 2 * (lane & 3) + jj;
                    int corr = (cat == 4) ? 0 : g_corr[cat * CC + c];
                    u[mf][nf][rh * 2 + jj] = acc[mf][nf][rh * 2 + jj] + corr;
                }
            }
        }
    }
#pragma unroll
    for (int nf = 0; nf < 4; nf++) {
#pragma unroll
        for (int jj = 0; jj < 2; jj++) {
            int s = 0, s2 = 0;
#pragma unroll
            for (int mf = 0; mf < 2; mf++)
#pragma unroll
                for (int rh = 0; rh < 2; rh++) {
                    int v = u[mf][nf][rh * 2 + jj];
                    s += v; s2 += v * v;
                }
#pragma unroll
            for (int m = 4; m < 32; m <<= 1) {
                s  += __shfl_xor_sync(~0u, s, m);
                s2 += __shfl_xor_sync(~0u, s2, m);
            }
            if (lane < 4) {
                int c = n0 + wn * 32 + nf * 8 + 2 * lane + jj;
                atomicAdd(&g_isum[c],   (unsigned long long)(long long)s);
                atomicAdd(&g_isumsq[c], (unsigned long long)(long long)s2);
            }
        }
    }
#pragma unroll
    for (int mf = 0; mf < 2; mf++) {
#pragma unroll
        for (int rh = 0; rh < 2; rh++) {
            int p2 = m0 + wm * 32 + mf * 16 + (lane >> 2) + rh * 8;
            int b2 = p2 / HWs, hw2 = p2 - b2 * HWs;
            short* yd = g_y16 + (size_t)b2 * CHW + hw2;
#pragma unroll
            for (int nf = 0; nf < 4; nf++) {
                int c = n0 + wn * 32 + nf * 8 + 2 * (lane & 3);
                yd[(size_t)c * HWs]       = (short)u[mf][nf][rh * 2 + 0];
                yd[(size_t)(c + 1) * HWs] = (short)u[mf][nf][rh * 2 + 1];
            }
        }
    }
}

// ---------------------------------------------------------------------------
// Unified hybrid kernel: Bresenham-interleaved popc / IMMA blocks
// ---------------------------------------------------------------------------
__global__ __launch_bounds__(256, 3) void gemm_kernel() {
    extern __shared__ uint32_t smem[];
    const uint32_t bid = blockIdx.x;
    const uint32_t before = (bid * (uint32_t)IMMA_BLOCKS) / (uint32_t)TOT_BLOCKS;
    const uint32_t after  = ((bid + 1) * (uint32_t)IMMA_BLOCKS) / (uint32_t)TOT_BLOCKS;
    if (after > before)
        imma_block(smem, (int)before);
    else
        popc_block(smem, (int)(bid - before));
}

// ---------------------------------------------------------------------------
// Kernel: BN affine coefficients (exact integer stats, weight scale folded)
// ---------------------------------------------------------------------------
__global__ void coeff_kernel(const float* __restrict__ gamma, const float* __restrict__ beta) {
    int c = threadIdx.x;
    double n  = (double)PIX;
    double mu = (double)(long long)g_isum[c] / n;
    double vu = (double)(long long)g_isumsq[c] / n - mu * mu;
    double sc = (double)g_scale[c];
    double A  = (double)gamma[c] * sc / sqrt(sc * sc * vu + (double)BN_EPS);
    g_ab[c]      = (float)A;
    g_ab[CC + c] = (float)((double)beta[c] - A * mu);
}

// ---------------------------------------------------------------------------
// Kernel: out = relu(A*u + B), int16 -> fp32, NCHW
// ---------------------------------------------------------------------------
__global__ void finalize_kernel(float* __restrict__ out) {
    size_t idx = (size_t)blockIdx.x * 256 + threadIdx.x;   // one per 8 elems
    size_t j = idx * 8;
    int c = (int)((j / HWs) & 255);
    float A = g_ab[c], Bv = g_ab[CC + c];
    uint4 raw = ((const uint4*)g_y16)[idx];
    float4 o0, o1;
    o0.x = fmaxf(fmaf((float)(short)(raw.x & 0xffff), A, Bv), 0.0f);
    o0.y = fmaxf(fmaf((float)(short)(raw.x >> 16),    A, Bv), 0.0f);
    o0.z = fmaxf(fmaf((float)(short)(raw.y & 0xffff), A, Bv), 0.0f);
    o0.w = fmaxf(fmaf((float)(short)(raw.y >> 16),    A, Bv), 0.0f);
    o1.x = fmaxf(fmaf((float)(short)(raw.z & 0xffff), A, Bv), 0.0f);
    o1.y = fmaxf(fmaf((float)(short)(raw.z >> 16),    A, Bv), 0.0f);
    o1.z = fmaxf(fmaf((float)(short)(raw.w & 0xffff), A, Bv), 0.0f);
    o1.w = fmaxf(fmaf((float)(short)(raw.w >> 16),    A, Bv), 0.0f);
    ((float4*)out)[idx * 2]     = o0;
    ((float4*)out)[idx * 2 + 1] = o1;
}

// ---------------------------------------------------------------------------
// Launch (gemm is launch index 3 so the profiler lands on it)
// ---------------------------------------------------------------------------
extern "C" void kernel_launch(void* const* d_in, const int* in_sizes, int n_in,
                              void* d_out, int out_size) {
    (void)in_sizes; (void)n_in; (void)out_size;
    const float* x     = (const float*)d_in[0];
    const float* wt    = (const float*)d_in[1];
    const float* gamma = (const float*)d_in[2];
    const float* beta  = (const float*)d_in[3];
    float* out = (float*)d_out;

    static int smem_set = 0;
    if (!smem_set) {
        cudaFuncSetAttribute(gemm_kernel, cudaFuncAttributeMaxDynamicSharedMemorySize,
                             SMEM_DYN);
        smem_set = 1;
    }

    wprep_kernel<<<256, 256>>>(wt);
    zero_xp_kernel<<<(BB * HP * WP * 8 / 4) / 256, 256>>>();
    xpack_kernel<<<dim3(HH, BB), 256>>>(x);
    gemm_kernel<<<TOT_BLOCKS, 256, SMEM_DYN>>>();
    coeff_kernel<<<1, 256>>>(gamma, beta);
    finalize_kernel<<<(int)((size_t)PIX * CC / 8 / 256), 256>>>(out);
}

// round 9
// speedup vs baseline: 1.1301x; 1.1301x over previous
#include <cuda_runtime.h>
#include <cstdint>

// ---------------------------------------------------------------------------
// Problem constants
// ---------------------------------------------------------------------------
constexpr int BB = 32, CC = 256, HH = 56, WW = 56;
constexpr int HP = 58, WP = 58;                 // padded spatial
constexpr int HWs = HH * WW;                    // 3136
constexpr int CHW = CC * HWs;                   // 802816
constexpr int PIX = BB * HWs;                   // 100352
constexpr int KW  = 72;                         // K in 32-bit words (2304 bits)
constexpr int KD  = 2304;                       // K in int8 elements
constexpr int KBITS = 2304;
constexpr float BN_EPS = 1e-5f;

// ---- hybrid split: popc covers pixels [0, 69376), IMMA covers the rest ----
constexpr int TM = 64;                          // popc CTA pixel tile
constexpr int TN = 128;                         // popc CTA cout tile
constexpr int POPC_MTILES = 1084;               // 1084*64 = 69376 pixels
constexpr int IMMA_PIX0  = POPC_MTILES * TM;    // 69376
constexpr int IMMA_B0    = 22;                  // first batch containing IMMA pixels
constexpr int IMMA_NB    = 10;                  // batches 22..31 need int8 xa
constexpr int IMMA_MTILES = 484;                // 484*64 = 30976 pixels
constexpr int POPC_BLOCKS = POPC_MTILES * 2;    // 2168  (2 x 128-cout halves)
constexpr int IMMA_BLOCKS = IMMA_MTILES * 4;    // 1936  (4 x 64-cout quarters)
constexpr int TOT_BLOCKS  = POPC_BLOCKS + IMMA_BLOCKS;  // 4104

// popc smem: W tile [72][128] + X tile [72][64] words
constexpr int SW_WORDS = KW * TN;               // 9216
constexpr int SX_WORDS = KW * TM;               // 4608
constexpr int SMEM_DYN = (SW_WORDS + SX_WORDS) * 4;   // 55296 B

// IMMA smem: 3 stages of (A 64x80 + B 64x80) int8 = 30720 <= 55296
constexpr int ISSTR = 80;
constexpr int IA_BYTES = 64 * ISSTR;            // 5120
constexpr int ISTAGE = 2 * IA_BYTES;            // 10240

// ---------------------------------------------------------------------------
// Device scratch (allocation-free: __device__ globals)
// ---------------------------------------------------------------------------
__device__ uint32_t g_xp[(size_t)BB * HP * WP * 8];   // packed x, padded NHWC, 3.4MB
__device__ uint4    g_xa8_raw[(size_t)IMMA_NB * HP * WP * CC / 16]; // int8 xa, 8.6MB
__device__ uint32_t g_wpT[KW * CC];                   // packed w, [k][cout]
__device__ uint4    g_wb_raw[(size_t)CC * KD / 16];   // int8 w, [co][tap*256+ci]
__device__ int      g_corr[9 * CC];                   // border corrections (popc)
__device__ short    g_y16[(size_t)PIX * CC];          // conv result, NCHW int16, 51MB
__device__ float    g_scale[CC];
__device__ unsigned long long g_isum[CC];
__device__ unsigned long long g_isumsq[CC];
__device__ float    g_ab[2 * CC];

#define G_WB  ((int8_t*)g_wb_raw)
#define G_XA8 ((int8_t*)g_xa8_raw)
constexpr int XP_U4  = (int)((size_t)BB * HP * WP * 8 / 4);          // 215296
constexpr int XA8_U4 = (int)((size_t)IMMA_NB * HP * WP * CC / 16);   // 538240

// ---------------------------------------------------------------------------
// PTX helpers (baseline, assemble at .target sm_103)
// ---------------------------------------------------------------------------
__device__ __forceinline__ uint32_t smem_to_u32(const void* p) {
    uint32_t a;
    asm("{ .reg .u64 t; cvta.to.shared.u64 t, %1; cvt.u32.u64 %0, t; }" : "=r"(a) : "l"(p));
    return a;
}
__device__ __forceinline__ void cp16(uint32_t dst, const void* src) {
    asm volatile("cp.async.cg.shared.global [%0], [%1], 16;" :: "r"(dst), "l"(src));
}
#define CP_COMMIT() asm volatile("cp.async.commit_group;" ::: "memory")
#define CP_WAIT1()  asm volatile("cp.async.wait_group 1;" ::: "memory")
__device__ __forceinline__ void ldsm4(uint32_t& r0, uint32_t& r1, uint32_t& r2,
                                      uint32_t& r3, uint32_t addr) {
    asm volatile("ldmatrix.sync.aligned.m8n8.x4.shared.b16 {%0,%1,%2,%3}, [%4];"
                 : "=r"(r0), "=r"(r1), "=r"(r2), "=r"(r3) : "r"(addr));
}
__device__ __forceinline__ void mma_s8(int* d, uint32_t a0, uint32_t a1,
                                       uint32_t a2, uint32_t a3,
                                       uint32_t b0, uint32_t b1) {
    asm volatile(
        "mma.sync.aligned.m16n8k32.row.col.s32.s8.s8.s32 "
        "{%0,%1,%2,%3}, {%4,%5,%6,%7}, {%8,%9}, {%0,%1,%2,%3};"
        : "+r"(d[0]), "+r"(d[1]), "+r"(d[2]), "+r"(d[3])
        : "r"(a0), "r"(a1), "r"(a2), "r"(a3), "r"(b0), "r"(b1));
}

// ---------------------------------------------------------------------------
// Kernel: weight prep — scale, packed bits [k][o], int8 signs [o][tap*256+ci],
// border-correction table, zero integer BN accumulators.
// ---------------------------------------------------------------------------
__global__ void wprep_kernel(const float* __restrict__ w) {
    int o = blockIdx.x, tid = threadIdx.x;
    int lane = tid & 31, warp = tid >> 5;
    const float* wp = w + ((size_t)o * CC + tid) * 9;
    float v[9]; float s = 0.0f;
#pragma unroll
    for (int t = 0; t < 9; t++) { v[t] = wp[t]; s += fabsf(v[t]); }
#pragma unroll
    for (int off = 16; off; off >>= 1) s += __shfl_xor_sync(~0u, s, off);
    __shared__ float sh[8];
    __shared__ uint32_t words[9][8];
    __shared__ int S[9];
    if (lane == 0) sh[warp] = s;

#pragma unroll
    for (int t = 0; t < 9; t++) {
        uint32_t m = __ballot_sync(~0u, v[t] > 0.0f);
        if (lane == 0) words[t][warp] = m;
        // match popc convention exactly: x>0 -> +1 else -1 style sign for w:
        int sg = (v[t] > 0.0f) ? 1 : ((v[t] < 0.0f) ? -1 : 0);
        G_WB[(size_t)o * KD + t * 256 + tid] = (int8_t)sg;
    }
    __syncthreads();
    if (tid == 0) {
        float tot = 0.0f;
        for (int i = 0; i < 8; i++) tot += sh[i];
        g_scale[o] = tot / (float)KBITS;
        g_isum[o] = 0ull; g_isumsq[o] = 0ull;
    }
    if (tid < 72) {
        int t = tid >> 3, j = tid & 7;
        g_wpT[(t * 8 + j) * CC + o] = words[t][j];
    }
    if (tid < 9) {
        int P = 0;
        for (int j = 0; j < 8; j++) P += __popc(words[tid][j]);
        S[tid] = 2 * P - 256;          // sum_ci sign(w[o][ci][tap])
    }
    __syncthreads();
    if (tid < 9) {                      // tid = border category ht*3+wt
        int ht = tid / 3, wt = tid % 3;
        int corr = 0;
        for (int kh = 0; kh < 3; kh++)
            for (int kw = 0; kw < 3; kw++) {
                bool miss = (ht == 0 && kh == 0) || (ht == 2 && kh == 2) ||
                            (wt == 0 && kw == 0) || (wt == 2 && kw == 2);
                if (miss) corr += S[kh * 3 + kw];
            }
        g_corr[tid * CC + o] = corr;
    }
}

// ---------------------------------------------------------------------------
// Kernel: zero packed-x + int8-xa buffers (pad rings must be 0)
// ---------------------------------------------------------------------------
__global__ void zero_xp_kernel() {
    int i = blockIdx.x * 256 + threadIdx.x;
    if (i < XP_U4) ((uint4*)g_xp)[i] = make_uint4(0, 0, 0, 0);
    else if (i < XP_U4 + XA8_U4) g_xa8_raw[i - XP_U4] = make_uint4(0, 0, 0, 0);
}

// ---------------------------------------------------------------------------
// Kernel: pack sign bits of x (all batches) + int8 xa (batches >= 22)
// ---------------------------------------------------------------------------
__global__ void xpack_kernel(const float* __restrict__ x) {
    int h = blockIdx.x, b = blockIdx.y;
    __shared__ float tile[64][57];
    int tid = threadIdx.x;
    int lane = tid & 31, warp = tid >> 5;
    // bit-pack path (warp-per-channel-word)
    const float4* xrow =
        (const float4*)(x + (((size_t)(b * CC + warp * 32 + lane)) * HH + h) * WW);
    uint32_t* base = &g_xp[(((size_t)(b * HP + h + 1)) * WP + 1) * 8 + warp];
    for (int w0 = 0; w0 < WW; w0 += 4) {
        float4 v = xrow[w0 >> 2];
        uint32_t m0 = __ballot_sync(~0u, v.x > 0.0f);
        uint32_t m1 = __ballot_sync(~0u, v.y > 0.0f);
        uint32_t m2 = __ballot_sync(~0u, v.z > 0.0f);
        uint32_t m3 = __ballot_sync(~0u, v.w > 0.0f);
        if (lane == 0) {
            base[(w0 + 0) * 8] = m0; base[(w0 + 1) * 8] = m1;
            base[(w0 + 2) * 8] = m2; base[(w0 + 3) * 8] = m3;
        }
    }
    // int8 path for IMMA batches
    if (b >= IMMA_B0) {
        int bp = b - IMMA_B0;
        for (int cb = 0; cb < 4; cb++) {
            __syncthreads();
            for (int idx = tid; idx < 64 * 56; idx += 256) {
                int ci = idx / 56, w = idx - ci * 56;
                tile[ci][w] = x[((size_t)(b * CC + cb * 64 + ci) * HH + h) * WW + w];
            }
            __syncthreads();
            for (int idx = tid; idx < 56 * 16; idx += 256) {
                int w = idx >> 4, g = idx & 15;
                uint32_t packed = 0;
#pragma unroll
                for (int k = 0; k < 4; k++) {
                    float v = tile[g * 4 + k][w];
                    uint32_t byte = (v > 0.0f) ? 0x01u : 0xFFu;   // +1 / -1
                    packed |= byte << (k * 8);
                }
                *(uint32_t*)&G_XA8[(((size_t)(bp * HP + h + 1) * WP + (w + 1)) * CC) +
                                   cb * 64 + g * 4] = packed;
            }
        }
    }
}

// ---------------------------------------------------------------------------
// Shared epilogue helper
// ---------------------------------------------------------------------------
__device__ __forceinline__ int pixel_cat(int p) {
    int hw = p % HWs;
    int h = hw / WW, w = hw - h * WW;
    int ht = (h == 0) ? 0 : ((h == HH - 1) ? 2 : 1);
    int wt = (w == 0) ? 0 : ((w == WW - 1) ? 2 : 1);
    return ht * 3 + wt;
}

// ---------------------------------------------------------------------------
// popc block: 64 pixels x 128 couts (proven R6 body)
// ---------------------------------------------------------------------------
__device__ __forceinline__ void popc_block(uint32_t* smem, int q) {
    uint32_t* sW = smem;                // [72][128]
    uint32_t* sX = smem + SW_WORDS;     // [72][64]
    const int tid = threadIdx.x;
    const int lane = tid & 31;
    const int p0 = (q >> 1) * TM;
    const int n0 = (q & 1) * TN;

    {
        int col = tid & 127, khalf = tid >> 7;
        for (int k = khalf; k < KW; k += 2)
            sW[k * TN + col] = g_wpT[k * CC + n0 + col];
    }
    for (int idx = tid; idx < 576; idx += 256) {
        int pix = idx & 63, tap = idx >> 6;
        int p = p0 + pix;
        int b = p / HWs, hw = p - b * HWs;
        int h = hw / WW, w = hw - h * WW;
        int kh = tap / 3, kw = tap - 3 * kh;
        const uint4* src =
            (const uint4*)&g_xp[(((size_t)(b * HP + h + kh)) * WP + (w + kw)) * 8];
        uint4 q0 = src[0], q1 = src[1];
        int kb = tap * 8;
        sX[(kb + 0) * TM + pix] = q0.x; sX[(kb + 1) * TM + pix] = q0.y;
        sX[(kb + 2) * TM + pix] = q0.z; sX[(kb + 3) * TM + pix] = q0.w;
        sX[(kb + 4) * TM + pix] = q1.x; sX[(kb + 5) * TM + pix] = q1.y;
        sX[(kb + 6) * TM + pix] = q1.z; sX[(kb + 7) * TM + pix] = q1.w;
    }
    __syncthreads();

    const int pg = tid & 15;
    const int cg = tid >> 4;
    const uint4* sXv = (const uint4*)sX;
    const uint4* sWv = (const uint4*)sW;

    int acc[4][8];
#pragma unroll
    for (int i = 0; i < 4; i++)
#pragma unroll
        for (int j = 0; j < 8; j++) acc[i][j] = 0;

#pragma unroll 2
    for (int k = 0; k < KW; k += 2) {
        uint4 xq0 = sXv[k * 16 + pg];
        uint4 xq1 = sXv[(k + 1) * 16 + pg];
        uint32_t xs0[4] = {xq0.x, xq0.y, xq0.z, xq0.w};
        uint32_t xs1[4] = {xq1.x, xq1.y, xq1.z, xq1.w};
        {
            uint4 w0 = sWv[k * 32 + cg * 2];
            uint4 w1 = sWv[(k + 1) * 32 + cg * 2];
            uint32_t ws0[4] = {w0.x, w0.y, w0.z, w0.w};
            uint32_t ws1[4] = {w1.x, w1.y, w1.z, w1.w};
#pragma unroll
            for (int i = 0; i < 4; i++)
#pragma unroll
                for (int j = 0; j < 4; j++)
                    acc[i][j] += __popc(xs0[i] ^ ws0[j]) + __popc(xs1[i] ^ ws1[j]);
        }
        {
            uint4 w0 = sWv[k * 32 + cg * 2 + 1];
            uint4 w1 = sWv[(k + 1) * 32 + cg * 2 + 1];
            uint32_t ws0[4] = {w0.x, w0.y, w0.z, w0.w};
            uint32_t ws1[4] = {w1.x, w1.y, w1.z, w1.w};
#pragma unroll
            for (int i = 0; i < 4; i++)
#pragma unroll
                for (int j = 0; j < 4; j++)
                    acc[i][j + 4] += __popc(xs0[i] ^ ws0[j]) + __popc(xs1[i] ^ ws1[j]);
        }
    }

    int pcat[4];
#pragma unroll
    for (int i = 0; i < 4; i++) pcat[i] = pixel_cat(p0 + pg * 4 + i);
    int u[4][8];
#pragma unroll
    for (int j = 0; j < 8; j++) {
        int c = n0 + cg * 8 + j;
#pragma unroll
        for (int i = 0; i < 4; i++) {
            int corr = (pcat[i] == 4) ? 0 : g_corr[pcat[i] * CC + c];
            u[i][j] = KBITS - 2 * acc[i][j] + corr;
        }
    }

#pragma unroll
    for (int j = 0; j < 8; j++) {
        int s = 0, s2 = 0;
#pragma unroll
        for (int i = 0; i < 4; i++) { s += u[i][j]; s2 += u[i][j] * u[i][j]; }
#pragma unroll
        for (int m = 1; m < 16; m <<= 1) {
            s  += __shfl_xor_sync(~0u, s, m);
            s2 += __shfl_xor_sync(~0u, s2, m);
        }
        if ((lane & 15) == 0) {
            int c = n0 + cg * 8 + j;
            atomicAdd(&g_isum[c],   (unsigned long long)(long long)s);
            atomicAdd(&g_isumsq[c], (unsigned long long)(long long)s2);
        }
    }
    {
        int p2 = p0 + pg * 4;
        int b2 = p2 / HWs, hw2 = p2 - b2 * HWs;
        short* yd = g_y16 + (size_t)b2 * CHW + hw2;
#pragma unroll
        for (int j = 0; j < 8; j++) {
            int c = n0 + cg * 8 + j;
            uint2 val;
            val.x = (uint32_t)(u[0][j] & 0xffff) | ((uint32_t)u[1][j] << 16);
            val.y = (uint32_t)(u[2][j] & 0xffff) | ((uint32_t)u[3][j] << 16);
            *(uint2*)&yd[(size_t)c * HWs] = val;
        }
    }
}

// ---------------------------------------------------------------------------
// IMMA block: 64 pixels x 64 couts; cp.async 3-stage, 1 barrier per chunk.
// True zero padding (int8 xa pad ring = 0) -> no border correction needed.
// ---------------------------------------------------------------------------
__device__ __forceinline__ void imma_block(uint32_t* smem32, int jb) {
    char* smem = (char*)smem32;
    const uint32_t sbase = smem_to_u32(smem);
    const int tid = threadIdx.x;
    const int wid = tid >> 5;
    const int lane = tid & 31;
    const int wm = wid & 3;          // 16-px block
    const int wn = wid >> 2;         // 32-cout block (0..1)
    const int m0 = IMMA_PIX0 + (jb >> 2) * 64;
    const int n0 = (jb & 3) * 64;

    // staging: thread covers row r = tid>>2 (pixel & cout row), 16B quarter q
    const int r = tid >> 2, qq = tid & 3;
    int p = m0 + r;
    int b = p / HWs; int hw = p - b * HWs;
    int h = hw / WW; int w = hw - h * WW;
    const int8_t* asrc =
        G_XA8 + (((size_t)((b - IMMA_B0) * HP + h)) * WP + w) * CC + qq * 16;
    const int8_t* bsrc = G_WB + (size_t)(n0 + r) * KD + qq * 16;
    const uint32_t sdstA = (uint32_t)(r * ISSTR + qq * 16);
    const uint32_t sdstB = (uint32_t)(IA_BYTES + r * ISSTR + qq * 16);

    auto issue = [&](int kc) {
        int buf = kc % 3;
        int tap = kc >> 2;
        int ci0 = (kc & 3) * 64;
        int kh = tap / 3, kw = tap - 3 * kh;
        cp16(sbase + buf * ISTAGE + sdstA, asrc + ((kh * WP + kw) * CC + ci0));
        cp16(sbase + buf * ISTAGE + sdstB, bsrc + tap * 256 + ci0);
    };

    int acc[4][4];
#pragma unroll
    for (int nf = 0; nf < 4; nf++)
#pragma unroll
        for (int i = 0; i < 4; i++) acc[nf][i] = 0;

    const int lrow = lane & 15;
    const int lko  = (lane >> 4) * 16;
    const uint32_t aFrag = (uint32_t)((wm * 16 + lrow) * ISSTR + lko);
    const uint32_t bFrag = (uint32_t)(IA_BYTES + (wn * 32 + lrow) * ISSTR + lko);

    issue(0); CP_COMMIT();
    issue(1); CP_COMMIT();
    for (int kc = 0; kc < 36; kc++) {
        CP_WAIT1();
        __syncthreads();
        if (kc + 2 < 36) issue(kc + 2);
        CP_COMMIT();
        const uint32_t sb = sbase + (kc % 3) * ISTAGE;
#pragma unroll
        for (int s = 0; s < 2; s++) {
            uint32_t a0, a1, a2, a3;
            ldsm4(a0, a1, a2, a3, sb + aFrag + s * 32);
#pragma unroll
            for (int nb = 0; nb < 2; nb++) {
                uint32_t b0, b1, b2, b3;
                ldsm4(b0, b1, b2, b3, sb + bFrag + nb * 16 * ISSTR + s * 32);
                mma_s8(acc[2 * nb],     a0, a1, a2, a3, b0, b2);
                mma_s8(acc[2 * nb + 1], a0, a1, a2, a3, b1, b3);
            }
        }
    }

    // ---- epilogue: exact conv (zero padding), fused stats, int16 store ----
#pragma unroll
    for (int nf = 0; nf < 4; nf++) {
#pragma unroll
        for (int jj = 0; jj < 2; jj++) {
            int s = 0, s2 = 0;
#pragma unroll
            for (int rh = 0; rh < 2; rh++) {
                int v = acc[nf][rh * 2 + jj];
                s += v; s2 += v * v;
            }
#pragma unroll
            for (int m = 4; m < 32; m <<= 1) {
                s  += __shfl_xor_sync(~0u, s, m);
                s2 += __shfl_xor_sync(~0u, s2, m);
            }
            if (lane < 4) {
                int c = n0 + wn * 32 + nf * 8 + 2 * lane + jj;
                atomicAdd(&g_isum[c],   (unsigned long long)(long long)s);
                atomicAdd(&g_isumsq[c], (unsigned long long)(long long)s2);
            }
        }
    }
#pragma unroll
    for (int rh = 0; rh < 2; rh++) {
        int p2 = m0 + wm * 16 + (lane >> 2) + rh * 8;
        int b2 = p2 / HWs, hw2 = p2 - b2 * HWs;
        short* yd = g_y16 + (size_t)b2 * CHW + hw2;
#pragma unroll
        for (int nf = 0; nf < 4; nf++) {
            int c = n0 + wn * 32 + nf * 8 + 2 * (lane & 3);
            yd[(size_t)c * HWs]       = (short)acc[nf][rh * 2 + 0];
            yd[(size_t)(c + 1) * HWs] = (short)acc[nf][rh * 2 + 1];
        }
    }
}

// ---------------------------------------------------------------------------
// Unified hybrid kernel: Bresenham-interleaved popc / IMMA blocks
// ---------------------------------------------------------------------------
__global__ __launch_bounds__(256, 3) void gemm_kernel() {
    extern __shared__ uint32_t smem[];
    const uint32_t bid = blockIdx.x;
    const uint32_t before = (bid * (uint32_t)IMMA_BLOCKS) / (uint32_t)TOT_BLOCKS;
    const uint32_t after  = ((bid + 1) * (uint32_t)IMMA_BLOCKS) / (uint32_t)TOT_BLOCKS;
    if (after > before)
        imma_block(smem, (int)before);
    else
        popc_block(smem, (int)(bid - before));
}

// ---------------------------------------------------------------------------
// Kernel: BN affine coefficients (exact integer stats, weight scale folded)
// ---------------------------------------------------------------------------
__global__ void coeff_kernel(const float* __restrict__ gamma, const float* __restrict__ beta) {
    int c = threadIdx.x;
    double n  = (double)PIX;
    double mu = (double)(long long)g_isum[c] / n;
    double vu = (double)(long long)g_isumsq[c] / n - mu * mu;
    double sc = (double)g_scale[c];
    double A  = (double)gamma[c] * sc / sqrt(sc * sc * vu + (double)BN_EPS);
    g_ab[c]      = (float)A;
    g_ab[CC + c] = (float)((double)beta[c] - A * mu);
}

// ---------------------------------------------------------------------------
// Kernel: out = relu(A*u + B), int16 -> fp32, NCHW
// ---------------------------------------------------------------------------
__global__ void finalize_kernel(float* __restrict__ out) {
    size_t idx = (size_t)blockIdx.x * 256 + threadIdx.x;   // one per 8 elems
    size_t j = idx * 8;
    int c = (int)((j / HWs) & 255);
    float A = g_ab[c], Bv = g_ab[CC + c];
    uint4 raw = ((const uint4*)g_y16)[idx];
    float4 o0, o1;
    o0.x = fmaxf(fmaf((float)(short)(raw.x & 0xffff), A, Bv), 0.0f);
    o0.y = fmaxf(fmaf((float)(short)(raw.x >> 16),    A, Bv), 0.0f);
    o0.z = fmaxf(fmaf((float)(short)(raw.y & 0xffff), A, Bv), 0.0f);
    o0.w = fmaxf(fmaf((float)(short)(raw.y >> 16),    A, Bv), 0.0f);
    o1.x = fmaxf(fmaf((float)(short)(raw.z & 0xffff), A, Bv), 0.0f);
    o1.y = fmaxf(fmaf((float)(short)(raw.z >> 16),    A, Bv), 0.0f);
    o1.z = fmaxf(fmaf((float)(short)(raw.w & 0xffff), A, Bv), 0.0f);
    o1.w = fmaxf(fmaf((float)(short)(raw.w >> 16),    A, Bv), 0.0f);
    ((float4*)out)[idx * 2]     = o0;
    ((float4*)out)[idx * 2 + 1] = o1;
}

// ---------------------------------------------------------------------------
// Launch (gemm stays at launch index 3 so the profiler lands on it)
// ---------------------------------------------------------------------------
extern "C" void kernel_launch(void* const* d_in, const int* in_sizes, int n_in,
                              void* d_out, int out_size) {
    (void)in_sizes; (void)n_in; (void)out_size;
    const float* x     = (const float*)d_in[0];
    const float* wt    = (const float*)d_in[1];
    const float* gamma = (const float*)d_in[2];
    const float* beta  = (const float*)d_in[3];
    float* out = (float*)d_out;

    static int smem_set = 0;
    if (!smem_set) {
        cudaFuncSetAttribute(gemm_kernel, cudaFuncAttributeMaxDynamicSharedMemorySize,
                             SMEM_DYN);
        smem_set = 1;
    }

    wprep_kernel<<<256, 256>>>(wt);
    zero_xp_kernel<<<(XP_U4 + XA8_U4 + 255) / 256, 256>>>();
    xpack_kernel<<<dim3(HH, BB), 256>>>(x);
    gemm_kernel<<<TOT_BLOCKS, 256, SMEM_DYN>>>();
    coeff_kernel<<<1, 256>>>(gamma, beta);
    finalize_kernel<<<(int)((size_t)PIX * CC / 8 / 256), 256>>>(out);
}

// round 13
// speedup vs baseline: 1.2363x; 1.0940x over previous
#include <cuda_runtime.h>
#include <cstdint>

// ---------------------------------------------------------------------------
// Problem constants
// ---------------------------------------------------------------------------
constexpr int BB = 32, CC = 256, HH = 56, WW = 56;
constexpr int HP = 58, WP = 58;                 // padded spatial
constexpr int HWs = HH * WW;                    // 3136
constexpr int CHW = CC * HWs;                   // 802816
constexpr int PIX = BB * HWs;                   // 100352
constexpr int KW  = 72;                         // K in 32-bit words (2304 bits)
constexpr int KD  = 2304;                       // K in int8 elements
constexpr int KBITS = 2304;
constexpr float BN_EPS = 1e-5f;

// ---- fused split: popc pixels [0,66816), IMMA [66816,100224), 128 leftover
constexpr int POPC_PT   = 1044;                 // 64px tiles -> 66816 px
constexpr int IMMA_PIX0 = POPC_PT * 64;         // 66816
constexpr int IMMA_B0   = 21;                   // first batch holding IMMA px
constexpr int IMMA_NB   = 11;                   // batches 21..31 -> int8 xa
constexpr int FUSED_BLOCKS = POPC_PT * 4;       // 4176 (4 cout quarters)
constexpr int LEFT_PIX0 = IMMA_PIX0 + POPC_PT * 32;   // 100224
constexpr int TOT_BLOCKS = FUSED_BLOCKS + 4;    // + 4 pure popc blocks

// smem layout (fused CTA): IMMA 3 stages then popc W/X tiles
constexpr int ISSTR = 80;
constexpr int IA_BYTES = 32 * ISSTR;            // 2560
constexpr int IB_BYTES = 64 * ISSTR;            // 5120
constexpr int ISTAGE = IA_BYTES + IB_BYTES;     // 7680, x3 = 23040
constexpr int PW_OFF = 23040 / 4;               // word offset of popc W [72][64]
constexpr int PX_OFF = PW_OFF + KW * 64;        // popc X [72][64]
constexpr int SMEM_DYN = (PX_OFF + KW * 64) * 4;   // 59904 B

// pure popc leftover block (R9 layout): W [72][128] at 0, X [72][64] after
constexpr int SW_WORDS = KW * 128;              // 9216 (words)

// ---------------------------------------------------------------------------
// Device scratch (allocation-free: __device__ globals)
// ---------------------------------------------------------------------------
__device__ uint32_t g_xp[(size_t)BB * HP * WP * 8];   // packed x, padded NHWC
__device__ uint4    g_xa8_raw[(size_t)IMMA_NB * HP * WP * CC / 16]; // int8 xa
__device__ uint32_t g_wpT[KW * CC];                   // packed w, [k][cout]
__device__ uint4    g_wb_raw[(size_t)CC * KD / 16];   // int8 w, [co][tap*256+ci]
__device__ int      g_corr[9 * CC];                   // border corrections
__device__ short    g_y16[(size_t)PIX * CC];          // conv result, NCHW int16
__device__ float    g_scale[CC];
__device__ unsigned long long g_isum[CC];
__device__ unsigned long long g_isumsq[CC];
__device__ float    g_ab[2 * CC];

#define G_WB  ((int8_t*)g_wb_raw)
#define G_XA8 ((int8_t*)g_xa8_raw)
constexpr int XP_U4  = (int)((size_t)BB * HP * WP * 8 / 4);
constexpr int XA8_U4 = (int)((size_t)IMMA_NB * HP * WP * CC / 16);

// ---------------------------------------------------------------------------
// PTX helpers (baseline, assemble at .target sm_103)
// ---------------------------------------------------------------------------
__device__ __forceinline__ uint32_t smem_to_u32(const void* p) {
    uint32_t a;
    asm("{ .reg .u64 t; cvta.to.shared.u64 t, %1; cvt.u32.u64 %0, t; }" : "=r"(a) : "l"(p));
    return a;
}
__device__ __forceinline__ void cp16(uint32_t dst, const void* src) {
    asm volatile("cp.async.cg.shared.global [%0], [%1], 16;" :: "r"(dst), "l"(src));
}
#define CP_COMMIT() asm volatile("cp.async.commit_group;" ::: "memory")
#define CP_WAIT1()  asm volatile("cp.async.wait_group 1;" ::: "memory")
#define BAR_SYNC(id, cnt) \
    asm volatile("bar.sync %0, %1;" :: "r"(id), "r"(cnt) : "memory")
__device__ __forceinline__ void ldsm4(uint32_t& r0, uint32_t& r1, uint32_t& r2,
                                      uint32_t& r3, uint32_t addr) {
    asm volatile("ldmatrix.sync.aligned.m8n8.x4.shared.b16 {%0,%1,%2,%3}, [%4];"
                 : "=r"(r0), "=r"(r1), "=r"(r2), "=r"(r3) : "r"(addr));
}
__device__ __forceinline__ void mma_s8(int* d, uint32_t a0, uint32_t a1,
                                       uint32_t a2, uint32_t a3,
                                       uint32_t b0, uint32_t b1) {
    asm volatile(
        "mma.sync.aligned.m16n8k32.row.col.s32.s8.s8.s32 "
        "{%0,%1,%2,%3}, {%4,%5,%6,%7}, {%8,%9}, {%0,%1,%2,%3};"
        : "+r"(d[0]), "+r"(d[1]), "+r"(d[2]), "+r"(d[3])
        : "r"(a0), "r"(a1), "r"(a2), "r"(a3), "r"(b0), "r"(b1));
}

// ---------------------------------------------------------------------------
// Kernel: weight prep
// ---------------------------------------------------------------------------
__global__ void wprep_kernel(const float* __restrict__ w) {
    int o = blockIdx.x, tid = threadIdx.x;
    int lane = tid & 31, warp = tid >> 5;
    const float* wp = w + ((size_t)o * CC + tid) * 9;
    float v[9]; float s = 0.0f;
#pragma unroll
    for (int t = 0; t < 9; t++) { v[t] = wp[t]; s += fabsf(v[t]); }
#pragma unroll
    for (int off = 16; off; off >>= 1) s += __shfl_xor_sync(~0u, s, off);
    __shared__ float sh[8];
    __shared__ uint32_t words[9][8];
    __shared__ int S[9];
    if (lane == 0) sh[warp] = s;

#pragma unroll
    for (int t = 0; t < 9; t++) {
        uint32_t m = __ballot_sync(~0u, v[t] > 0.0f);
        if (lane == 0) words[t][warp] = m;
        int sg = (v[t] > 0.0f) ? 1 : ((v[t] < 0.0f) ? -1 : 0);
        G_WB[(size_t)o * KD + t * 256 + tid] = (int8_t)sg;
    }
    __syncthreads();
    if (tid == 0) {
        float tot = 0.0f;
        for (int i = 0; i < 8; i++) tot += sh[i];
        g_scale[o] = tot / (float)KBITS;
        g_isum[o] = 0ull; g_isumsq[o] = 0ull;
    }
    if (tid < 72) {
        int t = tid >> 3, j = tid & 7;
        g_wpT[(t * 8 + j) * CC + o] = words[t][j];
    }
    if (tid < 9) {
        int P = 0;
        for (int j = 0; j < 8; j++) P += __popc(words[tid][j]);
        S[tid] = 2 * P - 256;
    }
    __syncthreads();
    if (tid < 9) {
        int ht = tid / 3, wt = tid % 3;
        int corr = 0;
        for (int kh = 0; kh < 3; kh++)
            for (int kw = 0; kw < 3; kw++) {
                bool miss = (ht == 0 && kh == 0) || (ht == 2 && kh == 2) ||
                            (wt == 0 && kw == 0) || (wt == 2 && kw == 2);
                if (miss) corr += S[kh * 3 + kw];
            }
        g_corr[tid * CC + o] = corr;
    }
}

// ---------------------------------------------------------------------------
// Kernel: zero packed-x + int8-xa buffers (pad rings must be 0)
// ---------------------------------------------------------------------------
__global__ void zero_xp_kernel() {
    int i = blockIdx.x * 256 + threadIdx.x;
    if (i < XP_U4) ((uint4*)g_xp)[i] = make_uint4(0, 0, 0, 0);
    else if (i < XP_U4 + XA8_U4) g_xa8_raw[i - XP_U4] = make_uint4(0, 0, 0, 0);
}

// ---------------------------------------------------------------------------
// Kernel: pack sign bits of x (all batches) + int8 xa (batches >= 21)
// ---------------------------------------------------------------------------
__global__ void xpack_kernel(const float* __restrict__ x) {
    int h = blockIdx.x, b = blockIdx.y;
    __shared__ float tile[64][57];
    int tid = threadIdx.x;
    int lane = tid & 31, warp = tid >> 5;
    const float4* xrow =
        (const float4*)(x + (((size_t)(b * CC + warp * 32 + lane)) * HH + h) * WW);
    uint32_t* base = &g_xp[(((size_t)(b * HP + h + 1)) * WP + 1) * 8 + warp];
    for (int w0 = 0; w0 < WW; w0 += 4) {
        float4 v = xrow[w0 >> 2];
        uint32_t m0 = __ballot_sync(~0u, v.x > 0.0f);
        uint32_t m1 = __ballot_sync(~0u, v.y > 0.0f);
        uint32_t m2 = __ballot_sync(~0u, v.z > 0.0f);
        uint32_t m3 = __ballot_sync(~0u, v.w > 0.0f);
        if (lane == 0) {
            base[(w0 + 0) * 8] = m0; base[(w0 + 1) * 8] = m1;
            base[(w0 + 2) * 8] = m2; base[(w0 + 3) * 8] = m3;
        }
    }
    if (b >= IMMA_B0) {
        int bp = b - IMMA_B0;
        for (int cb = 0; cb < 4; cb++) {
            __syncthreads();
            for (int idx = tid; idx < 64 * 56; idx += 256) {
                int ci = idx / 56, w = idx - ci * 56;
                tile[ci][w] = x[((size_t)(b * CC + cb * 64 + ci) * HH + h) * WW + w];
            }
            __syncthreads();
            for (int idx = tid; idx < 56 * 16; idx += 256) {
                int w = idx >> 4, g = idx & 15;
                uint32_t packed = 0;
#pragma unroll
                for (int k = 0; k < 4; k++) {
                    float v = tile[g * 4 + k][w];
                    uint32_t byte = (v > 0.0f) ? 0x01u : 0xFFu;
                    packed |= byte << (k * 8);
                }
                *(uint32_t*)&G_XA8[(((size_t)(bp * HP + h + 1) * WP + (w + 1)) * CC) +
                                   cb * 64 + g * 4] = packed;
            }
        }
    }
}

// ---------------------------------------------------------------------------
__device__ __forceinline__ int pixel_cat(int p) {
    int hw = p % HWs;
    int h = hw / WW, w = hw - h * WW;
    int ht = (h == 0) ? 0 : ((h == HH - 1) ? 2 : 1);
    int wt = (w == 0) ? 0 : ((w == WW - 1) ? 2 : 1);
    return ht * 3 + wt;
}

// ---------------------------------------------------------------------------
// popc half (fused CTA): 128 threads, 64px x 64c, named barrier 3.
// sW: [72][64] words, sX: [72][64] words.
// ---------------------------------------------------------------------------
__device__ __forceinline__ void popc_half(uint32_t* sW, uint32_t* sX,
                                          int wg, int p0, int n0) {
    {
        int col = wg & 63, khalf = wg >> 6;
        for (int k = khalf; k < KW; k += 2)
            sW[k * 64 + col] = g_wpT[k * CC + n0 + col];
    }
    for (int idx = wg; idx < 576; idx += 128) {
        int pix = idx & 63, tap = idx >> 6;
        int p = p0 + pix;
        int b = p / HWs, hw = p - b * HWs;
        int h = hw / WW, w = hw - h * WW;
        int kh = tap / 3, kw = tap - 3 * kh;
        const uint4* src =
            (const uint4*)&g_xp[(((size_t)(b * HP + h + kh)) * WP + (w + kw)) * 8];
        uint4 q0 = src[0], q1 = src[1];
        int kb = tap * 8;
        sX[(kb + 0) * 64 + pix] = q0.x; sX[(kb + 1) * 64 + pix] = q0.y;
        sX[(kb + 2) * 64 + pix] = q0.z; sX[(kb + 3) * 64 + pix] = q0.w;
        sX[(kb + 4) * 64 + pix] = q1.x; sX[(kb + 5) * 64 + pix] = q1.y;
        sX[(kb + 6) * 64 + pix] = q1.z; sX[(kb + 7) * 64 + pix] = q1.w;
    }
    BAR_SYNC(3, 128);

    const int pg = wg & 15;
    const int cg = wg >> 4;          // 0..7, 8 couts each over 64c
    const int lane = wg & 31;
    const uint4* sXv = (const uint4*)sX;
    const uint4* sWv = (const uint4*)sW;

    int acc[4][8];
#pragma unroll
    for (int i = 0; i < 4; i++)
#pragma unroll
        for (int j = 0; j < 8; j++) acc[i][j] = 0;

#pragma unroll 2
    for (int k = 0; k < KW; k += 2) {
        uint4 xq0 = sXv[k * 16 + pg];
        uint4 xq1 = sXv[(k + 1) * 16 + pg];
        uint32_t xs0[4] = {xq0.x, xq0.y, xq0.z, xq0.w};
        uint32_t xs1[4] = {xq1.x, xq1.y, xq1.z, xq1.w};
        {
            uint4 w0 = sWv[k * 16 + cg * 2];
            uint4 w1 = sWv[(k + 1) * 16 + cg * 2];
            uint32_t ws0[4] = {w0.x, w0.y, w0.z, w0.w};
            uint32_t ws1[4] = {w1.x, w1.y, w1.z, w1.w};
#pragma unroll
            for (int i = 0; i < 4; i++)
#pragma unroll
                for (int j = 0; j < 4; j++)
                    acc[i][j] += __popc(xs0[i] ^ ws0[j]) + __popc(xs1[i] ^ ws1[j]);
        }
        {
            uint4 w0 = sWv[k * 16 + cg * 2 + 1];
            uint4 w1 = sWv[(k + 1) * 16 + cg * 2 + 1];
            uint32_t ws0[4] = {w0.x, w0.y, w0.z, w0.w};
            uint32_t ws1[4] = {w1.x, w1.y, w1.z, w1.w};
#pragma unroll
            for (int i = 0; i < 4; i++)
#pragma unroll
                for (int j = 0; j < 4; j++)
                    acc[i][j + 4] += __popc(xs0[i] ^ ws0[j]) + __popc(xs1[i] ^ ws1[j]);
        }
    }

    int pcat[4];
#pragma unroll
    for (int i = 0; i < 4; i++) pcat[i] = pixel_cat(p0 + pg * 4 + i);
    int u[4][8];
#pragma unroll
    for (int j = 0; j < 8; j++) {
        int c = n0 + cg * 8 + j;
#pragma unroll
        for (int i = 0; i < 4; i++) {
            int corr = (pcat[i] == 4) ? 0 : g_corr[pcat[i] * CC + c];
            u[i][j] = KBITS - 2 * acc[i][j] + corr;
        }
    }
#pragma unroll
    for (int j = 0; j < 8; j++) {
        int s = 0, s2 = 0;
#pragma unroll
        for (int i = 0; i < 4; i++) { s += u[i][j]; s2 += u[i][j] * u[i][j]; }
#pragma unroll
        for (int m = 1; m < 16; m <<= 1) {
            s  += __shfl_xor_sync(~0u, s, m);
            s2 += __shfl_xor_sync(~0u, s2, m);
        }
        if ((lane & 15) == 0) {
            int c = n0 + cg * 8 + j;
            atomicAdd(&g_isum[c],   (unsigned long long)(long long)s);
            atomicAdd(&g_isumsq[c], (unsigned long long)(long long)s2);
        }
    }
    {
        int p2 = p0 + pg * 4;
        int b2 = p2 / HWs, hw2 = p2 - b2 * HWs;
        short* yd = g_y16 + (size_t)b2 * CHW + hw2;
#pragma unroll
        for (int j = 0; j < 8; j++) {
            int c = n0 + cg * 8 + j;
            uint2 val;
            val.x = (uint32_t)(u[0][j] & 0xffff) | ((uint32_t)u[1][j] << 16);
            val.y = (uint32_t)(u[2][j] & 0xffff) | ((uint32_t)u[3][j] << 16);
            *(uint2*)&yd[(size_t)c * HWs] = val;
        }
    }
}

// ---------------------------------------------------------------------------
// IMMA half: 4 warps (threads 0..127), 32px x 64c, cp.async 3-stage
// ---------------------------------------------------------------------------
__device__ __forceinline__ void imma_half(uint32_t* smem32, int f) {
    char* smem = (char*)smem32;
    const uint32_t sbase = smem_to_u32(smem);
    const int wg = threadIdx.x;         // 0..127
    const int iw = wg >> 5;
    const int lane = wg & 31;
    const int wm = iw & 1;              // 16-px block
    const int wn = iw >> 1;             // 32-cout block
    const int m0 = IMMA_PIX0 + (f >> 2) * 32;
    const int n0 = (f & 3) * 64;

    const int rA = wg >> 2, qA = wg & 3;          // A: 32 rows x 4 quarters
    int p = m0 + rA;
    int b = p / HWs; int hw = p - b * HWs;
    int h = hw / WW; int w = hw - h * WW;
    const int8_t* asrc =
        G_XA8 + (((size_t)((b - IMMA_B0) * HP + h)) * WP + w) * CC + qA * 16;
    const uint32_t sdstA = (uint32_t)(rA * ISSTR + qA * 16);
    const int rB = wg >> 1, qB = wg & 1;          // B: 64 rows x 2 halves
    const int8_t* bsrc = G_WB + (size_t)(n0 + rB) * KD + qB * 32;
    const uint32_t sdstB = (uint32_t)(IA_BYTES + rB * ISSTR + qB * 32);

    auto issue = [&](int kc) {
        int buf = kc % 3;
        int tap = kc >> 2;
        int ci0 = (kc & 3) * 64;
        int kh = tap / 3, kw = tap - 3 * kh;
        cp16(sbase + buf * ISTAGE + sdstA, asrc + ((kh * WP + kw) * CC + ci0));
        const int8_t* bp = bsrc + tap * 256 + ci0;
        cp16(sbase + buf * ISTAGE + sdstB, bp);
        cp16(sbase + buf * ISTAGE + sdstB + 16, bp + 16);
    };

    int acc[4][4];
#pragma unroll
    for (int nf = 0; nf < 4; nf++)
#pragma unroll
        for (int i = 0; i < 4; i++) acc[nf][i] = 0;

    const uint32_t aFrag = (uint32_t)((wm * 16 + (lane & 15)) * ISSTR + (lane >> 4) * 16);
    const uint32_t bFrag = (uint32_t)(IA_BYTES + (wn * 32 + (lane & 15)) * ISSTR +
                                      (lane >> 4) * 16);

    issue(0); CP_COMMIT();
    issue(1); CP_COMMIT();
    for (int kc = 0; kc < 36; kc++) {
        CP_WAIT1();
        BAR_SYNC(1, 128);
        if (kc + 2 < 36) issue(kc + 2);
        CP_COMMIT();
        const uint32_t sb = sbase + (kc % 3) * ISTAGE;
#pragma unroll
        for (int s = 0; s < 2; s++) {
            uint32_t a0, a1, a2, a3;
            ldsm4(a0, a1, a2, a3, sb + aFrag + s * 32);
#pragma unroll
            for (int nb = 0; nb < 2; nb++) {
                uint32_t b0, b1, b2, b3;
                ldsm4(b0, b1, b2, b3, sb + bFrag + nb * 16 * ISSTR + s * 32);
                mma_s8(acc[2 * nb],     a0, a1, a2, a3, b0, b2);
                mma_s8(acc[2 * nb + 1], a0, a1, a2, a3, b1, b3);
            }
        }
    }

    // epilogue: zero padding is exact -> no correction
#pragma unroll
    for (int nf = 0; nf < 4; nf++) {
#pragma unroll
        for (int jj = 0; jj < 2; jj++) {
            int s = 0, s2 = 0;
#pragma unroll
            for (int rh = 0; rh < 2; rh++) {
                int v = acc[nf][rh * 2 + jj];
                s += v; s2 += v * v;
            }
#pragma unroll
            for (int m = 4; m < 32; m <<= 1) {
                s  += __shfl_xor_sync(~0u, s, m);
                s2 += __shfl_xor_sync(~0u, s2, m);
            }
            if (lane < 4) {
                int c = n0 + wn * 32 + nf * 8 + 2 * lane + jj;
                atomicAdd(&g_isum[c],   (unsigned long long)(long long)s);
                atomicAdd(&g_isumsq[c], (unsigned long long)(long long)s2);
            }
        }
    }
#pragma unroll
    for (int rh = 0; rh < 2; rh++) {
        int p2 = m0 + wm * 16 + (lane >> 2) + rh * 8;
        int b2 = p2 / HWs, hw2 = p2 - b2 * HWs;
        short* yd = g_y16 + (size_t)b2 * CHW + hw2;
#pragma unroll
        for (int nf = 0; nf < 4; nf++) {
            int c = n0 + wn * 32 + nf * 8 + 2 * (lane & 3);
            yd[(size_t)c * HWs]       = (short)acc[nf][rh * 2 + 0];
            yd[(size_t)(c + 1) * HWs] = (short)acc[nf][rh * 2 + 1];
        }
    }
}

// ---------------------------------------------------------------------------
// Leftover block: proven R9 popc body. 256 threads, 64px x 128c.
// W [72][128] at smem[0], X [72][64] at smem+SW_WORDS. __syncthreads only.
// ---------------------------------------------------------------------------
__device__ __forceinline__ void popc_block256(uint32_t* smem, int q) {
    uint32_t* sW = smem;
    uint32_t* sX = smem + SW_WORDS;
    const int tid = threadIdx.x;
    const int lane = tid & 31;
    const int p0 = LEFT_PIX0 + (q >> 1) * 64;
    const int n0 = (q & 1) * 128;

    {
        int col = tid & 127, khalf = tid >> 7;
        for (int k = khalf; k < KW; k += 2)
            sW[k * 128 + col] = g_wpT[k * CC + n0 + col];
    }
    for (int idx = tid; idx < 576; idx += 256) {
        int pix = idx & 63, tap = idx >> 6;
        int p = p0 + pix;
        int b = p / HWs, hw = p - b * HWs;
        int h = hw / WW, w = hw - h * WW;
        int kh = tap / 3, kw = tap - 3 * kh;
        const uint4* src =
            (const uint4*)&g_xp[(((size_t)(b * HP + h + kh)) * WP + (w + kw)) * 8];
        uint4 q0 = src[0], q1 = src[1];
        int kb = tap * 8;
        sX[(kb + 0) * 64 + pix] = q0.x; sX[(kb + 1) * 64 + pix] = q0.y;
        sX[(kb + 2) * 64 + pix] = q0.z; sX[(kb + 3) * 64 + pix] = q0.w;
        sX[(kb + 4) * 64 + pix] = q1.x; sX[(kb + 5) * 64 + pix] = q1.y;
        sX[(kb + 6) * 64 + pix] = q1.z; sX[(kb + 7) * 64 + pix] = q1.w;
    }
    __syncthreads();

    const int pg = tid & 15;
    const int cg = tid >> 4;          // 0..15 over 128c
    const uint4* sXv = (const uint4*)sX;
    const uint4* sWv = (const uint4*)sW;   // row stride 32 uint4

    int acc[4][8];
#pragma unroll
    for (int i = 0; i < 4; i++)
#pragma unroll
        for (int j = 0; j < 8; j++) acc[i][j] = 0;

#pragma unroll 2
    for (int k = 0; k < KW; k += 2) {
        uint4 xq0 = sXv[k * 16 + pg];
        uint4 xq1 = sXv[(k + 1) * 16 + pg];
        uint32_t xs0[4] = {xq0.x, xq0.y, xq0.z, xq0.w};
        uint32_t xs1[4] = {xq1.x, xq1.y, xq1.z, xq1.w};
        {
            uint4 w0 = sWv[k * 32 + cg * 2];
            uint4 w1 = sWv[(k + 1) * 32 + cg * 2];
            uint32_t ws0[4] = {w0.x, w0.y, w0.z, w0.w};
            uint32_t ws1[4] = {w1.x, w1.y, w1.z, w1.w};
#pragma unroll
            for (int i = 0; i < 4; i++)
#pragma unroll
                for (int j = 0; j < 4; j++)
                    acc[i][j] += __popc(xs0[i] ^ ws0[j]) + __popc(xs1[i] ^ ws1[j]);
        }
        {
            uint4 w0 = sWv[k * 32 + cg * 2 + 1];
            uint4 w1 = sWv[(k + 1) * 32 + cg * 2 + 1];
            uint32_t ws0[4] = {w0.x, w0.y, w0.z, w0.w};
            uint32_t ws1[4] = {w1.x, w1.y, w1.z, w1.w};
#pragma unroll
            for (int i = 0; i < 4; i++)
#pragma unroll
                for (int j = 0; j < 4; j++)
                    acc[i][j + 4] += __popc(xs0[i] ^ ws0[j]) + __popc(xs1[i] ^ ws1[j]);
        }
    }

    int pcat[4];
#pragma unroll
    for (int i = 0; i < 4; i++) pcat[i] = pixel_cat(p0 + pg * 4 + i);
    int u[4][8];
#pragma unroll
    for (int j = 0; j < 8; j++) {
        int c = n0 + cg * 8 + j;
#pragma unroll
        for (int i = 0; i < 4; i++) {
            int corr = (pcat[i] == 4) ? 0 : g_corr[pcat[i] * CC + c];
            u[i][j] = KBITS - 2 * acc[i][j] + corr;
        }
    }
#pragma unroll
    for (int j = 0; j < 8; j++) {
        int s = 0, s2 = 0;
#pragma unroll
        for (int i = 0; i < 4; i++) { s += u[i][j]; s2 += u[i][j] * u[i][j]; }
#pragma unroll
        for (int m = 1; m < 16; m <<= 1) {
            s  += __shfl_xor_sync(~0u, s, m);
            s2 += __shfl_xor_sync(~0u, s2, m);
        }
        if ((lane & 15) == 0) {
            int c = n0 + cg * 8 + j;
            atomicAdd(&g_isum[c],   (unsigned long long)(long long)s);
            atomicAdd(&g_isumsq[c], (unsigned long long)(long long)s2);
        }
    }
    {
        int p2 = p0 + pg * 4;
        int b2 = p2 / HWs, hw2 = p2 - b2 * HWs;
        short* yd = g_y16 + (size_t)b2 * CHW + hw2;
#pragma unroll
        for (int j = 0; j < 8; j++) {
            int c = n0 + cg * 8 + j;
            uint2 val;
            val.x = (uint32_t)(u[0][j] & 0xffff) | ((uint32_t)u[1][j] << 16);
            val.y = (uint32_t)(u[2][j] & 0xffff) | ((uint32_t)u[3][j] << 16);
            *(uint2*)&yd[(size_t)c * HWs] = val;
        }
    }
}

// ---------------------------------------------------------------------------
// Unified kernel: warp-specialized fused CTAs (+4 pure popc leftover blocks)
// ---------------------------------------------------------------------------
__global__ __launch_bounds__(256, 3) void gemm_kernel() {
    extern __shared__ uint32_t smem[];
    const int bid = blockIdx.x;
    if (bid < FUSED_BLOCKS) {
        if (threadIdx.x < 128) {
            imma_half(smem, bid);
        } else {
            int wg = threadIdx.x - 128;
            int p0 = (bid >> 2) * 64;
            int n0 = (bid & 3) * 64;
            popc_half(smem + PW_OFF, smem + PX_OFF, wg, p0, n0);
        }
    } else {
        popc_block256(smem, bid - FUSED_BLOCKS);
    }
}

// ---------------------------------------------------------------------------
// Kernel: BN affine coefficients
// ---------------------------------------------------------------------------
__global__ void coeff_kernel(const float* __restrict__ gamma, const float* __restrict__ beta) {
    int c = threadIdx.x;
    double n  = (double)PIX;
    double mu = (double)(long long)g_isum[c] / n;
    double vu = (double)(long long)g_isumsq[c] / n - mu * mu;
    double sc = (double)g_scale[c];
    double A  = (double)gamma[c] * sc / sqrt(sc * sc * vu + (double)BN_EPS);
    g_ab[c]      = (float)A;
    g_ab[CC + c] = (float)((double)beta[c] - A * mu);
}

// ---------------------------------------------------------------------------
// Kernel: out = relu(A*u + B), int16 -> fp32, NCHW
// ---------------------------------------------------------------------------
__global__ void finalize_kernel(float* __restrict__ out) {
    size_t idx = (size_t)blockIdx.x * 256 + threadIdx.x;
    size_t j = idx * 8;
    int c = (int)((j / HWs) & 255);
    float A = g_ab[c], Bv = g_ab[CC + c];
    uint4 raw = ((const uint4*)g_y16)[idx];
    float4 o0, o1;
    o0.x = fmaxf(fmaf((float)(short)(raw.x & 0xffff), A, Bv), 0.0f);
    o0.y = fmaxf(fmaf((float)(short)(raw.x >> 16),    A, Bv), 0.0f);
    o0.z = fmaxf(fmaf((float)(short)(raw.y & 0xffff), A, Bv), 0.0f);
    o0.w = fmaxf(fmaf((float)(short)(raw.y >> 16),    A, Bv), 0.0f);
    o1.x = fmaxf(fmaf((float)(short)(raw.z & 0xffff), A, Bv), 0.0f);
    o1.y = fmaxf(fmaf((float)(short)(raw.z >> 16),    A, Bv), 0.0f);
    o1.z = fmaxf(fmaf((float)(short)(raw.w & 0xffff), A, Bv), 0.0f);
    o1.w = fmaxf(fmaf((float)(short)(raw.w >> 16),    A, Bv), 0.0f);
    ((float4*)out)[idx * 2]     = o0;
    ((float4*)out)[idx * 2 + 1] = o1;
}

// ---------------------------------------------------------------------------
// Launch (gemm stays at launch index 3 so the profiler lands on it)
// ---------------------------------------------------------------------------
extern "C" void kernel_launch(void* const* d_in, const int* in_sizes, int n_in,
                              void* d_out, int out_size) {
    (void)in_sizes; (void)n_in; (void)out_size;
    const float* x     = (const float*)d_in[0];
    const float* wt    = (const float*)d_in[1];
    const float* gamma = (const float*)d_in[2];
    const float* beta  = (const float*)d_in[3];
    float* out = (float*)d_out;

    static int smem_set = 0;
    if (!smem_set) {
        cudaFuncSetAttribute(gemm_kernel, cudaFuncAttributeMaxDynamicSharedMemorySize,
                             SMEM_DYN);
        smem_set = 1;
    }

    wprep_kernel<<<256, 256>>>(wt);
    zero_xp_kernel<<<(XP_U4 + XA8_U4 + 255) / 256, 256>>>();
    xpack_kernel<<<dim3(HH, BB), 256>>>(x);
    gemm_kernel<<<TOT_BLOCKS, 256, SMEM_DYN>>>();
    coeff_kernel<<<1, 256>>>(gamma, beta);
    finalize_kernel<<<(int)((size_t)PIX * CC / 8 / 256), 256>>>(out);
}

// round 14
// speedup vs baseline: 1.2580x; 1.0175x over previous
#include <cuda_runtime.h>
#include <cstdint>

// ---------------------------------------------------------------------------
// Problem constants
// ---------------------------------------------------------------------------
constexpr int BB = 32, CC = 256, HH = 56, WW = 56;
constexpr int HP = 58, WP = 58;                 // padded spatial
constexpr int HWs = HH * WW;                    // 3136
constexpr int CHW = CC * HWs;                   // 802816
constexpr int PIX = BB * HWs;                   // 100352
constexpr int KW  = 72;                         // K in 32-bit words (2304 bits)
constexpr int KD  = 2304;                       // K in int8 elements
constexpr int KBITS = 2304;
constexpr float BN_EPS = 1e-5f;

// ---- rebalanced split (f ~= 0.29):
//  popc-in-fused px [0, 58240)          : 910 tiles x 64px, 4 cout quarters
//  popc-pure     px [58240, 71232)      : 203 tiles x 64px, 2 cout halves
//  IMMA          px [71232, 100352)     : 910 tiles x 32px, 4 cout quarters
constexpr int FUSED_PT   = 910;
constexpr int PURE_PIX0  = FUSED_PT * 64;       // 58240
constexpr int PURE_PT    = 203;
constexpr int IMMA_PIX0  = PURE_PIX0 + PURE_PT * 64;  // 71232
constexpr int IMMA_B0    = 22;                  // first batch holding IMMA px
constexpr int IMMA_NB    = 10;                  // batches 22..31 -> int8 xa
constexpr int FUSED_BLOCKS = FUSED_PT * 4;      // 3640
constexpr int PURE_BLOCKS  = PURE_PT * 2;       // 406
constexpr int TOT_BLOCKS   = FUSED_BLOCKS + PURE_BLOCKS;  // 4046

// smem layout (fused CTA): IMMA 3 stages then popc W/X tiles
constexpr int ISSTR = 80;
constexpr int IA_BYTES = 32 * ISSTR;            // 2560
constexpr int IB_BYTES = 64 * ISSTR;            // 5120
constexpr int ISTAGE = IA_BYTES + IB_BYTES;     // 7680, x3 = 23040
constexpr int PW_OFF = 23040 / 4;               // word offset of popc W [72][64]
constexpr int PX_OFF = PW_OFF + KW * 64;        // popc X [72][64]
constexpr int SMEM_DYN = (PX_OFF + KW * 64) * 4;   // 59904 B

// pure popc block (R9 layout): W [72][128] at 0, X [72][64] after
constexpr int SW_WORDS = KW * 128;              // 9216 (words)

// ---------------------------------------------------------------------------
// Device scratch (allocation-free: __device__ globals)
// ---------------------------------------------------------------------------
__device__ uint32_t g_xp[(size_t)BB * HP * WP * 8];   // packed x, padded NHWC
__device__ uint4    g_xa8_raw[(size_t)IMMA_NB * HP * WP * CC / 16]; // int8 xa
__device__ uint32_t g_wpT[KW * CC];                   // packed w, [k][cout]
__device__ uint4    g_wb_raw[(size_t)CC * KD / 16];   // int8 w, [co][tap*256+ci]
__device__ int      g_corr[9 * CC];                   // border corrections
__device__ short    g_y16[(size_t)PIX * CC];          // conv result, NCHW int16
__device__ float    g_scale[CC];
__device__ unsigned long long g_isum[CC];
__device__ unsigned long long g_isumsq[CC];
__device__ float    g_ab[2 * CC];

#define G_WB  ((int8_t*)g_wb_raw)
#define G_XA8 ((int8_t*)g_xa8_raw)
constexpr int XP_U4  = (int)((size_t)BB * HP * WP * 8 / 4);
constexpr int XA8_U4 = (int)((size_t)IMMA_NB * HP * WP * CC / 16);

// ---------------------------------------------------------------------------
// PTX helpers (baseline, assemble at .target sm_103)
// ---------------------------------------------------------------------------
__device__ __forceinline__ uint32_t smem_to_u32(const void* p) {
    uint32_t a;
    asm("{ .reg .u64 t; cvta.to.shared.u64 t, %1; cvt.u32.u64 %0, t; }" : "=r"(a) : "l"(p));
    return a;
}
__device__ __forceinline__ void cp16(uint32_t dst, const void* src) {
    asm volatile("cp.async.cg.shared.global [%0], [%1], 16;" :: "r"(dst), "l"(src));
}
#define CP_COMMIT() asm volatile("cp.async.commit_group;" ::: "memory")
#define CP_WAIT1()  asm volatile("cp.async.wait_group 1;" ::: "memory")
#define BAR_SYNC(id, cnt) \
    asm volatile("bar.sync %0, %1;" :: "r"(id), "r"(cnt) : "memory")
__device__ __forceinline__ void ldsm4(uint32_t& r0, uint32_t& r1, uint32_t& r2,
                                      uint32_t& r3, uint32_t addr) {
    asm volatile("ldmatrix.sync.aligned.m8n8.x4.shared.b16 {%0,%1,%2,%3}, [%4];"
                 : "=r"(r0), "=r"(r1), "=r"(r2), "=r"(r3) : "r"(addr));
}
__device__ __forceinline__ void mma_s8(int* d, uint32_t a0, uint32_t a1,
                                       uint32_t a2, uint32_t a3,
                                       uint32_t b0, uint32_t b1) {
    asm volatile(
        "mma.sync.aligned.m16n8k32.row.col.s32.s8.s8.s32 "
        "{%0,%1,%2,%3}, {%4,%5,%6,%7}, {%8,%9}, {%0,%1,%2,%3};"
        : "+r"(d[0]), "+r"(d[1]), "+r"(d[2]), "+r"(d[3])
        : "r"(a0), "r"(a1), "r"(a2), "r"(a3), "r"(b0), "r"(b1));
}

// ---------------------------------------------------------------------------
// Kernel: weight prep
// ---------------------------------------------------------------------------
__global__ void wprep_kernel(const float* __restrict__ w) {
    int o = blockIdx.x, tid = threadIdx.x;
    int lane = tid & 31, warp = tid >> 5;
    const float* wp = w + ((size_t)o * CC + tid) * 9;
    float v[9]; float s = 0.0f;
#pragma unroll
    for (int t = 0; t < 9; t++) { v[t] = wp[t]; s += fabsf(v[t]); }
#pragma unroll
    for (int off = 16; off; off >>= 1) s += __shfl_xor_sync(~0u, s, off);
    __shared__ float sh[8];
    __shared__ uint32_t words[9][8];
    __shared__ int S[9];
    if (lane == 0) sh[warp] = s;

#pragma unroll
    for (int t = 0; t < 9; t++) {
        uint32_t m = __ballot_sync(~0u, v[t] > 0.0f);
        if (lane == 0) words[t][warp] = m;
        int sg = (v[t] > 0.0f) ? 1 : ((v[t] < 0.0f) ? -1 : 0);
        G_WB[(size_t)o * KD + t * 256 + tid] = (int8_t)sg;
    }
    __syncthreads();
    if (tid == 0) {
        float tot = 0.0f;
        for (int i = 0; i < 8; i++) tot += sh[i];
        g_scale[o] = tot / (float)KBITS;
        g_isum[o] = 0ull; g_isumsq[o] = 0ull;
    }
    if (tid < 72) {
        int t = tid >> 3, j = tid & 7;
        g_wpT[(t * 8 + j) * CC + o] = words[t][j];
    }
    if (tid < 9) {
        int P = 0;
        for (int j = 0; j < 8; j++) P += __popc(words[tid][j]);
        S[tid] = 2 * P - 256;
    }
    __syncthreads();
    if (tid < 9) {
        int ht = tid / 3, wt = tid % 3;
        int corr = 0;
        for (int kh = 0; kh < 3; kh++)
            for (int kw = 0; kw < 3; kw++) {
                bool miss = (ht == 0 && kh == 0) || (ht == 2 && kh == 2) ||
                            (wt == 0 && kw == 0) || (wt == 2 && kw == 2);
                if (miss) corr += S[kh * 3 + kw];
            }
        g_corr[tid * CC + o] = corr;
    }
}

// ---------------------------------------------------------------------------
// Kernel: zero packed-x + int8-xa buffers (pad rings must be 0)
// ---------------------------------------------------------------------------
__global__ void zero_xp_kernel() {
    int i = blockIdx.x * 256 + threadIdx.x;
    if (i < XP_U4) ((uint4*)g_xp)[i] = make_uint4(0, 0, 0, 0);
    else if (i < XP_U4 + XA8_U4) g_xa8_raw[i - XP_U4] = make_uint4(0, 0, 0, 0);
}

// ---------------------------------------------------------------------------
// Kernel: pack sign bits of x (all batches) + int8 xa (batches >= IMMA_B0)
// ---------------------------------------------------------------------------
__global__ void xpack_kernel(const float* __restrict__ x) {
    int h = blockIdx.x, b = blockIdx.y;
    __shared__ float tile[64][57];
    int tid = threadIdx.x;
    int lane = tid & 31, warp = tid >> 5;
    const float4* xrow =
        (const float4*)(x + (((size_t)(b * CC + warp * 32 + lane)) * HH + h) * WW);
    uint32_t* base = &g_xp[(((size_t)(b * HP + h + 1)) * WP + 1) * 8 + warp];
    for (int w0 = 0; w0 < WW; w0 += 4) {
        float4 v = xrow[w0 >> 2];
        uint32_t m0 = __ballot_sync(~0u, v.x > 0.0f);
        uint32_t m1 = __ballot_sync(~0u, v.y > 0.0f);
        uint32_t m2 = __ballot_sync(~0u, v.z > 0.0f);
        uint32_t m3 = __ballot_sync(~0u, v.w > 0.0f);
        if (lane == 0) {
            base[(w0 + 0) * 8] = m0; base[(w0 + 1) * 8] = m1;
            base[(w0 + 2) * 8] = m2; base[(w0 + 3) * 8] = m3;
        }
    }
    if (b >= IMMA_B0) {
        int bp = b - IMMA_B0;
        for (int cb = 0; cb < 4; cb++) {
            __syncthreads();
            for (int idx = tid; idx < 64 * 56; idx += 256) {
                int ci = idx / 56, w = idx - ci * 56;
                tile[ci][w] = x[((size_t)(b * CC + cb * 64 + ci) * HH + h) * WW + w];
            }
            __syncthreads();
            for (int idx = tid; idx < 56 * 16; idx += 256) {
                int w = idx >> 4, g = idx & 15;
                uint32_t packed = 0;
#pragma unroll
                for (int k = 0; k < 4; k++) {
                    float v = tile[g * 4 + k][w];
                    uint32_t byte = (v > 0.0f) ? 0x01u : 0xFFu;
                    packed |= byte << (k * 8);
                }
                *(uint32_t*)&G_XA8[(((size_t)(bp * HP + h + 1) * WP + (w + 1)) * CC) +
                                   cb * 64 + g * 4] = packed;
            }
        }
    }
}

// ---------------------------------------------------------------------------
__device__ __forceinline__ int pixel_cat(int p) {
    int hw = p % HWs;
    int h = hw / WW, w = hw - h * WW;
    int ht = (h == 0) ? 0 : ((h == HH - 1) ? 2 : 1);
    int wt = (w == 0) ? 0 : ((w == WW - 1) ? 2 : 1);
    return ht * 3 + wt;
}

// ---------------------------------------------------------------------------
// popc half (fused CTA): 128 threads, 64px x 64c, named barrier 3.
// ---------------------------------------------------------------------------
__device__ __forceinline__ void popc_half(uint32_t* sW, uint32_t* sX,
                                          int wg, int p0, int n0) {
    {
        int col = wg & 63, khalf = wg >> 6;
        for (int k = khalf; k < KW; k += 2)
            sW[k * 64 + col] = g_wpT[k * CC + n0 + col];
    }
    for (int idx = wg; idx < 576; idx += 128) {
        int pix = idx & 63, tap = idx >> 6;
        int p = p0 + pix;
        int b = p / HWs, hw = p - b * HWs;
        int h = hw / WW, w = hw - h * WW;
        int kh = tap / 3, kw = tap - 3 * kh;
        const uint4* src =
            (const uint4*)&g_xp[(((size_t)(b * HP + h + kh)) * WP + (w + kw)) * 8];
        uint4 q0 = src[0], q1 = src[1];
        int kb = tap * 8;
        sX[(kb + 0) * 64 + pix] = q0.x; sX[(kb + 1) * 64 + pix] = q0.y;
        sX[(kb + 2) * 64 + pix] = q0.z; sX[(kb + 3) * 64 + pix] = q0.w;
        sX[(kb + 4) * 64 + pix] = q1.x; sX[(kb + 5) * 64 + pix] = q1.y;
        sX[(kb + 6) * 64 + pix] = q1.z; sX[(kb + 7) * 64 + pix] = q1.w;
    }
    BAR_SYNC(3, 128);

    const int pg = wg & 15;
    const int cg = wg >> 4;          // 0..7, 8 couts each over 64c
    const int lane = wg & 31;
    const uint4* sXv = (const uint4*)sX;
    const uint4* sWv = (const uint4*)sW;

    int acc[4][8];
#pragma unroll
    for (int i = 0; i < 4; i++)
#pragma unroll
        for (int j = 0; j < 8; j++) acc[i][j] = 0;

#pragma unroll 2
    for (int k = 0; k < KW; k += 2) {
        uint4 xq0 = sXv[k * 16 + pg];
        uint4 xq1 = sXv[(k + 1) * 16 + pg];
        uint32_t xs0[4] = {xq0.x, xq0.y, xq0.z, xq0.w};
        uint32_t xs1[4] = {xq1.x, xq1.y, xq1.z, xq1.w};
        {
            uint4 w0 = sWv[k * 16 + cg * 2];
            uint4 w1 = sWv[(k + 1) * 16 + cg * 2];
            uint32_t ws0[4] = {w0.x, w0.y, w0.z, w0.w};
            uint32_t ws1[4] = {w1.x, w1.y, w1.z, w1.w};
#pragma unroll
            for (int i = 0; i < 4; i++)
#pragma unroll
                for (int j = 0; j < 4; j++)
                    acc[i][j] += __popc(xs0[i] ^ ws0[j]) + __popc(xs1[i] ^ ws1[j]);
        }
        {
            uint4 w0 = sWv[k * 16 + cg * 2 + 1];
            uint4 w1 = sWv[(k + 1) * 16 + cg * 2 + 1];
            uint32_t ws0[4] = {w0.x, w0.y, w0.z, w0.w};
            uint32_t ws1[4] = {w1.x, w1.y, w1.z, w1.w};
#pragma unroll
            for (int i = 0; i < 4; i++)
#pragma unroll
                for (int j = 0; j < 4; j++)
                    acc[i][j + 4] += __popc(xs0[i] ^ ws0[j]) + __popc(xs1[i] ^ ws1[j]);
        }
    }

    int pcat[4];
#pragma unroll
    for (int i = 0; i < 4; i++) pcat[i] = pixel_cat(p0 + pg * 4 + i);
    int u[4][8];
#pragma unroll
    for (int j = 0; j < 8; j++) {
        int c = n0 + cg * 8 + j;
#pragma unroll
        for (int i = 0; i < 4; i++) {
            int corr = (pcat[i] == 4) ? 0 : g_corr[pcat[i] * CC + c];
            u[i][j] = KBITS - 2 * acc[i][j] + corr;
        }
    }
#pragma unroll
    for (int j = 0; j < 8; j++) {
        int s = 0, s2 = 0;
#pragma unroll
        for (int i = 0; i < 4; i++) { s += u[i][j]; s2 += u[i][j] * u[i][j]; }
#pragma unroll
        for (int m = 1; m < 16; m <<= 1) {
            s  += __shfl_xor_sync(~0u, s, m);
            s2 += __shfl_xor_sync(~0u, s2, m);
        }
        if ((lane & 15) == 0) {
            int c = n0 + cg * 8 + j;
            atomicAdd(&g_isum[c],   (unsigned long long)(long long)s);
            atomicAdd(&g_isumsq[c], (unsigned long long)(long long)s2);
        }
    }
    {
        int p2 = p0 + pg * 4;
        int b2 = p2 / HWs, hw2 = p2 - b2 * HWs;
        short* yd = g_y16 + (size_t)b2 * CHW + hw2;
#pragma unroll
        for (int j = 0; j < 8; j++) {
            int c = n0 + cg * 8 + j;
            uint2 val;
            val.x = (uint32_t)(u[0][j] & 0xffff) | ((uint32_t)u[1][j] << 16);
            val.y = (uint32_t)(u[2][j] & 0xffff) | ((uint32_t)u[3][j] << 16);
            *(uint2*)&yd[(size_t)c * HWs] = val;
        }
    }
}

// ---------------------------------------------------------------------------
// IMMA half: 4 warps (threads 0..127), 32px x 64c, cp.async 3-stage
// ---------------------------------------------------------------------------
__device__ __forceinline__ void imma_half(uint32_t* smem32, int f) {
    char* smem = (char*)smem32;
    const uint32_t sbase = smem_to_u32(smem);
    const int wg = threadIdx.x;         // 0..127
    const int iw = wg >> 5;
    const int lane = wg & 31;
    const int wm = iw & 1;              // 16-px block
    const int wn = iw >> 1;             // 32-cout block
    const int m0 = IMMA_PIX0 + (f >> 2) * 32;
    const int n0 = (f & 3) * 64;

    const int rA = wg >> 2, qA = wg & 3;          // A: 32 rows x 4 quarters
    int p = m0 + rA;
    int b = p / HWs; int hw = p - b * HWs;
    int h = hw / WW; int w = hw - h * WW;
    const int8_t* asrc =
        G_XA8 + (((size_t)((b - IMMA_B0) * HP + h)) * WP + w) * CC + qA * 16;
    const uint32_t sdstA = (uint32_t)(rA * ISSTR + qA * 16);
    const int rB = wg >> 1, qB = wg & 1;          // B: 64 rows x 2 halves
    const int8_t* bsrc = G_WB + (size_t)(n0 + rB) * KD + qB * 32;
    const uint32_t sdstB = (uint32_t)(IA_BYTES + rB * ISSTR + qB * 32);

    auto issue = [&](int kc) {
        int buf = kc % 3;
        int tap = kc >> 2;
        int ci0 = (kc & 3) * 64;
        int kh = tap / 3, kw = tap - 3 * kh;
        cp16(sbase + buf * ISTAGE + sdstA, asrc + ((kh * WP + kw) * CC + ci0));
        const int8_t* bp = bsrc + tap * 256 + ci0;
        cp16(sbase + buf * ISTAGE + sdstB, bp);
        cp16(sbase + buf * ISTAGE + sdstB + 16, bp + 16);
    };

    int acc[4][4];
#pragma unroll
    for (int nf = 0; nf < 4; nf++)
#pragma unroll
        for (int i = 0; i < 4; i++) acc[nf][i] = 0;

    const uint32_t aFrag = (uint32_t)((wm * 16 + (lane & 15)) * ISSTR + (lane >> 4) * 16);
    const uint32_t bFrag = (uint32_t)(IA_BYTES + (wn * 32 + (lane & 15)) * ISSTR +
                                      (lane >> 4) * 16);

    issue(0); CP_COMMIT();
    issue(1); CP_COMMIT();
    for (int kc = 0; kc < 36; kc++) {
        CP_WAIT1();
        BAR_SYNC(1, 128);
        if (kc + 2 < 36) issue(kc + 2);
        CP_COMMIT();
        const uint32_t sb = sbase + (kc % 3) * ISTAGE;
#pragma unroll
        for (int s = 0; s < 2; s++) {
            uint32_t a0, a1, a2, a3;
            ldsm4(a0, a1, a2, a3, sb + aFrag + s * 32);
#pragma unroll
            for (int nb = 0; nb < 2; nb++) {
                uint32_t b0, b1, b2, b3;
                ldsm4(b0, b1, b2, b3, sb + bFrag + nb * 16 * ISSTR + s * 32);
                mma_s8(acc[2 * nb],     a0, a1, a2, a3, b0, b2);
                mma_s8(acc[2 * nb + 1], a0, a1, a2, a3, b1, b3);
            }
        }
    }

    // epilogue: zero padding is exact -> no correction
#pragma unroll
    for (int nf = 0; nf < 4; nf++) {
#pragma unroll
        for (int jj = 0; jj < 2; jj++) {
            int s = 0, s2 = 0;
#pragma unroll
            for (int rh = 0; rh < 2; rh++) {
                int v = acc[nf][rh * 2 + jj];
                s += v; s2 += v * v;
            }
#pragma unroll
            for (int m = 4; m < 32; m <<= 1) {
                s  += __shfl_xor_sync(~0u, s, m);
                s2 += __shfl_xor_sync(~0u, s2, m);
            }
            if (lane < 4) {
                int c = n0 + wn * 32 + nf * 8 + 2 * lane + jj;
                atomicAdd(&g_isum[c],   (unsigned long long)(long long)s);
                atomicAdd(&g_isumsq[c], (unsigned long long)(long long)s2);
            }
        }
    }
#pragma unroll
    for (int rh = 0; rh < 2; rh++) {
        int p2 = m0 + wm * 16 + (lane >> 2) + rh * 8;
        int b2 = p2 / HWs, hw2 = p2 - b2 * HWs;
        short* yd = g_y16 + (size_t)b2 * CHW + hw2;
#pragma unroll
        for (int nf = 0; nf < 4; nf++) {
            int c = n0 + wn * 32 + nf * 8 + 2 * (lane & 3);
            yd[(size_t)c * HWs]       = (short)acc[nf][rh * 2 + 0];
            yd[(size_t)(c + 1) * HWs] = (short)acc[nf][rh * 2 + 1];
        }
    }
}

// ---------------------------------------------------------------------------
// Pure popc block (R9 body): 256 threads, 64px x 128c, __syncthreads only.
// ---------------------------------------------------------------------------
__device__ __forceinline__ void popc_block256(uint32_t* smem, int q) {
    uint32_t* sW = smem;
    uint32_t* sX = smem + SW_WORDS;
    const int tid = threadIdx.x;
    const int lane = tid & 31;
    const int p0 = PURE_PIX0 + (q >> 1) * 64;
    const int n0 = (q & 1) * 128;

    {
        int col = tid & 127, khalf = tid >> 7;
        for (int k = khalf; k < KW; k += 2)
            sW[k * 128 + col] = g_wpT[k * CC + n0 + col];
    }
    for (int idx = tid; idx < 576; idx += 256) {
        int pix = idx & 63, tap = idx >> 6;
        int p = p0 + pix;
        int b = p / HWs, hw = p - b * HWs;
        int h = hw / WW, w = hw - h * WW;
        int kh = tap / 3, kw = tap - 3 * kh;
        const uint4* src =
            (const uint4*)&g_xp[(((size_t)(b * HP + h + kh)) * WP + (w + kw)) * 8];
        uint4 q0 = src[0], q1 = src[1];
        int kb = tap * 8;
        sX[(kb + 0) * 64 + pix] = q0.x; sX[(kb + 1) * 64 + pix] = q0.y;
        sX[(kb + 2) * 64 + pix] = q0.z; sX[(kb + 3) * 64 + pix] = q0.w;
        sX[(kb + 4) * 64 + pix] = q1.x; sX[(kb + 5) * 64 + pix] = q1.y;
        sX[(kb + 6) * 64 + pix] = q1.z; sX[(kb + 7) * 64 + pix] = q1.w;
    }
    __syncthreads();

    const int pg = tid & 15;
    const int cg = tid >> 4;          // 0..15 over 128c
    const uint4* sXv = (const uint4*)sX;
    const uint4* sWv = (const uint4*)sW;   // row stride 32 uint4

    int acc[4][8];
#pragma unroll
    for (int i = 0; i < 4; i++)
#pragma unroll
        for (int j = 0; j < 8; j++) acc[i][j] = 0;

#pragma unroll 2
    for (int k = 0; k < KW; k += 2) {
        uint4 xq0 = sXv[k * 16 + pg];
        uint4 xq1 = sXv[(k + 1) * 16 + pg];
        uint32_t xs0[4] = {xq0.x, xq0.y, xq0.z, xq0.w};
        uint32_t xs1[4] = {xq1.x, xq1.y, xq1.z, xq1.w};
        {
            uint4 w0 = sWv[k * 32 + cg * 2];
            uint4 w1 = sWv[(k + 1) * 32 + cg * 2];
            uint32_t ws0[4] = {w0.x, w0.y, w0.z, w0.w};
            uint32_t ws1[4] = {w1.x, w1.y, w1.z, w1.w};
#pragma unroll
            for (int i = 0; i < 4; i++)
#pragma unroll
                for (int j = 0; j < 4; j++)
                    acc[i][j] += __popc(xs0[i] ^ ws0[j]) + __popc(xs1[i] ^ ws1[j]);
        }
        {
            uint4 w0 = sWv[k * 32 + cg * 2 + 1];
            uint4 w1 = sWv[(k + 1) * 32 + cg * 2 + 1];
            uint32_t ws0[4] = {w0.x, w0.y, w0.z, w0.w};
            uint32_t ws1[4] = {w1.x, w1.y, w1.z, w1.w};
#pragma unroll
            for (int i = 0; i < 4; i++)
#pragma unroll
                for (int j = 0; j < 4; j++)
                    acc[i][j + 4] += __popc(xs0[i] ^ ws0[j]) + __popc(xs1[i] ^ ws1[j]);
        }
    }

    int pcat[4];
#pragma unroll
    for (int i = 0; i < 4; i++) pcat[i] = pixel_cat(p0 + pg * 4 + i);
    int u[4][8];
#pragma unroll
    for (int j = 0; j < 8; j++) {
        int c = n0 + cg * 8 + j;
#pragma unroll
        for (int i = 0; i < 4; i++) {
            int corr = (pcat[i] == 4) ? 0 : g_corr[pcat[i] * CC + c];
            u[i][j] = KBITS - 2 * acc[i][j] + corr;
        }
    }
#pragma unroll
    for (int j = 0; j < 8; j++) {
        int s = 0, s2 = 0;
#pragma unroll
        for (int i = 0; i < 4; i++) { s += u[i][j]; s2 += u[i][j] * u[i][j]; }
#pragma unroll
        for (int m = 1; m < 16; m <<= 1) {
            s  += __shfl_xor_sync(~0u, s, m);
            s2 += __shfl_xor_sync(~0u, s2, m);
        }
        if ((lane & 15) == 0) {
            int c = n0 + cg * 8 + j;
            atomicAdd(&g_isum[c],   (unsigned long long)(long long)s);
            atomicAdd(&g_isumsq[c], (unsigned long long)(long long)s2);
        }
    }
    {
        int p2 = p0 + pg * 4;
        int b2 = p2 / HWs, hw2 = p2 - b2 * HWs;
        short* yd = g_y16 + (size_t)b2 * CHW + hw2;
#pragma unroll
        for (int j = 0; j < 8; j++) {
            int c = n0 + cg * 8 + j;
            uint2 val;
            val.x = (uint32_t)(u[0][j] & 0xffff) | ((uint32_t)u[1][j] << 16);
            val.y = (uint32_t)(u[2][j] & 0xffff) | ((uint32_t)u[3][j] << 16);
            *(uint2*)&yd[(size_t)c * HWs] = val;
        }
    }
}

// ---------------------------------------------------------------------------
// Unified kernel: fused warp-specialized CTAs with 10% pure popc blocks
// Bresenham-interleaved (rebalances the engine split to ~0.29 IMMA).
// ---------------------------------------------------------------------------
__global__ __launch_bounds__(256, 3) void gemm_kernel() {
    extern __shared__ uint32_t smem[];
    const uint32_t bid = blockIdx.x;
    const uint32_t before = (bid * (uint32_t)PURE_BLOCKS) / (uint32_t)TOT_BLOCKS;
    const uint32_t after  = ((bid + 1) * (uint32_t)PURE_BLOCKS) / (uint32_t)TOT_BLOCKS;
    if (after > before) {
        popc_block256(smem, (int)before);
    } else {
        int f = (int)(bid - before);
        if (threadIdx.x < 128) {
            imma_half(smem, f);
        } else {
            int wg = threadIdx.x - 128;
            int p0 = (f >> 2) * 64;
            int n0 = (f & 3) * 64;
            popc_half(smem + PW_OFF, smem + PX_OFF, wg, p0, n0);
        }
    }
}

// ---------------------------------------------------------------------------
// Kernel: BN affine coefficients
// ---------------------------------------------------------------------------
__global__ void coeff_kernel(const float* __restrict__ gamma, const float* __restrict__ beta) {
    int c = threadIdx.x;
    double n  = (double)PIX;
    double mu = (double)(long long)g_isum[c] / n;
    double vu = (double)(long long)g_isumsq[c] / n - mu * mu;
    double sc = (double)g_scale[c];
    double A  = (double)gamma[c] * sc / sqrt(sc * sc * vu + (double)BN_EPS);
    g_ab[c]      = (float)A;
    g_ab[CC + c] = (float)((double)beta[c] - A * mu);
}

// ---------------------------------------------------------------------------
// Kernel: out = relu(A*u + B), int16 -> fp32, NCHW
// ---------------------------------------------------------------------------
__global__ void finalize_kernel(float* __restrict__ out) {
    size_t idx = (size_t)blockIdx.x * 256 + threadIdx.x;
    size_t j = idx * 8;
    int c = (int)((j / HWs) & 255);
    float A = g_ab[c], Bv = g_ab[CC + c];
    uint4 raw = ((const uint4*)g_y16)[idx];
    float4 o0, o1;
    o0.x = fmaxf(fmaf((float)(short)(raw.x & 0xffff), A, Bv), 0.0f);
    o0.y = fmaxf(fmaf((float)(short)(raw.x >> 16),    A, Bv), 0.0f);
    o0.z = fmaxf(fmaf((float)(short)(raw.y & 0xffff), A, Bv), 0.0f);
    o0.w = fmaxf(fmaf((float)(short)(raw.y >> 16),    A, Bv), 0.0f);
    o1.x = fmaxf(fmaf((float)(short)(raw.z & 0xffff), A, Bv), 0.0f);
    o1.y = fmaxf(fmaf((float)(short)(raw.z >> 16),    A, Bv), 0.0f);
    o1.z = fmaxf(fmaf((float)(short)(raw.w & 0xffff), A, Bv), 0.0f);
    o1.w = fmaxf(fmaf((float)(short)(raw.w >> 16),    A, Bv), 0.0f);
    ((float4*)out)[idx * 2]     = o0;
    ((float4*)out)[idx * 2 + 1] = o1;
}

// ---------------------------------------------------------------------------
// Launch (gemm stays at launch index 3 so the profiler lands on it)
// ---------------------------------------------------------------------------
extern "C" void kernel_launch(void* const* d_in, const int* in_sizes, int n_in,
                              void* d_out, int out_size) {
    (void)in_sizes; (void)n_in; (void)out_size;
    const float* x     = (const float*)d_in[0];
    const float* wt    = (const float*)d_in[1];
    const float* gamma = (const float*)d_in[2];
    const float* beta  = (const float*)d_in[3];
    float* out = (float*)d_out;

    static int smem_set = 0;
    if (!smem_set) {
        cudaFuncSetAttribute(gemm_kernel, cudaFuncAttributeMaxDynamicSharedMemorySize,
                             SMEM_DYN);
        smem_set = 1;
    }

    wprep_kernel<<<256, 256>>>(wt);
    zero_xp_kernel<<<(XP_U4 + XA8_U4 + 255) / 256, 256>>>();
    xpack_kernel<<<dim3(HH, BB), 256>>>(x);
    gemm_kernel<<<TOT_BLOCKS, 256, SMEM_DYN>>>();
    coeff_kernel<<<1, 256>>>(gamma, beta);
    finalize_kernel<<<(int)((size_t)PIX * CC / 8 / 256), 256>>>(out);
}

// round 15
// speedup vs baseline: 1.2646x; 1.0052x over previous
#include <cuda_runtime.h>
#include <cstdint>

// ---------------------------------------------------------------------------
// Problem constants
// ---------------------------------------------------------------------------
constexpr int BB = 32, CC = 256, HH = 56, WW = 56;
constexpr int HP = 58, WP = 58;                 // padded spatial
constexpr int HWs = HH * WW;                    // 3136
constexpr int CHW = CC * HWs;                   // 802816
constexpr int PIX = BB * HWs;                   // 100352
constexpr int KW  = 72;                         // K in 32-bit words (2304 bits)
constexpr int KD  = 2304;                       // K in int8 elements
constexpr int KBITS = 2304;
constexpr float BN_EPS = 1e-5f;

// ---- rebalanced split (f ~= 0.29):
//  popc-in-fused px [0, 58240)          : 910 tiles x 64px, 4 cout quarters
//  popc-pure     px [58240, 71232)      : 203 tiles x 64px, 2 cout halves
//  IMMA          px [71232, 100352)     : 910 tiles x 32px, 4 cout quarters
constexpr int FUSED_PT   = 910;
constexpr int PURE_PIX0  = FUSED_PT * 64;       // 58240
constexpr int PURE_PT    = 203;
constexpr int IMMA_PIX0  = PURE_PIX0 + PURE_PT * 64;  // 71232
constexpr int IMMA_B0    = 22;                  // first batch holding IMMA px
constexpr int IMMA_NB    = 10;                  // batches 22..31 -> int8 xa
constexpr int FUSED_BLOCKS = FUSED_PT * 4;      // 3640
constexpr int PURE_BLOCKS  = PURE_PT * 2;       // 406
constexpr int TOT_BLOCKS   = FUSED_BLOCKS + PURE_BLOCKS;  // 4046

// smem layout (fused CTA): IMMA 3 stages then popc W/X tiles
constexpr int ISSTR = 80;
constexpr int IA_BYTES = 32 * ISSTR;            // 2560
constexpr int IB_BYTES = 64 * ISSTR;            // 5120
constexpr int ISTAGE = IA_BYTES + IB_BYTES;     // 7680, x3 = 23040
constexpr int PW_OFF = 23040 / 4;               // word offset of popc W [72][64]
constexpr int PX_OFF = PW_OFF + KW * 64;        // popc X [72][64]
constexpr int SMEM_DYN = (PX_OFF + KW * 64) * 4;   // 59904 B

// pure popc block (R9 layout): W [72][128] at 0, X [72][64] after
constexpr int SW_WORDS = KW * 128;              // 9216 (words)

// ---------------------------------------------------------------------------
// Device scratch (allocation-free: __device__ globals)
// ---------------------------------------------------------------------------
__device__ uint32_t g_xp[(size_t)BB * HP * WP * 8];   // packed x, padded NHWC
__device__ uint4    g_xa8_raw[(size_t)IMMA_NB * HP * WP * CC / 16]; // int8 xa
__device__ uint32_t g_wpT[KW * CC];                   // packed w, [k][cout]
__device__ uint4    g_wb_raw[(size_t)CC * KD / 16];   // int8 w, [co][tap*256+ci]
__device__ int      g_corr[9 * CC];                   // border corrections
__device__ short    g_y16[(size_t)PIX * CC];          // conv result, NCHW int16
__device__ float    g_scale[CC];
__device__ unsigned long long g_isum[CC];
__device__ unsigned long long g_isumsq[CC];
__device__ float    g_ab[2 * CC];

#define G_WB  ((int8_t*)g_wb_raw)
#define G_XA8 ((int8_t*)g_xa8_raw)

// ---------------------------------------------------------------------------
// PTX helpers (baseline, assemble at .target sm_103)
// ---------------------------------------------------------------------------
__device__ __forceinline__ uint32_t smem_to_u32(const void* p) {
    uint32_t a;
    asm("{ .reg .u64 t; cvta.to.shared.u64 t, %1; cvt.u32.u64 %0, t; }" : "=r"(a) : "l"(p));
    return a;
}
__device__ __forceinline__ void cp16(uint32_t dst, const void* src) {
    asm volatile("cp.async.cg.shared.global [%0], [%1], 16;" :: "r"(dst), "l"(src));
}
#define CP_COMMIT() asm volatile("cp.async.commit_group;" ::: "memory")
#define CP_WAIT1()  asm volatile("cp.async.wait_group 1;" ::: "memory")
#define BAR_SYNC(id, cnt) \
    asm volatile("bar.sync %0, %1;" :: "r"(id), "r"(cnt) : "memory")
__device__ __forceinline__ void ldsm4(uint32_t& r0, uint32_t& r1, uint32_t& r2,
                                      uint32_t& r3, uint32_t addr) {
    asm volatile("ldmatrix.sync.aligned.m8n8.x4.shared.b16 {%0,%1,%2,%3}, [%4];"
                 : "=r"(r0), "=r"(r1), "=r"(r2), "=r"(r3) : "r"(addr));
}
__device__ __forceinline__ void mma_s8(int* d, uint32_t a0, uint32_t a1,
                                       uint32_t a2, uint32_t a3,
                                       uint32_t b0, uint32_t b1) {
    asm volatile(
        "mma.sync.aligned.m16n8k32.row.col.s32.s8.s8.s32 "
        "{%0,%1,%2,%3}, {%4,%5,%6,%7}, {%8,%9}, {%0,%1,%2,%3};"
        : "+r"(d[0]), "+r"(d[1]), "+r"(d[2]), "+r"(d[3])
        : "r"(a0), "r"(a1), "r"(a2), "r"(a3), "r"(b0), "r"(b1));
}

// ---------------------------------------------------------------------------
// Kernel: weight prep
// ---------------------------------------------------------------------------
__global__ void wprep_kernel(const float* __restrict__ w) {
    int o = blockIdx.x, tid = threadIdx.x;
    int lane = tid & 31, warp = tid >> 5;
    const float* wp = w + ((size_t)o * CC + tid) * 9;
    float v[9]; float s = 0.0f;
#pragma unroll
    for (int t = 0; t < 9; t++) { v[t] = wp[t]; s += fabsf(v[t]); }
#pragma unroll
    for (int off = 16; off; off >>= 1) s += __shfl_xor_sync(~0u, s, off);
    __shared__ float sh[8];
    __shared__ uint32_t words[9][8];
    __shared__ int S[9];
    if (lane == 0) sh[warp] = s;

#pragma unroll
    for (int t = 0; t < 9; t++) {
        uint32_t m = __ballot_sync(~0u, v[t] > 0.0f);
        if (lane == 0) words[t][warp] = m;
        int sg = (v[t] > 0.0f) ? 1 : ((v[t] < 0.0f) ? -1 : 0);
        G_WB[(size_t)o * KD + t * 256 + tid] = (int8_t)sg;
    }
    __syncthreads();
    if (tid == 0) {
        float tot = 0.0f;
        for (int i = 0; i < 8; i++) tot += sh[i];
        g_scale[o] = tot / (float)KBITS;
        g_isum[o] = 0ull; g_isumsq[o] = 0ull;
    }
    if (tid < 72) {
        int t = tid >> 3, j = tid & 7;
        g_wpT[(t * 8 + j) * CC + o] = words[t][j];
    }
    if (tid < 9) {
        int P = 0;
        for (int j = 0; j < 8; j++) P += __popc(words[tid][j]);
        S[tid] = 2 * P - 256;
    }
    __syncthreads();
    if (tid < 9) {
        int ht = tid / 3, wt = tid % 3;
        int corr = 0;
        for (int kh = 0; kh < 3; kh++)
            for (int kw = 0; kw < 3; kw++) {
                bool miss = (ht == 0 && kh == 0) || (ht == 2 && kh == 2) ||
                            (wt == 0 && kw == 0) || (wt == 2 && kw == 2);
                if (miss) corr += S[kh * 3 + kw];
            }
        g_corr[tid * CC + o] = corr;
    }
}

// ---------------------------------------------------------------------------
// Kernel: zero ONLY the pad rings (interior fully overwritten by xpack)
// grid (228, BB), 256 threads. 228 border pixels per padded image.
// ---------------------------------------------------------------------------
__global__ void ring_zero_kernel() {
    int i = blockIdx.x, b = blockIdx.y;
    int tid = threadIdx.x;
    int h, w;
    if (i < 58)       { h = 0;           w = i; }
    else if (i < 116) { h = 57;          w = i - 58; }
    else if (i < 172) { h = i - 116 + 1; w = 0; }
    else              { h = i - 172 + 1; w = 57; }
    if (tid < 8)
        g_xp[(((size_t)(b * HP + h)) * WP + w) * 8 + tid] = 0;
    if (b >= IMMA_B0 && tid >= 16 && tid < 32) {
        int bp = b - IMMA_B0;
        ((uint4*)&G_XA8[(((size_t)(bp * HP + h)) * WP + w) * CC])[tid - 16] =
            make_uint4(0, 0, 0, 0);
    }
}

// ---------------------------------------------------------------------------
// Kernel: pack sign bits of x (all batches) + direct int8 expansion
// (batches >= IMMA_B0) from the ballot masks — no smem transpose.
// ---------------------------------------------------------------------------
__global__ void xpack_kernel(const float* __restrict__ x) {
    int h = blockIdx.x, b = blockIdx.y;
    int tid = threadIdx.x;
    int lane = tid & 31, warp = tid >> 5;
    const float4* xrow =
        (const float4*)(x + (((size_t)(b * CC + warp * 32 + lane)) * HH + h) * WW);
    uint32_t* base = &g_xp[(((size_t)(b * HP + h + 1)) * WP + 1) * 8 + warp];
    const bool do8 = (b >= IMMA_B0);
    int8_t* a8base = do8
        ? &G_XA8[(((size_t)((b - IMMA_B0) * HP + h + 1)) * WP + 1) * CC + warp * 32]
        : (int8_t*)nullptr;
    const int pix = lane >> 3;          // which of the 4 pixels this lane expands
    const int sub = lane & 7;           // which 4-channel nibble

    for (int w0 = 0; w0 < WW; w0 += 4) {
        float4 v = xrow[w0 >> 2];
        uint32_t m0 = __ballot_sync(~0u, v.x > 0.0f);
        uint32_t m1 = __ballot_sync(~0u, v.y > 0.0f);
        uint32_t m2 = __ballot_sync(~0u, v.z > 0.0f);
        uint32_t m3 = __ballot_sync(~0u, v.w > 0.0f);
        if (lane == 0) {
            base[(w0 + 0) * 8] = m0; base[(w0 + 1) * 8] = m1;
            base[(w0 + 2) * 8] = m2; base[(w0 + 3) * 8] = m3;
        }
        if (do8) {
            uint32_t mm = (pix == 0) ? m0 : (pix == 1) ? m1 : (pix == 2) ? m2 : m3;
            uint32_t nib = (mm >> (sub * 4)) & 0xFu;
            uint32_t spread = (nib * 0x00204081u) & 0x01010101u;
            uint32_t word = __vsub4(spread << 1, 0x01010101u);  // 0x01 / 0xFF
            *(uint32_t*)&a8base[(size_t)(w0 + pix) * CC + sub * 4] = word;
        }
    }
}

// ---------------------------------------------------------------------------
__device__ __forceinline__ int pixel_cat(int p) {
    int hw = p % HWs;
    int h = hw / WW, w = hw - h * WW;
    int ht = (h == 0) ? 0 : ((h == HH - 1) ? 2 : 1);
    int wt = (w == 0) ? 0 : ((w == WW - 1) ? 2 : 1);
    return ht * 3 + wt;
}

// ---------------------------------------------------------------------------
// popc half (fused CTA): 128 threads, 64px x 64c, named barrier 3.
// ---------------------------------------------------------------------------
__device__ __forceinline__ void popc_half(uint32_t* sW, uint32_t* sX,
                                          int wg, int p0, int n0) {
    {
        int col = wg & 63, khalf = wg >> 6;
        for (int k = khalf; k < KW; k += 2)
            sW[k * 64 + col] = g_wpT[k * CC + n0 + col];
    }
    for (int idx = wg; idx < 576; idx += 128) {
        int pix = idx & 63, tap = idx >> 6;
        int p = p0 + pix;
        int b = p / HWs, hw = p - b * HWs;
        int h = hw / WW, w = hw - h * WW;
        int kh = tap / 3, kw = tap - 3 * kh;
        const uint4* src =
            (const uint4*)&g_xp[(((size_t)(b * HP + h + kh)) * WP + (w + kw)) * 8];
        uint4 q0 = src[0], q1 = src[1];
        int kb = tap * 8;
        sX[(kb + 0) * 64 + pix] = q0.x; sX[(kb + 1) * 64 + pix] = q0.y;
        sX[(kb + 2) * 64 + pix] = q0.z; sX[(kb + 3) * 64 + pix] = q0.w;
        sX[(kb + 4) * 64 + pix] = q1.x; sX[(kb + 5) * 64 + pix] = q1.y;
        sX[(kb + 6) * 64 + pix] = q1.z; sX[(kb + 7) * 64 + pix] = q1.w;
    }
    BAR_SYNC(3, 128);

    const int pg = wg & 15;
    const int cg = wg >> 4;          // 0..7, 8 couts each over 64c
    const int lane = wg & 31;
    const uint4* sXv = (const uint4*)sX;
    const uint4* sWv = (const uint4*)sW;

    int acc[4][8];
#pragma unroll
    for (int i = 0; i < 4; i++)
#pragma unroll
        for (int j = 0; j < 8; j++) acc[i][j] = 0;

#pragma unroll 2
    for (int k = 0; k < KW; k += 2) {
        uint4 xq0 = sXv[k * 16 + pg];
        uint4 xq1 = sXv[(k + 1) * 16 + pg];
        uint32_t xs0[4] = {xq0.x, xq0.y, xq0.z, xq0.w};
        uint32_t xs1[4] = {xq1.x, xq1.y, xq1.z, xq1.w};
        {
            uint4 w0 = sWv[k * 16 + cg * 2];
            uint4 w1 = sWv[(k + 1) * 16 + cg * 2];
            uint32_t ws0[4] = {w0.x, w0.y, w0.z, w0.w};
            uint32_t ws1[4] = {w1.x, w1.y, w1.z, w1.w};
#pragma unroll
            for (int i = 0; i < 4; i++)
#pragma unroll
                for (int j = 0; j < 4; j++)
                    acc[i][j] += __popc(xs0[i] ^ ws0[j]) + __popc(xs1[i] ^ ws1[j]);
        }
        {
            uint4 w0 = sWv[k * 16 + cg * 2 + 1];
            uint4 w1 = sWv[(k + 1) * 16 + cg * 2 + 1];
            uint32_t ws0[4] = {w0.x, w0.y, w0.z, w0.w};
            uint32_t ws1[4] = {w1.x, w1.y, w1.z, w1.w};
#pragma unroll
            for (int i = 0; i < 4; i++)
#pragma unroll
                for (int j = 0; j < 4; j++)
                    acc[i][j + 4] += __popc(xs0[i] ^ ws0[j]) + __popc(xs1[i] ^ ws1[j]);
        }
    }

    int pcat[4];
#pragma unroll
    for (int i = 0; i < 4; i++) pcat[i] = pixel_cat(p0 + pg * 4 + i);
    int u[4][8];
#pragma unroll
    for (int j = 0; j < 8; j++) {
        int c = n0 + cg * 8 + j;
#pragma unroll
        for (int i = 0; i < 4; i++) {
            int corr = (pcat[i] == 4) ? 0 : g_corr[pcat[i] * CC + c];
            u[i][j] = KBITS - 2 * acc[i][j] + corr;
        }
    }
#pragma unroll
    for (int j = 0; j < 8; j++) {
        int s = 0, s2 = 0;
#pragma unroll
        for (int i = 0; i < 4; i++) { s += u[i][j]; s2 += u[i][j] * u[i][j]; }
#pragma unroll
        for (int m = 1; m < 16; m <<= 1) {
            s  += __shfl_xor_sync(~0u, s, m);
            s2 += __shfl_xor_sync(~0u, s2, m);
        }
        if ((lane & 15) == 0) {
            int c = n0 + cg * 8 + j;
            atomicAdd(&g_isum[c],   (unsigned long long)(long long)s);
            atomicAdd(&g_isumsq[c], (unsigned long long)(long long)s2);
        }
    }
    {
        int p2 = p0 + pg * 4;
        int b2 = p2 / HWs, hw2 = p2 - b2 * HWs;
        short* yd = g_y16 + (size_t)b2 * CHW + hw2;
#pragma unroll
        for (int j = 0; j < 8; j++) {
            int c = n0 + cg * 8 + j;
            uint2 val;
            val.x = (uint32_t)(u[0][j] & 0xffff) | ((uint32_t)u[1][j] << 16);
            val.y = (uint32_t)(u[2][j] & 0xffff) | ((uint32_t)u[3][j] << 16);
            *(uint2*)&yd[(size_t)c * HWs] = val;
        }
    }
}

// ---------------------------------------------------------------------------
// IMMA half: 4 warps (threads 0..127), 32px x 64c, cp.async 3-stage
// ---------------------------------------------------------------------------
__device__ __forceinline__ void imma_half(uint32_t* smem32, int f) {
    char* smem = (char*)smem32;
    const uint32_t sbase = smem_to_u32(smem);
    const int wg = threadIdx.x;         // 0..127
    const int iw = wg >> 5;
    const int lane = wg & 31;
    const int wm = iw & 1;              // 16-px block
    const int wn = iw >> 1;             // 32-cout block
    const int m0 = IMMA_PIX0 + (f >> 2) * 32;
    const int n0 = (f & 3) * 64;

    const int rA = wg >> 2, qA = wg & 3;          // A: 32 rows x 4 quarters
    int p = m0 + rA;
    int b = p / HWs; int hw = p - b * HWs;
    int h = hw / WW; int w = hw - h * WW;
    const int8_t* asrc =
        G_XA8 + (((size_t)((b - IMMA_B0) * HP + h)) * WP + w) * CC + qA * 16;
    const uint32_t sdstA = (uint32_t)(rA * ISSTR + qA * 16);
    const int rB = wg >> 1, qB = wg & 1;          // B: 64 rows x 2 halves
    const int8_t* bsrc = G_WB + (size_t)(n0 + rB) * KD + qB * 32;
    const uint32_t sdstB = (uint32_t)(IA_BYTES + rB * ISSTR + qB * 32);

    auto issue = [&](int kc) {
        int buf = kc % 3;
        int tap = kc >> 2;
        int ci0 = (kc & 3) * 64;
        int kh = tap / 3, kw = tap - 3 * kh;
        cp16(sbase + buf * ISTAGE + sdstA, asrc + ((kh * WP + kw) * CC + ci0));
        const int8_t* bp = bsrc + tap * 256 + ci0;
        cp16(sbase + buf * ISTAGE + sdstB, bp);
        cp16(sbase + buf * ISTAGE + sdstB + 16, bp + 16);
    };

    int acc[4][4];
#pragma unroll
    for (int nf = 0; nf < 4; nf++)
#pragma unroll
        for (int i = 0; i < 4; i++) acc[nf][i] = 0;

    const uint32_t aFrag = (uint32_t)((wm * 16 + (lane & 15)) * ISSTR + (lane >> 4) * 16);
    const uint32_t bFrag = (uint32_t)(IA_BYTES + (wn * 32 + (lane & 15)) * ISSTR +
                                      (lane >> 4) * 16);

    issue(0); CP_COMMIT();
    issue(1); CP_COMMIT();
    for (int kc = 0; kc < 36; kc++) {
        CP_WAIT1();
        BAR_SYNC(1, 128);
        if (kc + 2 < 36) issue(kc + 2);
        CP_COMMIT();
        const uint32_t sb = sbase + (kc % 3) * ISTAGE;
#pragma unroll
        for (int s = 0; s < 2; s++) {
            uint32_t a0, a1, a2, a3;
            ldsm4(a0, a1, a2, a3, sb + aFrag + s * 32);
#pragma unroll
            for (int nb = 0; nb < 2; nb++) {
                uint32_t b0, b1, b2, b3;
                ldsm4(b0, b1, b2, b3, sb + bFrag + nb * 16 * ISSTR + s * 32);
                mma_s8(acc[2 * nb],     a0, a1, a2, a3, b0, b2);
                mma_s8(acc[2 * nb + 1], a0, a1, a2, a3, b1, b3);
            }
        }
    }

    // epilogue: zero padding is exact -> no correction
#pragma unroll
    for (int nf = 0; nf < 4; nf++) {
#pragma unroll
        for (int jj = 0; jj < 2; jj++) {
            int s = 0, s2 = 0;
#pragma unroll
            for (int rh = 0; rh < 2; rh++) {
                int v = acc[nf][rh * 2 + jj];
                s += v; s2 += v * v;
            }
#pragma unroll
            for (int m = 4; m < 32; m <<= 1) {
                s  += __shfl_xor_sync(~0u, s, m);
                s2 += __shfl_xor_sync(~0u, s2, m);
            }
            if (lane < 4) {
                int c = n0 + wn * 32 + nf * 8 + 2 * lane + jj;
                atomicAdd(&g_isum[c],   (unsigned long long)(long long)s);
                atomicAdd(&g_isumsq[c], (unsigned long long)(long long)s2);
            }
        }
    }
#pragma unroll
    for (int rh = 0; rh < 2; rh++) {
        int p2 = m0 + wm * 16 + (lane >> 2) + rh * 8;
        int b2 = p2 / HWs, hw2 = p2 - b2 * HWs;
        short* yd = g_y16 + (size_t)b2 * CHW + hw2;
#pragma unroll
        for (int nf = 0; nf < 4; nf++) {
            int c = n0 + wn * 32 + nf * 8 + 2 * (lane & 3);
            yd[(size_t)c * HWs]       = (short)acc[nf][rh * 2 + 0];
            yd[(size_t)(c + 1) * HWs] = (short)acc[nf][rh * 2 + 1];
        }
    }
}

// ---------------------------------------------------------------------------
// Pure popc block (R9 body): 256 threads, 64px x 128c, __syncthreads only.
// ---------------------------------------------------------------------------
__device__ __forceinline__ void popc_block256(uint32_t* smem, int q) {
    uint32_t* sW = smem;
    uint32_t* sX = smem + SW_WORDS;
    const int tid = threadIdx.x;
    const int lane = tid & 31;
    const int p0 = PURE_PIX0 + (q >> 1) * 64;
    const int n0 = (q & 1) * 128;

    {
        int col = tid & 127, khalf = tid >> 7;
        for (int k = khalf; k < KW; k += 2)
            sW[k * 128 + col] = g_wpT[k * CC + n0 + col];
    }
    for (int idx = tid; idx < 576; idx += 256) {
        int pix = idx & 63, tap = idx >> 6;
        int p = p0 + pix;
        int b = p / HWs, hw = p - b * HWs;
        int h = hw / WW, w = hw - h * WW;
        int kh = tap / 3, kw = tap - 3 * kh;
        const uint4* src =
            (const uint4*)&g_xp[(((size_t)(b * HP + h + kh)) * WP + (w + kw)) * 8];
        uint4 q0 = src[0], q1 = src[1];
        int kb = tap * 8;
        sX[(kb + 0) * 64 + pix] = q0.x; sX[(kb + 1) * 64 + pix] = q0.y;
        sX[(kb + 2) * 64 + pix] = q0.z; sX[(kb + 3) * 64 + pix] = q0.w;
        sX[(kb + 4) * 64 + pix] = q1.x; sX[(kb + 5) * 64 + pix] = q1.y;
        sX[(kb + 6) * 64 + pix] = q1.z; sX[(kb + 7) * 64 + pix] = q1.w;
    }
    __syncthreads();

    const int pg = tid & 15;
    const int cg = tid >> 4;          // 0..15 over 128c
    const uint4* sXv = (const uint4*)sX;
    const uint4* sWv = (const uint4*)sW;   // row stride 32 uint4

    int acc[4][8];
#pragma unroll
    for (int i = 0; i < 4; i++)
#pragma unroll
        for (int j = 0; j < 8; j++) acc[i][j] = 0;

#pragma unroll 2
    for (int k = 0; k < KW; k += 2) {
        uint4 xq0 = sXv[k * 16 + pg];
        uint4 xq1 = sXv[(k + 1) * 16 + pg];
        uint32_t xs0[4] = {xq0.x, xq0.y, xq0.z, xq0.w};
        uint32_t xs1[4] = {xq1.x, xq1.y, xq1.z, xq1.w};
        {
            uint4 w0 = sWv[k * 32 + cg * 2];
            uint4 w1 = sWv[(k + 1) * 32 + cg * 2];
            uint32_t ws0[4] = {w0.x, w0.y, w0.z, w0.w};
            uint32_t ws1[4] = {w1.x, w1.y, w1.z, w1.w};
#pragma unroll
            for (int i = 0; i < 4; i++)
#pragma unroll
                for (int j = 0; j < 4; j++)
                    acc[i][j] += __popc(xs0[i] ^ ws0[j]) + __popc(xs1[i] ^ ws1[j]);
        }
        {
            uint4 w0 = sWv[k * 32 + cg * 2 + 1];
            uint4 w1 = sWv[(k + 1) * 32 + cg * 2 + 1];
            uint32_t ws0[4] = {w0.x, w0.y, w0.z, w0.w};
            uint32_t ws1[4] = {w1.x, w1.y, w1.z, w1.w};
#pragma unroll
            for (int i = 0; i < 4; i++)
#pragma unroll
                for (int j = 0; j < 4; j++)
                    acc[i][j + 4] += __popc(xs0[i] ^ ws0[j]) + __popc(xs1[i] ^ ws1[j]);
        }
    }

    int pcat[4];
#pragma unroll
    for (int i = 0; i < 4; i++) pcat[i] = pixel_cat(p0 + pg * 4 + i);
    int u[4][8];
#pragma unroll
    for (int j = 0; j < 8; j++) {
        int c = n0 + cg * 8 + j;
#pragma unroll
        for (int i = 0; i < 4; i++) {
            int corr = (pcat[i] == 4) ? 0 : g_corr[pcat[i] * CC + c];
            u[i][j] = KBITS - 2 * acc[i][j] + corr;
        }
    }
#pragma unroll
    for (int j = 0; j < 8; j++) {
        int s = 0, s2 = 0;
#pragma unroll
        for (int i = 0; i < 4; i++) { s += u[i][j]; s2 += u[i][j] * u[i][j]; }
#pragma unroll
        for (int m = 1; m < 16; m <<= 1) {
            s  += __shfl_xor_sync(~0u, s, m);
            s2 += __shfl_xor_sync(~0u, s2, m);
        }
        if ((lane & 15) == 0) {
            int c = n0 + cg * 8 + j;
            atomicAdd(&g_isum[c],   (unsigned long long)(long long)s);
            atomicAdd(&g_isumsq[c], (unsigned long long)(long long)s2);
        }
    }
    {
        int p2 = p0 + pg * 4;
        int b2 = p2 / HWs, hw2 = p2 - b2 * HWs;
        short* yd = g_y16 + (size_t)b2 * CHW + hw2;
#pragma unroll
        for (int j = 0; j < 8; j++) {
            int c = n0 + cg * 8 + j;
            uint2 val;
            val.x = (uint32_t)(u[0][j] & 0xffff) | ((uint32_t)u[1][j] << 16);
            val.y = (uint32_t)(u[2][j] & 0xffff) | ((uint32_t)u[3][j] << 16);
            *(uint2*)&yd[(size_t)c * HWs] = val;
        }
    }
}

// ---------------------------------------------------------------------------
// Unified kernel: fused warp-specialized CTAs with 10% pure popc blocks
// Bresenham-interleaved (engine split ~0.29 IMMA).
// ---------------------------------------------------------------------------
__global__ __launch_bounds__(256, 3) void gemm_kernel() {
    extern __shared__ uint32_t smem[];
    const uint32_t bid = blockIdx.x;
    const uint32_t before = (bid * (uint32_t)PURE_BLOCKS) / (uint32_t)TOT_BLOCKS;
    const uint32_t after  = ((bid + 1) * (uint32_t)PURE_BLOCKS) / (uint32_t)TOT_BLOCKS;
    if (after > before) {
        popc_block256(smem, (int)before);
    } else {
        int f = (int)(bid - before);
        if (threadIdx.x < 128) {
            imma_half(smem, f);
        } else {
            int wg = threadIdx.x - 128;
            int p0 = (f >> 2) * 64;
            int n0 = (f & 3) * 64;
            popc_half(smem + PW_OFF, smem + PX_OFF, wg, p0, n0);
        }
    }
}

// ---------------------------------------------------------------------------
// Kernel: BN affine coefficients
// ---------------------------------------------------------------------------
__global__ void coeff_kernel(const float* __restrict__ gamma, const float* __restrict__ beta) {
    int c = threadIdx.x;
    double n  = (double)PIX;
    double mu = (double)(long long)g_isum[c] / n;
    double vu = (double)(long long)g_isumsq[c] / n - mu * mu;
    double sc = (double)g_scale[c];
    double A  = (double)gamma[c] * sc / sqrt(sc * sc * vu + (double)BN_EPS);
    g_ab[c]      = (float)A;
    g_ab[CC + c] = (float)((double)beta[c] - A * mu);
}

// ---------------------------------------------------------------------------
// Kernel: out = relu(A*u + B), int16 -> fp32, NCHW
// ---------------------------------------------------------------------------
__global__ void finalize_kernel(float* __restrict__ out) {
    size_t idx = (size_t)blockIdx.x * 256 + threadIdx.x;
    size_t j = idx * 8;
    int c = (int)((j / HWs) & 255);
    float A = g_ab[c], Bv = g_ab[CC + c];
    uint4 raw = ((const uint4*)g_y16)[idx];
    float4 o0, o1;
    o0.x = fmaxf(fmaf((float)(short)(raw.x & 0xffff), A, Bv), 0.0f);
    o0.y = fmaxf(fmaf((float)(short)(raw.x >> 16),    A, Bv), 0.0f);
    o0.z = fmaxf(fmaf((float)(short)(raw.y & 0xffff), A, Bv), 0.0f);
    o0.w = fmaxf(fmaf((float)(short)(raw.y >> 16),    A, Bv), 0.0f);
    o1.x = fmaxf(fmaf((float)(short)(raw.z & 0xffff), A, Bv), 0.0f);
    o1.y = fmaxf(fmaf((float)(short)(raw.z >> 16),    A, Bv), 0.0f);
    o1.z = fmaxf(fmaf((float)(short)(raw.w & 0xffff), A, Bv), 0.0f);
    o1.w = fmaxf(fmaf((float)(short)(raw.w >> 16),    A, Bv), 0.0f);
    ((float4*)out)[idx * 2]     = o0;
    ((float4*)out)[idx * 2 + 1] = o1;
}

// ---------------------------------------------------------------------------
// Launch (gemm stays at launch index 3 so the profiler lands on it)
// ---------------------------------------------------------------------------
extern "C" void kernel_launch(void* const* d_in, const int* in_sizes, int n_in,
                              void* d_out, int out_size) {
    (void)in_sizes; (void)n_in; (void)out_size;
    const float* x     = (const float*)d_in[0];
    const float* wt    = (const float*)d_in[1];
    const float* gamma = (const float*)d_in[2];
    const float* beta  = (const float*)d_in[3];
    float* out = (float*)d_out;

    static int smem_set = 0;
    if (!smem_set) {
        cudaFuncSetAttribute(gemm_kernel, cudaFuncAttributeMaxDynamicSharedMemorySize,
                             SMEM_DYN);
        smem_set = 1;
    }

    wprep_kernel<<<256, 256>>>(wt);
    ring_zero_kernel<<<dim3(228, BB), 32>>>();
    xpack_kernel<<<dim3(HH, BB), 256>>>(x);
    gemm_kernel<<<TOT_BLOCKS, 256, SMEM_DYN>>>();
    coeff_kernel<<<1, 256>>>(gamma, beta);
    finalize_kernel<<<(int)((size_t)PIX * CC / 8 / 256), 256>>>(out);
}

// round 16
// speedup vs baseline: 1.3052x; 1.0321x over previous
#include <cuda_runtime.h>
#include <cstdint>

// ---------------------------------------------------------------------------
// Problem constants
// ---------------------------------------------------------------------------
constexpr int BB = 32, CC = 256, HH = 56, WW = 56;
constexpr int HP = 58, WP = 58;                 // padded spatial
constexpr int HWs = HH * WW;                    // 3136
constexpr int CHW = CC * HWs;                   // 802816
constexpr int PIX = BB * HWs;                   // 100352
constexpr int KW  = 72;                         // K in 32-bit words (2304 bits)
constexpr int KD  = 2304;                       // K in int8 elements
constexpr int KBITS = 2304;
constexpr float BN_EPS = 1e-5f;

// ---- engine split (f ~= 0.29):
//  popc-in-fused px [0, 58240), popc-pure [58240, 71232), IMMA [71232, 100352)
constexpr int FUSED_PT   = 910;
constexpr int PURE_PIX0  = FUSED_PT * 64;       // 58240
constexpr int PURE_PT    = 203;
constexpr int IMMA_PIX0  = PURE_PIX0 + PURE_PT * 64;  // 71232
constexpr int IMMA_B0    = 22;                  // first batch holding IMMA px
constexpr int IMMA_NB    = 10;                  // batches 22..31 -> int8 xa
constexpr int FUSED_BLOCKS = FUSED_PT * 4;      // 3640
constexpr int PURE_BLOCKS  = PURE_PT * 2;       // 406
constexpr int TOT_BLOCKS   = FUSED_BLOCKS + PURE_BLOCKS;  // 4046

// smem layout (fused CTA): IMMA 3 stages then popc W/X tiles
constexpr int ISSTR = 80;
constexpr int IA_BYTES = 32 * ISSTR;            // 2560
constexpr int IB_BYTES = 64 * ISSTR;            // 5120
constexpr int ISTAGE = IA_BYTES + IB_BYTES;     // 7680, x3 = 23040
constexpr int PW_OFF = 23040 / 4;               // word offset of popc W [72][64]
constexpr int PX_OFF = PW_OFF + KW * 64;        // popc X [72][64]
constexpr int SMEM_DYN = (PX_OFF + KW * 64) * 4;   // 59904 B

// pure popc block layout: W [72][128] at 0, X [72][64] after
constexpr int SW_WORDS = KW * 128;              // 9216 (words)

// merged prep kernel block ranges
constexpr int PREP_WPREP = 256;
constexpr int PREP_XPACK = PREP_WPREP + HH * BB;   // 256 + 1792 = 2048
constexpr int PREP_BLOCKS = PREP_XPACK + BB;       // + 32 ring blocks = 2080

// ---------------------------------------------------------------------------
// Device scratch (allocation-free: __device__ globals)
// ---------------------------------------------------------------------------
__device__ uint32_t g_xp[(size_t)BB * HP * WP * 8];   // packed x, padded NHWC
__device__ uint4    g_xa8_raw[(size_t)IMMA_NB * HP * WP * CC / 16]; // int8 xa
__device__ uint32_t g_wpT[KW * CC];                   // packed w, [k][cout]
__device__ uint4    g_wb_raw[(size_t)CC * KD / 16];   // int8 w, [co][tap*256+ci]
__device__ int      g_corr[9 * CC];                   // border corrections
__device__ short    g_y16[(size_t)PIX * CC];          // conv result, NCHW int16
__device__ float    g_scale[CC];
__device__ unsigned long long g_isum[CC];
__device__ unsigned long long g_isumsq[CC];

#define G_WB  ((int8_t*)g_wb_raw)
#define G_XA8 ((int8_t*)g_xa8_raw)

// ---------------------------------------------------------------------------
// PTX helpers (baseline, assemble at .target sm_103)
// ---------------------------------------------------------------------------
__device__ __forceinline__ uint32_t smem_to_u32(const void* p) {
    uint32_t a;
    asm("{ .reg .u64 t; cvta.to.shared.u64 t, %1; cvt.u32.u64 %0, t; }" : "=r"(a) : "l"(p));
    return a;
}
__device__ __forceinline__ void cp16(uint32_t dst, const void* src) {
    asm volatile("cp.async.cg.shared.global [%0], [%1], 16;" :: "r"(dst), "l"(src));
}
#define CP_COMMIT() asm volatile("cp.async.commit_group;" ::: "memory")
#define CP_WAIT1()  asm volatile("cp.async.wait_group 1;" ::: "memory")
#define BAR_SYNC(id, cnt) \
    asm volatile("bar.sync %0, %1;" :: "r"(id), "r"(cnt) : "memory")
__device__ __forceinline__ void ldsm4(uint32_t& r0, uint32_t& r1, uint32_t& r2,
                                      uint32_t& r3, uint32_t addr) {
    asm volatile("ldmatrix.sync.aligned.m8n8.x4.shared.b16 {%0,%1,%2,%3}, [%4];"
                 : "=r"(r0), "=r"(r1), "=r"(r2), "=r"(r3) : "r"(addr));
}
__device__ __forceinline__ void mma_s8(int* d, uint32_t a0, uint32_t a1,
                                       uint32_t a2, uint32_t a3,
                                       uint32_t b0, uint32_t b1) {
    asm volatile(
        "mma.sync.aligned.m16n8k32.row.col.s32.s8.s8.s32 "
        "{%0,%1,%2,%3}, {%4,%5,%6,%7}, {%8,%9}, {%0,%1,%2,%3};"
        : "+r"(d[0]), "+r"(d[1]), "+r"(d[2]), "+r"(d[3])
        : "r"(a0), "r"(a1), "r"(a2), "r"(a3), "r"(b0), "r"(b1));
}

// ---------------------------------------------------------------------------
// Merged prep kernel: wprep (blocks 0..255) | xpack (256..2047) | ring (2048..2079)
// ---------------------------------------------------------------------------
__global__ void prep_kernel(const float* __restrict__ x, const float* __restrict__ w) {
    const int bid = blockIdx.x;
    const int tid = threadIdx.x;
    const int lane = tid & 31, warp = tid >> 5;

    if (bid < PREP_WPREP) {
        // ---- weight prep: scale, packed bits, int8 signs, corr table ----
        __shared__ float sh[8];
        __shared__ uint32_t words[9][8];
        __shared__ int S[9];
        int o = bid;
        const float* wp = w + ((size_t)o * CC + tid) * 9;
        float v[9]; float s = 0.0f;
#pragma unroll
        for (int t = 0; t < 9; t++) { v[t] = wp[t]; s += fabsf(v[t]); }
#pragma unroll
        for (int off = 16; off; off >>= 1) s += __shfl_xor_sync(~0u, s, off);
        if (lane == 0) sh[warp] = s;
#pragma unroll
        for (int t = 0; t < 9; t++) {
            uint32_t m = __ballot_sync(~0u, v[t] > 0.0f);
            if (lane == 0) words[t][warp] = m;
            int sg = (v[t] > 0.0f) ? 1 : ((v[t] < 0.0f) ? -1 : 0);
            G_WB[(size_t)o * KD + t * 256 + tid] = (int8_t)sg;
        }
        __syncthreads();
        if (tid == 0) {
            float tot = 0.0f;
            for (int i = 0; i < 8; i++) tot += sh[i];
            g_scale[o] = tot / (float)KBITS;
            g_isum[o] = 0ull; g_isumsq[o] = 0ull;
        }
        if (tid < 72) {
            int t = tid >> 3, j = tid & 7;
            g_wpT[(t * 8 + j) * CC + o] = words[t][j];
        }
        if (tid < 9) {
            int P = 0;
            for (int j = 0; j < 8; j++) P += __popc(words[tid][j]);
            S[tid] = 2 * P - 256;
        }
        __syncthreads();
        if (tid < 9) {
            int ht = tid / 3, wt = tid % 3;
            int corr = 0;
            for (int kh = 0; kh < 3; kh++)
                for (int kw = 0; kw < 3; kw++) {
                    bool miss = (ht == 0 && kh == 0) || (ht == 2 && kh == 2) ||
                                (wt == 0 && kw == 0) || (wt == 2 && kw == 2);
                    if (miss) corr += S[kh * 3 + kw];
                }
            g_corr[tid * CC + o] = corr;
        }
    } else if (bid < PREP_XPACK) {
        // ---- xpack: sign bits (all batches) + direct int8 expansion ----
        int idx = bid - PREP_WPREP;
        int h = idx % HH, b = idx / HH;
        const float4* xrow =
            (const float4*)(x + (((size_t)(b * CC + warp * 32 + lane)) * HH + h) * WW);
        uint32_t* base = &g_xp[(((size_t)(b * HP + h + 1)) * WP + 1) * 8 + warp];
        const bool do8 = (b >= IMMA_B0);
        int8_t* a8base = do8
            ? &G_XA8[(((size_t)((b - IMMA_B0) * HP + h + 1)) * WP + 1) * CC + warp * 32]
            : (int8_t*)nullptr;
        const int pix = lane >> 3;
        const int sub = lane & 7;
        for (int w0 = 0; w0 < WW; w0 += 4) {
            float4 v = xrow[w0 >> 2];
            uint32_t m0 = __ballot_sync(~0u, v.x > 0.0f);
            uint32_t m1 = __ballot_sync(~0u, v.y > 0.0f);
            uint32_t m2 = __ballot_sync(~0u, v.z > 0.0f);
            uint32_t m3 = __ballot_sync(~0u, v.w > 0.0f);
            if (lane == 0) {
                base[(w0 + 0) * 8] = m0; base[(w0 + 1) * 8] = m1;
                base[(w0 + 2) * 8] = m2; base[(w0 + 3) * 8] = m3;
            }
            if (do8) {
                uint32_t mm = (pix == 0) ? m0 : (pix == 1) ? m1 : (pix == 2) ? m2 : m3;
                uint32_t nib = (mm >> (sub * 4)) & 0xFu;
                uint32_t spread = (nib * 0x00204081u) & 0x01010101u;
                uint32_t word = __vsub4(spread << 1, 0x01010101u);
                *(uint32_t*)&a8base[(size_t)(w0 + pix) * CC + sub * 4] = word;
            }
        }
    } else {
        // ---- ring zero: pad borders of g_xp (all b) and g_xa8 (b>=22) ----
        int b = bid - PREP_XPACK;
        for (int i = tid; i < 228 * 8; i += 256) {
            int pos = i >> 3, word = i & 7;
            int h, w2;
            if (pos < 58)       { h = 0;            w2 = pos; }
            else if (pos < 116) { h = 57;           w2 = pos - 58; }
            else if (pos < 172) { h = pos - 116 + 1; w2 = 0; }
            else                { h = pos - 172 + 1; w2 = 57; }
            g_xp[(((size_t)(b * HP + h)) * WP + w2) * 8 + word] = 0;
        }
        if (b >= IMMA_B0) {
            int bp = b - IMMA_B0;
            for (int i = tid; i < 228 * 16; i += 256) {
                int pos = i >> 4, q = i & 15;
                int h, w2;
                if (pos < 58)       { h = 0;            w2 = pos; }
                else if (pos < 116) { h = 57;           w2 = pos - 58; }
                else if (pos < 172) { h = pos - 116 + 1; w2 = 0; }
                else                { h = pos - 172 + 1; w2 = 57; }
                ((uint4*)&G_XA8[(((size_t)(bp * HP + h)) * WP + w2) * CC])[q] =
                    make_uint4(0, 0, 0, 0);
            }
        }
    }
}

// ---------------------------------------------------------------------------
__device__ __forceinline__ int pixel_cat(int p) {
    int hw = p % HWs;
    int h = hw / WW, w = hw - h * WW;
    int ht = (h == 0) ? 0 : ((h == HH - 1) ? 2 : 1);
    int wt = (w == 0) ? 0 : ((w == WW - 1) ? 2 : 1);
    return ht * 3 + wt;
}

// ---------------------------------------------------------------------------
// popc half (fused CTA): 128 threads, 64px x 64c, named barrier 3.
// ---------------------------------------------------------------------------
__device__ __forceinline__ void popc_half(uint32_t* sW, uint32_t* sX,
                                          int wg, int p0, int n0) {
    {
        int col = wg & 63, khalf = wg >> 6;
        for (int k = khalf; k < KW; k += 2)
            sW[k * 64 + col] = g_wpT[k * CC + n0 + col];
    }
    for (int idx = wg; idx < 576; idx += 128) {
        int pix = idx & 63, tap = idx >> 6;
        int p = p0 + pix;
        int b = p / HWs, hw = p - b * HWs;
        int h = hw / WW, w = hw - h * WW;
        int kh = tap / 3, kw = tap - 3 * kh;
        const uint4* src =
            (const uint4*)&g_xp[(((size_t)(b * HP + h + kh)) * WP + (w + kw)) * 8];
        uint4 q0 = src[0], q1 = src[1];
        int kb = tap * 8;
        sX[(kb + 0) * 64 + pix] = q0.x; sX[(kb + 1) * 64 + pix] = q0.y;
        sX[(kb + 2) * 64 + pix] = q0.z; sX[(kb + 3) * 64 + pix] = q0.w;
        sX[(kb + 4) * 64 + pix] = q1.x; sX[(kb + 5) * 64 + pix] = q1.y;
        sX[(kb + 6) * 64 + pix] = q1.z; sX[(kb + 7) * 64 + pix] = q1.w;
    }
    BAR_SYNC(3, 128);

    const int pg = wg & 15;
    const int cg = wg >> 4;
    const int lane = wg & 31;
    const uint4* sXv = (const uint4*)sX;
    const uint4* sWv = (const uint4*)sW;

    int acc[4][8];
#pragma unroll
    for (int i = 0; i < 4; i++)
#pragma unroll
        for (int j = 0; j < 8; j++) acc[i][j] = 0;

#pragma unroll 2
    for (int k = 0; k < KW; k += 2) {
        uint4 xq0 = sXv[k * 16 + pg];
        uint4 xq1 = sXv[(k + 1) * 16 + pg];
        uint32_t xs0[4] = {xq0.x, xq0.y, xq0.z, xq0.w};
        uint32_t xs1[4] = {xq1.x, xq1.y, xq1.z, xq1.w};
        {
            uint4 w0 = sWv[k * 16 + cg * 2];
            uint4 w1 = sWv[(k + 1) * 16 + cg * 2];
            uint32_t ws0[4] = {w0.x, w0.y, w0.z, w0.w};
            uint32_t ws1[4] = {w1.x, w1.y, w1.z, w1.w};
#pragma unroll
            for (int i = 0; i < 4; i++)
#pragma unroll
                for (int j = 0; j < 4; j++)
                    acc[i][j] += __popc(xs0[i] ^ ws0[j]) + __popc(xs1[i] ^ ws1[j]);
        }
        {
            uint4 w0 = sWv[k * 16 + cg * 2 + 1];
            uint4 w1 = sWv[(k + 1) * 16 + cg * 2 + 1];
            uint32_t ws0[4] = {w0.x, w0.y, w0.z, w0.w};
            uint32_t ws1[4] = {w1.x, w1.y, w1.z, w1.w};
#pragma unroll
            for (int i = 0; i < 4; i++)
#pragma unroll
                for (int j = 0; j < 4; j++)
                    acc[i][j + 4] += __popc(xs0[i] ^ ws0[j]) + __popc(xs1[i] ^ ws1[j]);
        }
    }

    int pcat[4];
#pragma unroll
    for (int i = 0; i < 4; i++) pcat[i] = pixel_cat(p0 + pg * 4 + i);
    int u[4][8];
#pragma unroll
    for (int j = 0; j < 8; j++) {
        int c = n0 + cg * 8 + j;
#pragma unroll
        for (int i = 0; i < 4; i++) {
            int corr = (pcat[i] == 4) ? 0 : g_corr[pcat[i] * CC + c];
            u[i][j] = KBITS - 2 * acc[i][j] + corr;
        }
    }
#pragma unroll
    for (int j = 0; j < 8; j++) {
        int s = 0, s2 = 0;
#pragma unroll
        for (int i = 0; i < 4; i++) { s += u[i][j]; s2 += u[i][j] * u[i][j]; }
#pragma unroll
        for (int m = 1; m < 16; m <<= 1) {
            s  += __shfl_xor_sync(~0u, s, m);
            s2 += __shfl_xor_sync(~0u, s2, m);
        }
        if ((lane & 15) == 0) {
            int c = n0 + cg * 8 + j;
            atomicAdd(&g_isum[c],   (unsigned long long)(long long)s);
            atomicAdd(&g_isumsq[c], (unsigned long long)(long long)s2);
        }
    }
    {
        int p2 = p0 + pg * 4;
        int b2 = p2 / HWs, hw2 = p2 - b2 * HWs;
        short* yd = g_y16 + (size_t)b2 * CHW + hw2;
#pragma unroll
        for (int j = 0; j < 8; j++) {
            int c = n0 + cg * 8 + j;
            uint2 val;
            val.x = (uint32_t)(u[0][j] & 0xffff) | ((uint32_t)u[1][j] << 16);
            val.y = (uint32_t)(u[2][j] & 0xffff) | ((uint32_t)u[3][j] << 16);
            *(uint2*)&yd[(size_t)c * HWs] = val;
        }
    }
}

// ---------------------------------------------------------------------------
// IMMA half: 4 warps (threads 0..127), 32px x 64c, cp.async 3-stage
// ---------------------------------------------------------------------------
__device__ __forceinline__ void imma_half(uint32_t* smem32, int f) {
    char* smem = (char*)smem32;
    const uint32_t sbase = smem_to_u32(smem);
    const int wg = threadIdx.x;
    const int iw = wg >> 5;
    const int lane = wg & 31;
    const int wm = iw & 1;
    const int wn = iw >> 1;
    const int m0 = IMMA_PIX0 + (f >> 2) * 32;
    const int n0 = (f & 3) * 64;

    const int rA = wg >> 2, qA = wg & 3;
    int p = m0 + rA;
    int b = p / HWs; int hw = p - b * HWs;
    int h = hw / WW; int w = hw - h * WW;
    const int8_t* asrc =
        G_XA8 + (((size_t)((b - IMMA_B0) * HP + h)) * WP + w) * CC + qA * 16;
    const uint32_t sdstA = (uint32_t)(rA * ISSTR + qA * 16);
    const int rB = wg >> 1, qB = wg & 1;
    const int8_t* bsrc = G_WB + (size_t)(n0 + rB) * KD + qB * 32;
    const uint32_t sdstB = (uint32_t)(IA_BYTES + rB * ISSTR + qB * 32);

    auto issue = [&](int kc) {
        int buf = kc % 3;
        int tap = kc >> 2;
        int ci0 = (kc & 3) * 64;
        int kh = tap / 3, kw = tap - 3 * kh;
        cp16(sbase + buf * ISTAGE + sdstA, asrc + ((kh * WP + kw) * CC + ci0));
        const int8_t* bp = bsrc + tap * 256 + ci0;
        cp16(sbase + buf * ISTAGE + sdstB, bp);
        cp16(sbase + buf * ISTAGE + sdstB + 16, bp + 16);
    };

    int acc[4][4];
#pragma unroll
    for (int nf = 0; nf < 4; nf++)
#pragma unroll
        for (int i = 0; i < 4; i++) acc[nf][i] = 0;

    const uint32_t aFrag = (uint32_t)((wm * 16 + (lane & 15)) * ISSTR + (lane >> 4) * 16);
    const uint32_t bFrag = (uint32_t)(IA_BYTES + (wn * 32 + (lane & 15)) * ISSTR +
                                      (lane >> 4) * 16);

    issue(0); CP_COMMIT();
    issue(1); CP_COMMIT();
    for (int kc = 0; kc < 36; kc++) {
        CP_WAIT1();
        BAR_SYNC(1, 128);
        if (kc + 2 < 36) issue(kc + 2);
        CP_COMMIT();
        const uint32_t sb = sbase + (kc % 3) * ISTAGE;
#pragma unroll
        for (int s = 0; s < 2; s++) {
            uint32_t a0, a1, a2, a3;
            ldsm4(a0, a1, a2, a3, sb + aFrag + s * 32);
#pragma unroll
            for (int nb = 0; nb < 2; nb++) {
                uint32_t b0, b1, b2, b3;
                ldsm4(b0, b1, b2, b3, sb + bFrag + nb * 16 * ISSTR + s * 32);
                mma_s8(acc[2 * nb],     a0, a1, a2, a3, b0, b2);
                mma_s8(acc[2 * nb + 1], a0, a1, a2, a3, b1, b3);
            }
        }
    }

#pragma unroll
    for (int nf = 0; nf < 4; nf++) {
#pragma unroll
        for (int jj = 0; jj < 2; jj++) {
            int s = 0, s2 = 0;
#pragma unroll
            for (int rh = 0; rh < 2; rh++) {
                int v = acc[nf][rh * 2 + jj];
                s += v; s2 += v * v;
            }
#pragma unroll
            for (int m = 4; m < 32; m <<= 1) {
                s  += __shfl_xor_sync(~0u, s, m);
                s2 += __shfl_xor_sync(~0u, s2, m);
            }
            if (lane < 4) {
                int c = n0 + wn * 32 + nf * 8 + 2 * lane + jj;
                atomicAdd(&g_isum[c],   (unsigned long long)(long long)s);
                atomicAdd(&g_isumsq[c], (unsigned long long)(long long)s2);
            }
        }
    }
#pragma unroll
    for (int rh = 0; rh < 2; rh++) {
        int p2 = m0 + wm * 16 + (lane >> 2) + rh * 8;
        int b2 = p2 / HWs, hw2 = p2 - b2 * HWs;
        short* yd = g_y16 + (size_t)b2 * CHW + hw2;
#pragma unroll
        for (int nf = 0; nf < 4; nf++) {
            int c = n0 + wn * 32 + nf * 8 + 2 * (lane & 3);
            yd[(size_t)c * HWs]       = (short)acc[nf][rh * 2 + 0];
            yd[(size_t)(c + 1) * HWs] = (short)acc[nf][rh * 2 + 1];
        }
    }
}

// ---------------------------------------------------------------------------
// Pure popc block: 256 threads, 64px x 128c, __syncthreads only.
// ---------------------------------------------------------------------------
__device__ __forceinline__ void popc_block256(uint32_t* smem, int q) {
    uint32_t* sW = smem;
    uint32_t* sX = smem + SW_WORDS;
    const int tid = threadIdx.x;
    const int lane = tid & 31;
    const int p0 = PURE_PIX0 + (q >> 1) * 64;
    const int n0 = (q & 1) * 128;

    {
        int col = tid & 127, khalf = tid >> 7;
        for (int k = khalf; k < KW; k += 2)
            sW[k * 128 + col] = g_wpT[k * CC + n0 + col];
    }
    for (int idx = tid; idx < 576; idx += 256) {
        int pix = idx & 63, tap = idx >> 6;
        int p = p0 + pix;
        int b = p / HWs, hw = p - b * HWs;
        int h = hw / WW, w = hw - h * WW;
        int kh = tap / 3, kw = tap - 3 * kh;
        const uint4* src =
            (const uint4*)&g_xp[(((size_t)(b * HP + h + kh)) * WP + (w + kw)) * 8];
        uint4 q0 = src[0], q1 = src[1];
        int kb = tap * 8;
        sX[(kb + 0) * 64 + pix] = q0.x; sX[(kb + 1) * 64 + pix] = q0.y;
        sX[(kb + 2) * 64 + pix] = q0.z; sX[(kb + 3) * 64 + pix] = q0.w;
        sX[(kb + 4) * 64 + pix] = q1.x; sX[(kb + 5) * 64 + pix] = q1.y;
        sX[(kb + 6) * 64 + pix] = q1.z; sX[(kb + 7) * 64 + pix] = q1.w;
    }
    __syncthreads();

    const int pg = tid & 15;
    const int cg = tid >> 4;
    const uint4* sXv = (const uint4*)sX;
    const uint4* sWv = (const uint4*)sW;

    int acc[4][8];
#pragma unroll
    for (int i = 0; i < 4; i++)
#pragma unroll
        for (int j = 0; j < 8; j++) acc[i][j] = 0;

#pragma unroll 2
    for (int k = 0; k < KW; k += 2) {
        uint4 xq0 = sXv[k * 16 + pg];
        uint4 xq1 = sXv[(k + 1) * 16 + pg];
        uint32_t xs0[4] = {xq0.x, xq0.y, xq0.z, xq0.w};
        uint32_t xs1[4] = {xq1.x, xq1.y, xq1.z, xq1.w};
        {
            uint4 w0 = sWv[k * 32 + cg * 2];
            uint4 w1 = sWv[(k + 1) * 32 + cg * 2];
            uint32_t ws0[4] = {w0.x, w0.y, w0.z, w0.w};
            uint32_t ws1[4] = {w1.x, w1.y, w1.z, w1.w};
#pragma unroll
            for (int i = 0; i < 4; i++)
#pragma unroll
                for (int j = 0; j < 4; j++)
                    acc[i][j] += __popc(xs0[i] ^ ws0[j]) + __popc(xs1[i] ^ ws1[j]);
        }
        {
            uint4 w0 = sWv[k * 32 + cg * 2 + 1];
            uint4 w1 = sWv[(k + 1) * 32 + cg * 2 + 1];
            uint32_t ws0[4] = {w0.x, w0.y, w0.z, w0.w};
            uint32_t ws1[4] = {w1.x, w1.y, w1.z, w1.w};
#pragma unroll
            for (int i = 0; i < 4; i++)
#pragma unroll
                for (int j = 0; j < 4; j++)
                    acc[i][j + 4] += __popc(xs0[i] ^ ws0[j]) + __popc(xs1[i] ^ ws1[j]);
        }
    }

    int pcat[4];
#pragma unroll
    for (int i = 0; i < 4; i++) pcat[i] = pixel_cat(p0 + pg * 4 + i);
    int u[4][8];
#pragma unroll
    for (int j = 0; j < 8; j++) {
        int c = n0 + cg * 8 + j;
#pragma unroll
        for (int i = 0; i < 4; i++) {
            int corr = (pcat[i] == 4) ? 0 : g_corr[pcat[i] * CC + c];
            u[i][j] = KBITS - 2 * acc[i][j] + corr;
        }
    }
#pragma unroll
    for (int j = 0; j < 8; j++) {
        int s = 0, s2 = 0;
#pragma unroll
        for (int i = 0; i < 4; i++) { s += u[i][j]; s2 += u[i][j] * u[i][j]; }
#pragma unroll
        for (int m = 1; m < 16; m <<= 1) {
            s  += __shfl_xor_sync(~0u, s, m);
            s2 += __shfl_xor_sync(~0u, s2, m);
        }
        if ((lane & 15) == 0) {
            int c = n0 + cg * 8 + j;
            atomicAdd(&g_isum[c],   (unsigned long long)(long long)s);
            atomicAdd(&g_isumsq[c], (unsigned long long)(long long)s2);
        }
    }
    {
        int p2 = p0 + pg * 4;
        int b2 = p2 / HWs, hw2 = p2 - b2 * HWs;
        short* yd = g_y16 + (size_t)b2 * CHW + hw2;
#pragma unroll
        for (int j = 0; j < 8; j++) {
            int c = n0 + cg * 8 + j;
            uint2 val;
            val.x = (uint32_t)(u[0][j] & 0xffff) | ((uint32_t)u[1][j] << 16);
            val.y = (uint32_t)(u[2][j] & 0xffff) | ((uint32_t)u[3][j] << 16);
            *(uint2*)&yd[(size_t)c * HWs] = val;
        }
    }
}

// ---------------------------------------------------------------------------
// Unified gemm: fused warp-specialized CTAs + 10% pure popc, Bresenham mix
// ---------------------------------------------------------------------------
__global__ __launch_bounds__(256, 3) void gemm_kernel() {
    extern __shared__ uint32_t smem[];
    const uint32_t bid = blockIdx.x;
    const uint32_t before = (bid * (uint32_t)PURE_BLOCKS) / (uint32_t)TOT_BLOCKS;
    const uint32_t after  = ((bid + 1) * (uint32_t)PURE_BLOCKS) / (uint32_t)TOT_BLOCKS;
    if (after > before) {
        popc_block256(smem, (int)before);
    } else {
        int f = (int)(bid - before);
        if (threadIdx.x < 128) {
            imma_half(smem, f);
        } else {
            int wg = threadIdx.x - 128;
            int p0 = (f >> 2) * 64;
            int n0 = (f & 3) * 64;
            popc_half(smem + PW_OFF, smem + PX_OFF, wg, p0, n0);
        }
    }
}

// ---------------------------------------------------------------------------
// Kernel: out = relu(A*u + B), BN coefficients computed inline (fp32).
// ---------------------------------------------------------------------------
__global__ void finalize_kernel(float* __restrict__ out,
                                const float* __restrict__ gamma,
                                const float* __restrict__ beta) {
    size_t idx = (size_t)blockIdx.x * 256 + threadIdx.x;
    size_t j = idx * 8;
    int c = (int)((j / HWs) & 255);
    float n  = (float)PIX;
    float mu = (float)(long long)g_isum[c] / n;
    float vu = fmaf(-mu, mu, (float)(long long)g_isumsq[c] / n);
    float sc = g_scale[c];
    float A  = gamma[c] * sc * rsqrtf(fmaf(sc * sc, vu, BN_EPS));
    float Bv = fmaf(-A, mu, beta[c]);
    uint4 raw = ((const uint4*)g_y16)[idx];
    float4 o0, o1;
    o0.x = fmaxf(fmaf((float)(short)(raw.x & 0xffff), A, Bv), 0.0f);
    o0.y = fmaxf(fmaf((float)(short)(raw.x >> 16),    A, Bv), 0.0f);
    o0.z = fmaxf(fmaf((float)(short)(raw.y & 0xffff), A, Bv), 0.0f);
    o0.w = fmaxf(fmaf((float)(short)(raw.y >> 16),    A, Bv), 0.0f);
    o1.x = fmaxf(fmaf((float)(short)(raw.z & 0xffff), A, Bv), 0.0f);
    o1.y = fmaxf(fmaf((float)(short)(raw.z >> 16),    A, Bv), 0.0f);
    o1.z = fmaxf(fmaf((float)(short)(raw.w & 0xffff), A, Bv), 0.0f);
    o1.w = fmaxf(fmaf((float)(short)(raw.w >> 16),    A, Bv), 0.0f);
    ((float4*)out)[idx * 2]     = o0;
    ((float4*)out)[idx * 2 + 1] = o1;
}

// ---------------------------------------------------------------------------
// Launch: 3 kernels total (prep | gemm | finalize)
// ---------------------------------------------------------------------------
extern "C" void kernel_launch(void* const* d_in, const int* in_sizes, int n_in,
                              void* d_out, int out_size) {
    (void)in_sizes; (void)n_in; (void)out_size;
    const float* x     = (const float*)d_in[0];
    const float* wt    = (const float*)d_in[1];
    const float* gamma = (const float*)d_in[2];
    const float* beta  = (const float*)d_in[3];
    float* out = (float*)d_out;

    static int smem_set = 0;
    if (!smem_set) {
        cudaFuncSetAttribute(gemm_kernel, cudaFuncAttributeMaxDynamicSharedMemorySize,
                             SMEM_DYN);
        smem_set = 1;
    }

    prep_kernel<<<PREP_BLOCKS, 256>>>(x, wt);
    gemm_kernel<<<TOT_BLOCKS, 256, SMEM_DYN>>>();
    finalize_kernel<<<(int)((size_t)PIX * CC / 8 / 256), 256>>>(out, gamma, beta);
}

// round 17
// speedup vs baseline: 1.3362x; 1.0237x over previous
#include <cuda_runtime.h>
#include <cstdint>

// ---------------------------------------------------------------------------
// Problem constants
// ---------------------------------------------------------------------------
constexpr int BB = 32, CC = 256, HH = 56, WW = 56;
constexpr int HP = 58, WP = 58;                 // padded spatial
constexpr int HWs = HH * WW;                    // 3136
constexpr int CHW = CC * HWs;                   // 802816
constexpr int PIX = BB * HWs;                   // 100352
constexpr int KW  = 72;                         // K in 32-bit words (2304 bits)
constexpr int KD  = 2304;                       // K in int8 elements
constexpr int KBITS = 2304;
constexpr float BN_EPS = 1e-5f;

// ---- engine split (f ~= 0.29):
//  popc-in-fused px [0, 58240), popc-pure [58240, 71232), IMMA [71232, 100352)
constexpr int FUSED_PT   = 910;
constexpr int PURE_PIX0  = FUSED_PT * 64;       // 58240
constexpr int PURE_PT    = 203;
constexpr int IMMA_PIX0  = PURE_PIX0 + PURE_PT * 64;  // 71232
constexpr int IMMA_B0    = 22;                  // first batch holding IMMA px
constexpr int IMMA_NB    = 10;                  // batches 22..31 -> int8 xa
constexpr int FUSED_BLOCKS = FUSED_PT * 4;      // 3640
constexpr int PURE_BLOCKS  = PURE_PT * 2;       // 406
constexpr int TOT_BLOCKS   = FUSED_BLOCKS + PURE_BLOCKS;  // 4046

// smem layout (fused CTA): IMMA 3 stages then popc W/X tiles
constexpr int ISSTR = 80;
constexpr int IA_BYTES = 32 * ISSTR;            // 2560
constexpr int IB_BYTES = 64 * ISSTR;            // 5120
constexpr int ISTAGE = IA_BYTES + IB_BYTES;     // 7680, x3 = 23040
constexpr int PW_OFF = 23040 / 4;               // word offset of popc W [72][64]
constexpr int PX_OFF = PW_OFF + KW * 64;        // popc X [72][64]
constexpr int SMEM_DYN = (PX_OFF + KW * 64) * 4;   // 59904 B

// pure popc block layout: W [72][128] at 0, X [72][64] after
constexpr int SW_WORDS = KW * 128;              // 9216 (words)

// merged prep kernel block ranges
constexpr int PREP_WPREP = 256;
constexpr int PREP_XPACK = PREP_WPREP + HH * BB;   // 256 + 1792 = 2048
constexpr int PREP_BLOCKS = PREP_XPACK + BB;       // + 32 ring blocks = 2080

// ---------------------------------------------------------------------------
// Device scratch (allocation-free: __device__ globals)
// ---------------------------------------------------------------------------
__device__ uint32_t g_xp[(size_t)BB * HP * WP * 8];   // packed x, padded NHWC
__device__ uint4    g_xa8_raw[(size_t)IMMA_NB * HP * WP * CC / 16]; // int8 xa
__device__ uint32_t g_wpT[KW * CC];                   // packed w, [k][cout]
__device__ uint4    g_wb_raw[(size_t)CC * KD / 16];   // int8 w, [co][tap*256+ci]
__device__ int      g_corr[9 * CC];                   // border corrections
__device__ short    g_y16[(size_t)PIX * CC];          // conv result, NCHW int16
__device__ float    g_scale[CC];
__device__ unsigned long long g_isum[CC];
__device__ unsigned long long g_isumsq[CC];

#define G_WB  ((int8_t*)g_wb_raw)
#define G_XA8 ((int8_t*)g_xa8_raw)

// ---------------------------------------------------------------------------
// PTX helpers (baseline, assemble at .target sm_103)
// ---------------------------------------------------------------------------
__device__ __forceinline__ uint32_t smem_to_u32(const void* p) {
    uint32_t a;
    asm("{ .reg .u64 t; cvta.to.shared.u64 t, %1; cvt.u32.u64 %0, t; }" : "=r"(a) : "l"(p));
    return a;
}
__device__ __forceinline__ void cp16(uint32_t dst, const void* src) {
    asm volatile("cp.async.cg.shared.global [%0], [%1], 16;" :: "r"(dst), "l"(src));
}
#define CP_COMMIT() asm volatile("cp.async.commit_group;" ::: "memory")
#define CP_WAIT1()  asm volatile("cp.async.wait_group 1;" ::: "memory")
#define BAR_SYNC(id, cnt) \
    asm volatile("bar.sync %0, %1;" :: "r"(id), "r"(cnt) : "memory")
__device__ __forceinline__ void ldsm4(uint32_t& r0, uint32_t& r1, uint32_t& r2,
                                      uint32_t& r3, uint32_t addr) {
    asm volatile("ldmatrix.sync.aligned.m8n8.x4.shared.b16 {%0,%1,%2,%3}, [%4];"
                 : "=r"(r0), "=r"(r1), "=r"(r2), "=r"(r3) : "r"(addr));
}
__device__ __forceinline__ void mma_s8(int* d, uint32_t a0, uint32_t a1,
                                       uint32_t a2, uint32_t a3,
                                       uint32_t b0, uint32_t b1) {
    asm volatile(
        "mma.sync.aligned.m16n8k32.row.col.s32.s8.s8.s32 "
        "{%0,%1,%2,%3}, {%4,%5,%6,%7}, {%8,%9}, {%0,%1,%2,%3};"
        : "+r"(d[0]), "+r"(d[1]), "+r"(d[2]), "+r"(d[3])
        : "r"(a0), "r"(a1), "r"(a2), "r"(a3), "r"(b0), "r"(b1));
}

// ---------------------------------------------------------------------------
// Merged prep kernel: wprep (blocks 0..255) | xpack (256..2047) | ring (2048..2079)
// ---------------------------------------------------------------------------
__global__ void prep_kernel(const float* __restrict__ x, const float* __restrict__ w) {
    const int bid = blockIdx.x;
    const int tid = threadIdx.x;
    const int lane = tid & 31, warp = tid >> 5;

    if (bid < PREP_WPREP) {
        // ---- weight prep: scale, packed bits, int8 signs, corr table ----
        __shared__ float sh[8];
        __shared__ uint32_t words[9][8];
        __shared__ int S[9];
        int o = bid;
        const float* wp = w + ((size_t)o * CC + tid) * 9;
        float v[9]; float s = 0.0f;
#pragma unroll
        for (int t = 0; t < 9; t++) { v[t] = wp[t]; s += fabsf(v[t]); }
#pragma unroll
        for (int off = 16; off; off >>= 1) s += __shfl_xor_sync(~0u, s, off);
        if (lane == 0) sh[warp] = s;
#pragma unroll
        for (int t = 0; t < 9; t++) {
            uint32_t m = __ballot_sync(~0u, v[t] > 0.0f);
            if (lane == 0) words[t][warp] = m;
            int sg = (v[t] > 0.0f) ? 1 : ((v[t] < 0.0f) ? -1 : 0);
            G_WB[(size_t)o * KD + t * 256 + tid] = (int8_t)sg;
        }
        __syncthreads();
        if (tid == 0) {
            float tot = 0.0f;
            for (int i = 0; i < 8; i++) tot += sh[i];
            g_scale[o] = tot / (float)KBITS;
            g_isum[o] = 0ull; g_isumsq[o] = 0ull;
        }
        if (tid < 72) {
            int t = tid >> 3, j = tid & 7;
            g_wpT[(t * 8 + j) * CC + o] = words[t][j];
        }
        if (tid < 9) {
            int P = 0;
            for (int j = 0; j < 8; j++) P += __popc(words[tid][j]);
            S[tid] = 2 * P - 256;
        }
        __syncthreads();
        if (tid < 9) {
            int ht = tid / 3, wt = tid % 3;
            int corr = 0;
            for (int kh = 0; kh < 3; kh++)
                for (int kw = 0; kw < 3; kw++) {
                    bool miss = (ht == 0 && kh == 0) || (ht == 2 && kh == 2) ||
                                (wt == 0 && kw == 0) || (wt == 2 && kw == 2);
                    if (miss) corr += S[kh * 3 + kw];
                }
            g_corr[tid * CC + o] = corr;
        }
    } else if (bid < PREP_XPACK) {
        // ---- xpack: 32B-per-lane reads (full sector), sign bits + int8 ----
        int idx = bid - PREP_WPREP;
        int h = idx % HH, b = idx / HH;
        const float4* xrow =
            (const float4*)(x + (((size_t)(b * CC + warp * 32 + lane)) * HH + h) * WW);
        uint32_t* base = &g_xp[(((size_t)(b * HP + h + 1)) * WP + 1) * 8 + warp];
        const bool do8 = (b >= IMMA_B0);
        int8_t* a8base = do8
            ? &G_XA8[(((size_t)((b - IMMA_B0) * HP + h + 1)) * WP + 1) * CC + warp * 32]
            : (int8_t*)nullptr;
        const int pix = lane >> 3;          // 0..3
        const int sub = lane & 7;           // 0..7
        for (int w0 = 0; w0 < WW; w0 += 8) {
            float4 va = xrow[w0 >> 2];
            float4 vb = xrow[(w0 >> 2) + 1];
            uint32_t m[8];
            m[0] = __ballot_sync(~0u, va.x > 0.0f);
            m[1] = __ballot_sync(~0u, va.y > 0.0f);
            m[2] = __ballot_sync(~0u, va.z > 0.0f);
            m[3] = __ballot_sync(~0u, va.w > 0.0f);
            m[4] = __ballot_sync(~0u, vb.x > 0.0f);
            m[5] = __ballot_sync(~0u, vb.y > 0.0f);
            m[6] = __ballot_sync(~0u, vb.z > 0.0f);
            m[7] = __ballot_sync(~0u, vb.w > 0.0f);
            if (lane == 0) {
#pragma unroll
                for (int q = 0; q < 8; q++) base[(w0 + q) * 8] = m[q];
            }
            if (do8) {
                // lane expands pixels (w0+pix) and (w0+pix+4), nibble sub
                uint32_t mmA = m[pix], mmB = m[pix + 4];
                uint32_t nibA = (mmA >> (sub * 4)) & 0xFu;
                uint32_t nibB = (mmB >> (sub * 4)) & 0xFu;
                uint32_t wordA = __vsub4(((nibA * 0x00204081u) & 0x01010101u) << 1,
                                         0x01010101u);
                uint32_t wordB = __vsub4(((nibB * 0x00204081u) & 0x01010101u) << 1,
                                         0x01010101u);
                *(uint32_t*)&a8base[(size_t)(w0 + pix) * CC + sub * 4] = wordA;
                *(uint32_t*)&a8base[(size_t)(w0 + pix + 4) * CC + sub * 4] = wordB;
            }
        }
    } else {
        // ---- ring zero: pad borders of g_xp (all b) and g_xa8 (b>=22) ----
        int b = bid - PREP_XPACK;
        for (int i = tid; i < 228 * 8; i += 256) {
            int pos = i >> 3, word = i & 7;
            int h, w2;
            if (pos < 58)       { h = 0;            w2 = pos; }
            else if (pos < 116) { h = 57;           w2 = pos - 58; }
            else if (pos < 172) { h = pos - 116 + 1; w2 = 0; }
            else                { h = pos - 172 + 1; w2 = 57; }
            g_xp[(((size_t)(b * HP + h)) * WP + w2) * 8 + word] = 0;
        }
        if (b >= IMMA_B0) {
            int bp = b - IMMA_B0;
            for (int i = tid; i < 228 * 16; i += 256) {
                int pos = i >> 4, q = i & 15;
                int h, w2;
                if (pos < 58)       { h = 0;            w2 = pos; }
                else if (pos < 116) { h = 57;           w2 = pos - 58; }
                else if (pos < 172) { h = pos - 116 + 1; w2 = 0; }
                else                { h = pos - 172 + 1; w2 = 57; }
                ((uint4*)&G_XA8[(((size_t)(bp * HP + h)) * WP + w2) * CC])[q] =
                    make_uint4(0, 0, 0, 0);
            }
        }
    }
}

// ---------------------------------------------------------------------------
__device__ __forceinline__ int pixel_cat(int p) {
    int hw = p % HWs;
    int h = hw / WW, w = hw - h * WW;
    int ht = (h == 0) ? 0 : ((h == HH - 1) ? 2 : 1);
    int wt = (w == 0) ? 0 : ((w == WW - 1) ? 2 : 1);
    return ht * 3 + wt;
}

// ---------------------------------------------------------------------------
// popc half (fused CTA): 128 threads, 64px x 64c, named barrier 3.
// ---------------------------------------------------------------------------
__device__ __forceinline__ void popc_half(uint32_t* sW, uint32_t* sX,
                                          int wg, int p0, int n0) {
    {
        int col = wg & 63, khalf = wg >> 6;
        for (int k = khalf; k < KW; k += 2)
            sW[k * 64 + col] = g_wpT[k * CC + n0 + col];
    }
    for (int idx = wg; idx < 576; idx += 128) {
        int pix = idx & 63, tap = idx >> 6;
        int p = p0 + pix;
        int b = p / HWs, hw = p - b * HWs;
        int h = hw / WW, w = hw - h * WW;
        int kh = tap / 3, kw = tap - 3 * kh;
        const uint4* src =
            (const uint4*)&g_xp[(((size_t)(b * HP + h + kh)) * WP + (w + kw)) * 8];
        uint4 q0 = src[0], q1 = src[1];
        int kb = tap * 8;
        sX[(kb + 0) * 64 + pix] = q0.x; sX[(kb + 1) * 64 + pix] = q0.y;
        sX[(kb + 2) * 64 + pix] = q0.z; sX[(kb + 3) * 64 + pix] = q0.w;
        sX[(kb + 4) * 64 + pix] = q1.x; sX[(kb + 5) * 64 + pix] = q1.y;
        sX[(kb + 6) * 64 + pix] = q1.z; sX[(kb + 7) * 64 + pix] = q1.w;
    }
    BAR_SYNC(3, 128);

    const int pg = wg & 15;
    const int cg = wg >> 4;
    const int lane = wg & 31;
    const uint4* sXv = (const uint4*)sX;
    const uint4* sWv = (const uint4*)sW;

    int acc[4][8];
#pragma unroll
    for (int i = 0; i < 4; i++)
#pragma unroll
        for (int j = 0; j < 8; j++) acc[i][j] = 0;

#pragma unroll 2
    for (int k = 0; k < KW; k += 2) {
        uint4 xq0 = sXv[k * 16 + pg];
        uint4 xq1 = sXv[(k + 1) * 16 + pg];
        uint32_t xs0[4] = {xq0.x, xq0.y, xq0.z, xq0.w};
        uint32_t xs1[4] = {xq1.x, xq1.y, xq1.z, xq1.w};
        {
            uint4 w0 = sWv[k * 16 + cg * 2];
            uint4 w1 = sWv[(k + 1) * 16 + cg * 2];
            uint32_t ws0[4] = {w0.x, w0.y, w0.z, w0.w};
            uint32_t ws1[4] = {w1.x, w1.y, w1.z, w1.w};
#pragma unroll
            for (int i = 0; i < 4; i++)
#pragma unroll
                for (int j = 0; j < 4; j++)
                    acc[i][j] += __popc(xs0[i] ^ ws0[j]) + __popc(xs1[i] ^ ws1[j]);
        }
        {
            uint4 w0 = sWv[k * 16 + cg * 2 + 1];
            uint4 w1 = sWv[(k + 1) * 16 + cg * 2 + 1];
            uint32_t ws0[4] = {w0.x, w0.y, w0.z, w0.w};
            uint32_t ws1[4] = {w1.x, w1.y, w1.z, w1.w};
#pragma unroll
            for (int i = 0; i < 4; i++)
#pragma unroll
                for (int j = 0; j < 4; j++)
                    acc[i][j + 4] += __popc(xs0[i] ^ ws0[j]) + __popc(xs1[i] ^ ws1[j]);
        }
    }

    int pcat[4];
#pragma unroll
    for (int i = 0; i < 4; i++) pcat[i] = pixel_cat(p0 + pg * 4 + i);
    int u[4][8];
#pragma unroll
    for (int j = 0; j < 8; j++) {
        int c = n0 + cg * 8 + j;
#pragma unroll
        for (int i = 0; i < 4; i++) {
            int corr = (pcat[i] == 4) ? 0 : g_corr[pcat[i] * CC + c];
            u[i][j] = KBITS - 2 * acc[i][j] + corr;
        }
    }
#pragma unroll
    for (int j = 0; j < 8; j++) {
        int s = 0, s2 = 0;
#pragma unroll
        for (int i = 0; i < 4; i++) { s += u[i][j]; s2 += u[i][j] * u[i][j]; }
#pragma unroll
        for (int m = 1; m < 16; m <<= 1) {
            s  += __shfl_xor_sync(~0u, s, m);
            s2 += __shfl_xor_sync(~0u, s2, m);
        }
        if ((lane & 15) == 0) {
            int c = n0 + cg * 8 + j;
            atomicAdd(&g_isum[c],   (unsigned long long)(long long)s);
            atomicAdd(&g_isumsq[c], (unsigned long long)(long long)s2);
        }
    }
    {
        int p2 = p0 + pg * 4;
        int b2 = p2 / HWs, hw2 = p2 - b2 * HWs;
        short* yd = g_y16 + (size_t)b2 * CHW + hw2;
#pragma unroll
        for (int j = 0; j < 8; j++) {
            int c = n0 + cg * 8 + j;
            uint2 val;
            val.x = (uint32_t)(u[0][j] & 0xffff) | ((uint32_t)u[1][j] << 16);
            val.y = (uint32_t)(u[2][j] & 0xffff) | ((uint32_t)u[3][j] << 16);
            *(uint2*)&yd[(size_t)c * HWs] = val;
        }
    }
}

// ---------------------------------------------------------------------------
// IMMA half: 4 warps (threads 0..127), 32px x 64c, cp.async 3-stage
// ---------------------------------------------------------------------------
__device__ __forceinline__ void imma_half(uint32_t* smem32, int f) {
    char* smem = (char*)smem32;
    const uint32_t sbase = smem_to_u32(smem);
    const int wg = threadIdx.x;
    const int iw = wg >> 5;
    const int lane = wg & 31;
    const int wm = iw & 1;
    const int wn = iw >> 1;
    const int m0 = IMMA_PIX0 + (f >> 2) * 32;
    const int n0 = (f & 3) * 64;

    const int rA = wg >> 2, qA = wg & 3;
    int p = m0 + rA;
    int b = p / HWs; int hw = p - b * HWs;
    int h = hw / WW; int w = hw - h * WW;
    const int8_t* asrc =
        G_XA8 + (((size_t)((b - IMMA_B0) * HP + h)) * WP + w) * CC + qA * 16;
    const uint32_t sdstA = (uint32_t)(rA * ISSTR + qA * 16);
    const int rB = wg >> 1, qB = wg & 1;
    const int8_t* bsrc = G_WB + (size_t)(n0 + rB) * KD + qB * 32;
    const uint32_t sdstB = (uint32_t)(IA_BYTES + rB * ISSTR + qB * 32);

    auto issue = [&](int kc) {
        int buf = kc % 3;
        int tap = kc >> 2;
        int ci0 = (kc & 3) * 64;
        int kh = tap / 3, kw = tap - 3 * kh;
        cp16(sbase + buf * ISTAGE + sdstA, asrc + ((kh * WP + kw) * CC + ci0));
        const int8_t* bp = bsrc + tap * 256 + ci0;
        cp16(sbase + buf * ISTAGE + sdstB, bp);
        cp16(sbase + buf * ISTAGE + sdstB + 16, bp + 16);
    };

    int acc[4][4];
#pragma unroll
    for (int nf = 0; nf < 4; nf++)
#pragma unroll
        for (int i = 0; i < 4; i++) acc[nf][i] = 0;

    const uint32_t aFrag = (uint32_t)((wm * 16 + (lane & 15)) * ISSTR + (lane >> 4) * 16);
    const uint32_t bFrag = (uint32_t)(IA_BYTES + (wn * 32 + (lane & 15)) * ISSTR +
                                      (lane >> 4) * 16);

    issue(0); CP_COMMIT();
    issue(1); CP_COMMIT();
    for (int kc = 0; kc < 36; kc++) {
        CP_WAIT1();
        BAR_SYNC(1, 128);
        if (kc + 2 < 36) issue(kc + 2);
        CP_COMMIT();
        const uint32_t sb = sbase + (kc % 3) * ISTAGE;
#pragma unroll
        for (int s = 0; s < 2; s++) {
            uint32_t a0, a1, a2, a3;
            ldsm4(a0, a1, a2, a3, sb + aFrag + s * 32);
#pragma unroll
            for (int nb = 0; nb < 2; nb++) {
                uint32_t b0, b1, b2, b3;
                ldsm4(b0, b1, b2, b3, sb + bFrag + nb * 16 * ISSTR + s * 32);
                mma_s8(acc[2 * nb],     a0, a1, a2, a3, b0, b2);
                mma_s8(acc[2 * nb + 1], a0, a1, a2, a3, b1, b3);
            }
        }
    }

#pragma unroll
    for (int nf = 0; nf < 4; nf++) {
#pragma unroll
        for (int jj = 0; jj < 2; jj++) {
            int s = 0, s2 = 0;
#pragma unroll
            for (int rh = 0; rh < 2; rh++) {
                int v = acc[nf][rh * 2 + jj];
                s += v; s2 += v * v;
            }
#pragma unroll
            for (int m = 4; m < 32; m <<= 1) {
                s  += __shfl_xor_sync(~0u, s, m);
                s2 += __shfl_xor_sync(~0u, s2, m);
            }
            if (lane < 4) {
                int c = n0 + wn * 32 + nf * 8 + 2 * lane + jj;
                atomicAdd(&g_isum[c],   (unsigned long long)(long long)s);
                atomicAdd(&g_isumsq[c], (unsigned long long)(long long)s2);
            }
        }
    }
#pragma unroll
    for (int rh = 0; rh < 2; rh++) {
        int p2 = m0 + wm * 16 + (lane >> 2) + rh * 8;
        int b2 = p2 / HWs, hw2 = p2 - b2 * HWs;
        short* yd = g_y16 + (size_t)b2 * CHW + hw2;
#pragma unroll
        for (int nf = 0; nf < 4; nf++) {
            int c = n0 + wn * 32 + nf * 8 + 2 * (lane & 3);
            yd[(size_t)c * HWs]       = (short)acc[nf][rh * 2 + 0];
            yd[(size_t)(c + 1) * HWs] = (short)acc[nf][rh * 2 + 1];
        }
    }
}

// ---------------------------------------------------------------------------
// Pure popc block: 256 threads, 64px x 128c, __syncthreads only.
// ---------------------------------------------------------------------------
__device__ __forceinline__ void popc_block256(uint32_t* smem, int q) {
    uint32_t* sW = smem;
    uint32_t* sX = smem + SW_WORDS;
    const int tid = threadIdx.x;
    const int lane = tid & 31;
    const int p0 = PURE_PIX0 + (q >> 1) * 64;
    const int n0 = (q & 1) * 128;

    {
        int col = tid & 127, khalf = tid >> 7;
        for (int k = khalf; k < KW; k += 2)
            sW[k * 128 + col] = g_wpT[k * CC + n0 + col];
    }
    for (int idx = tid; idx < 576; idx += 256) {
        int pix = idx & 63, tap = idx >> 6;
        int p = p0 + pix;
        int b = p / HWs, hw = p - b * HWs;
        int h = hw / WW, w = hw - h * WW;
        int kh = tap / 3, kw = tap - 3 * kh;
        const uint4* src =
            (const uint4*)&g_xp[(((size_t)(b * HP + h + kh)) * WP + (w + kw)) * 8];
        uint4 q0 = src[0], q1 = src[1];
        int kb = tap * 8;
        sX[(kb + 0) * 64 + pix] = q0.x; sX[(kb + 1) * 64 + pix] = q0.y;
        sX[(kb + 2) * 64 + pix] = q0.z; sX[(kb + 3) * 64 + pix] = q0.w;
        sX[(kb + 4) * 64 + pix] = q1.x; sX[(kb + 5) * 64 + pix] = q1.y;
        sX[(kb + 6) * 64 + pix] = q1.z; sX[(kb + 7) * 64 + pix] = q1.w;
    }
    __syncthreads();

    const int pg = tid & 15;
    const int cg = tid >> 4;
    const uint4* sXv = (const uint4*)sX;
    const uint4* sWv = (const uint4*)sW;

    int acc[4][8];
#pragma unroll
    for (int i = 0; i < 4; i++)
#pragma unroll
        for (int j = 0; j < 8; j++) acc[i][j] = 0;

#pragma unroll 2
    for (int k = 0; k < KW; k += 2) {
        uint4 xq0 = sXv[k * 16 + pg];
        uint4 xq1 = sXv[(k + 1) * 16 + pg];
        uint32_t xs0[4] = {xq0.x, xq0.y, xq0.z, xq0.w};
        uint32_t xs1[4] = {xq1.x, xq1.y, xq1.z, xq1.w};
        {
            uint4 w0 = sWv[k * 32 + cg * 2];
            uint4 w1 = sWv[(k + 1) * 32 + cg * 2];
            uint32_t ws0[4] = {w0.x, w0.y, w0.z, w0.w};
            uint32_t ws1[4] = {w1.x, w1.y, w1.z, w1.w};
#pragma unroll
            for (int i = 0; i < 4; i++)
#pragma unroll
                for (int j = 0; j < 4; j++)
                    acc[i][j] += __popc(xs0[i] ^ ws0[j]) + __popc(xs1[i] ^ ws1[j]);
        }
        {
            uint4 w0 = sWv[k * 32 + cg * 2 + 1];
            uint4 w1 = sWv[(k + 1) * 32 + cg * 2 + 1];
            uint32_t ws0[4] = {w0.x, w0.y, w0.z, w0.w};
            uint32_t ws1[4] = {w1.x, w1.y, w1.z, w1.w};
#pragma unroll
            for (int i = 0; i < 4; i++)
#pragma unroll
                for (int j = 0; j < 4; j++)
                    acc[i][j + 4] += __popc(xs0[i] ^ ws0[j]) + __popc(xs1[i] ^ ws1[j]);
        }
    }

    int pcat[4];
#pragma unroll
    for (int i = 0; i < 4; i++) pcat[i] = pixel_cat(p0 + pg * 4 + i);
    int u[4][8];
#pragma unroll
    for (int j = 0; j < 8; j++) {
        int c = n0 + cg * 8 + j;
#pragma unroll
        for (int i = 0; i < 4; i++) {
            int corr = (pcat[i] == 4) ? 0 : g_corr[pcat[i] * CC + c];
            u[i][j] = KBITS - 2 * acc[i][j] + corr;
        }
    }
#pragma unroll
    for (int j = 0; j < 8; j++) {
        int s = 0, s2 = 0;
#pragma unroll
        for (int i = 0; i < 4; i++) { s += u[i][j]; s2 += u[i][j] * u[i][j]; }
#pragma unroll
        for (int m = 1; m < 16; m <<= 1) {
            s  += __shfl_xor_sync(~0u, s, m);
            s2 += __shfl_xor_sync(~0u, s2, m);
        }
        if ((lane & 15) == 0) {
            int c = n0 + cg * 8 + j;
            atomicAdd(&g_isum[c],   (unsigned long long)(long long)s);
            atomicAdd(&g_isumsq[c], (unsigned long long)(long long)s2);
        }
    }
    {
        int p2 = p0 + pg * 4;
        int b2 = p2 / HWs, hw2 = p2 - b2 * HWs;
        short* yd = g_y16 + (size_t)b2 * CHW + hw2;
#pragma unroll
        for (int j = 0; j < 8; j++) {
            int c = n0 + cg * 8 + j;
            uint2 val;
            val.x = (uint32_t)(u[0][j] & 0xffff) | ((uint32_t)u[1][j] << 16);
            val.y = (uint32_t)(u[2][j] & 0xffff) | ((uint32_t)u[3][j] << 16);
            *(uint2*)&yd[(size_t)c * HWs] = val;
        }
    }
}

// ---------------------------------------------------------------------------
// Unified gemm: fused warp-specialized CTAs + 10% pure popc, Bresenham mix
// ---------------------------------------------------------------------------
__global__ __launch_bounds__(256, 3) void gemm_kernel() {
    extern __shared__ uint32_t smem[];
    const uint32_t bid = blockIdx.x;
    const uint32_t before = (bid * (uint32_t)PURE_BLOCKS) / (uint32_t)TOT_BLOCKS;
    const uint32_t after  = ((bid + 1) * (uint32_t)PURE_BLOCKS) / (uint32_t)TOT_BLOCKS;
    if (after > before) {
        popc_block256(smem, (int)before);
    } else {
        int f = (int)(bid - before);
        if (threadIdx.x < 128) {
            imma_half(smem, f);
        } else {
            int wg = threadIdx.x - 128;
            int p0 = (f >> 2) * 64;
            int n0 = (f & 3) * 64;
            popc_half(smem + PW_OFF, smem + PX_OFF, wg, p0, n0);
        }
    }
}

// ---------------------------------------------------------------------------
// Kernel: out = relu(A*u + B), BN coefficients computed inline (fp32).
// ---------------------------------------------------------------------------
__global__ void finalize_kernel(float* __restrict__ out,
                                const float* __restrict__ gamma,
                                const float* __restrict__ beta) {
    size_t idx = (size_t)blockIdx.x * 256 + threadIdx.x;
    size_t j = idx * 8;
    int c = (int)((j / HWs) & 255);
    float n  = (float)PIX;
    float mu = (float)(long long)g_isum[c] / n;
    float vu = fmaf(-mu, mu, (float)(long long)g_isumsq[c] / n);
    float sc = g_scale[c];
    float A  = gamma[c] * sc * rsqrtf(fmaf(sc * sc, vu, BN_EPS));
    float Bv = fmaf(-A, mu, beta[c]);
    uint4 raw = ((const uint4*)g_y16)[idx];
    float4 o0, o1;
    o0.x = fmaxf(fmaf((float)(short)(raw.x & 0xffff), A, Bv), 0.0f);
    o0.y = fmaxf(fmaf((float)(short)(raw.x >> 16),    A, Bv), 0.0f);
    o0.z = fmaxf(fmaf((float)(short)(raw.y & 0xffff), A, Bv), 0.0f);
    o0.w = fmaxf(fmaf((float)(short)(raw.y >> 16),    A, Bv), 0.0f);
    o1.x = fmaxf(fmaf((float)(short)(raw.z & 0xffff), A, Bv), 0.0f);
    o1.y = fmaxf(fmaf((float)(short)(raw.z >> 16),    A, Bv), 0.0f);
    o1.z = fmaxf(fmaf((float)(short)(raw.w & 0xffff), A, Bv), 0.0f);
    o1.w = fmaxf(fmaf((float)(short)(raw.w >> 16),    A, Bv), 0.0f);
    ((float4*)out)[idx * 2]     = o0;
    ((float4*)out)[idx * 2 + 1] = o1;
}

// ---------------------------------------------------------------------------
// Launch: 3 kernels total (prep | gemm | finalize)
// ---------------------------------------------------------------------------
extern "C" void kernel_launch(void* const* d_in, const int* in_sizes, int n_in,
                              void* d_out, int out_size) {
    (void)in_sizes; (void)n_in; (void)out_size;
    const float* x     = (const float*)d_in[0];
    const float* wt    = (const float*)d_in[1];
    const float* gamma = (const float*)d_in[2];
    const float* beta  = (const float*)d_in[3];
    float* out = (float*)d_out;

    static int smem_set = 0;
    if (!smem_set) {
        cudaFuncSetAttribute(gemm_kernel, cudaFuncAttributeMaxDynamicSharedMemorySize,
                             SMEM_DYN);
        smem_set = 1;
    }

    prep_kernel<<<PREP_BLOCKS, 256>>>(x, wt);
    gemm_kernel<<<TOT_BLOCKS, 256, SMEM_DYN>>>();
    finalize_kernel<<<(int)((size_t)PIX * CC / 8 / 256), 256>>>(out, gamma, beta);
}